// round 1
// baseline (speedup 1.0000x reference)
#include <cuda_runtime.h>
#include <cuda_bf16.h>
#include <math.h>

// ---------------------------------------------------------------------------
// DiT block, fp32 baseline.
// B=2, T=2048, H=768, NH=12, HD=64.
// Pipeline:
//   1. t_emb = silu(t@Wss1+b)@Wss2+b            -> g_temb [2,4608]
//   2. h = g1*LN(x)+be1                          -> g_h
//   3. qkv = h@Wqkv+b                            -> g_qkv
//   4. flash attention (scale 1/sqrt(768))       -> g_o [B,T,H]
//   5. u = gelu(o@Wm1+b)                         -> g_u
//   6. x1 = x + a1*(u@Wm2+b)                     -> g_x1
//   7. h = g2*LN(x1)+be2                         -> g_h
//   8. u = gelu(h@Wf1+b)                         -> g_u
//   9. out = x1 + a2*(u@Wf2+b)                   -> d_out
// ---------------------------------------------------------------------------

#define HH   768
#define NHD  12
#define HDD  64
#define TT   2048
#define BB   2
#define MROWS (BB*TT)          // 4096

// ------------------------- scratch (static device) -------------------------
__device__ float g_hid [BB*6*HH];          // 2*4608
__device__ float g_temb[BB*6*HH];          // 2*4608
__device__ float g_h   [MROWS*HH];         // 4096*768
__device__ float g_qkv [MROWS*3*HH];       // 4096*2304
__device__ float g_o   [MROWS*HH];
__device__ float g_u   [MROWS*4*HH];       // 4096*3072
__device__ float g_x1  [MROWS*HH];

// ----------------------------- small helpers ------------------------------
__device__ __forceinline__ float warp_sum(float v) {
    #pragma unroll
    for (int o = 16; o; o >>= 1) v += __shfl_xor_sync(0xffffffffu, v, o);
    return v;
}

// ------------------------------- temb path --------------------------------
// out[b][n] = silu( sum_k t[b][k]*W[k][n] + bias[n] ),  K=768, N=4608
__global__ void temb1_k(const float* __restrict__ t, const float* __restrict__ W,
                        const float* __restrict__ bias) {
    int gid = blockIdx.x * blockDim.x + threadIdx.x;     // 0..9215
    int b = gid / 4608, n = gid % 4608;
    const float* tr = t + b * HH;
    float acc = bias[n];
    #pragma unroll 4
    for (int k = 0; k < HH; k++) acc += tr[k] * W[(size_t)k * 4608 + n];
    g_hid[gid] = acc / (1.0f + expf(-acc));
}

// out[b][n] = sum_k hid[b][k]*W[k][n] + bias[n],  K=4608, N=4608
__global__ void temb2_k(const float* __restrict__ W, const float* __restrict__ bias) {
    int gid = blockIdx.x * blockDim.x + threadIdx.x;
    int b = gid / 4608, n = gid % 4608;
    const float* hr = g_hid + b * 4608;
    float acc = bias[n];
    #pragma unroll 4
    for (int k = 0; k < 4608; k++) acc += hr[k] * W[(size_t)k * 4608 + n];
    g_temb[gid] = acc;
}

// --------------------------- LayerNorm + modulate --------------------------
// y[row] = temb[b][goff + c] * ( (x-mu)*rstd*lng[c] + lnb[c] ) + temb[b][goff+768+c]
__global__ void ln_mod_k(const float* __restrict__ x,
                         const float* __restrict__ lng, const float* __restrict__ lnb,
                         int goff, float* __restrict__ y) {
    int row = blockIdx.x;
    int b = row >> 11;
    const float* xr = x + (size_t)row * HH;
    int tid = threadIdx.x, lane = tid & 31, wid = tid >> 5;

    float s = 0.f, s2 = 0.f;
    #pragma unroll
    for (int i = tid; i < HH; i += 256) { float v = xr[i]; s += v; s2 += v * v; }
    s = warp_sum(s); s2 = warp_sum(s2);
    __shared__ float sh[2][8];
    if (lane == 0) { sh[0][wid] = s; sh[1][wid] = s2; }
    __syncthreads();
    if (wid == 0) {
        float a  = (lane < 8) ? sh[0][lane] : 0.f;
        float a2 = (lane < 8) ? sh[1][lane] : 0.f;
        a = warp_sum(a); a2 = warp_sum(a2);
        if (lane == 0) { sh[0][0] = a; sh[1][0] = a2; }
    }
    __syncthreads();
    const float inv = 1.0f / 768.0f;
    float mu  = sh[0][0] * inv;
    float var = sh[1][0] * inv - mu * mu;
    float rs  = rsqrtf(var + 1e-5f);
    const float* tb = g_temb + b * 4608;
    #pragma unroll
    for (int i = tid; i < HH; i += 256) {
        float v = (xr[i] - mu) * rs * lng[i] + lnb[i];
        y[(size_t)row * HH + i] = tb[goff + i] * v + tb[goff + 768 + i];
    }
}

// -------------------------------- SGEMM ------------------------------------
// C[M,N] = A[M,K] @ B[K,N] + bias[N]; EPI: 0=none, 1=gelu, 2=residual+gate
template <int EPI>
__global__ void __launch_bounds__(256) sgemm_k(
    const float* __restrict__ A, const float* __restrict__ B,
    const float* __restrict__ bias, float* __restrict__ C,
    int M, int N, int K,
    const float* __restrict__ res, int gate_off) {
    __shared__ float As[16][128];
    __shared__ float Bs[16][128];
    int tid = threadIdx.x;
    int bm = blockIdx.y, bn = blockIdx.x;
    int tx = tid & 15, ty = tid >> 4;
    float acc[8][8];
    #pragma unroll
    for (int i = 0; i < 8; i++)
        #pragma unroll
        for (int j = 0; j < 8; j++) acc[i][j] = 0.f;

    const float* Ap = A + (size_t)bm * 128 * K;
    const float* Bp = B + (size_t)bn * 128;

    for (int k0 = 0; k0 < K; k0 += 16) {
        #pragma unroll
        for (int i = 0; i < 2; i++) {
            int idx = tid + i * 256;                  // float4 index 0..511
            int ar = idx >> 2, ak = (idx & 3) << 2;
            float4 av = *(const float4*)(Ap + (size_t)ar * K + k0 + ak);
            As[ak + 0][ar] = av.x; As[ak + 1][ar] = av.y;
            As[ak + 2][ar] = av.z; As[ak + 3][ar] = av.w;
            int br = idx >> 5, bc = (idx & 31) << 2;
            *(float4*)&Bs[br][bc] = *(const float4*)(Bp + (size_t)(k0 + br) * N + bc);
        }
        __syncthreads();
        #pragma unroll
        for (int kk = 0; kk < 16; kk++) {
            float a[8], b[8];
            *(float4*)&a[0] = *(float4*)&As[kk][ty * 8];
            *(float4*)&a[4] = *(float4*)&As[kk][ty * 8 + 4];
            *(float4*)&b[0] = *(float4*)&Bs[kk][tx * 8];
            *(float4*)&b[4] = *(float4*)&Bs[kk][tx * 8 + 4];
            #pragma unroll
            for (int i = 0; i < 8; i++)
                #pragma unroll
                for (int j = 0; j < 8; j++)
                    acc[i][j] += a[i] * b[j];
        }
        __syncthreads();
    }

    int rowbase = bm * 128 + ty * 8;
    int colbase = bn * 128 + tx * 8;
    #pragma unroll
    for (int i = 0; i < 8; i++) {
        int row = rowbase + i;
        int bidx = row >> 11;
        const float* tb = g_temb + bidx * 4608 + gate_off;
        #pragma unroll
        for (int j = 0; j < 8; j++) {
            int col = colbase + j;
            float v = acc[i][j] + bias[col];
            if (EPI == 1) v = 0.5f * v * (1.0f + erff(v * 0.70710678118654752f));
            if (EPI == 2) v = res[(size_t)row * N + col] + tb[col] * v;
            C[(size_t)row * N + col] = v;
        }
    }
}

// ----------------------------- flash attention ------------------------------
// One thread per query row; block = 128 queries of one (b,h). 32 K/V tiles of 64.
__global__ void __launch_bounds__(128) attn_k(const float* __restrict__ qkv,
                                              float* __restrict__ o) {
    extern __shared__ float sm[];
    float* sK = sm;                  // 64*64
    float* sV = sm + 64 * 64;        // 64*64
    float* sS = sm + 2 * 64 * 64;    // 128*65
    int bh = blockIdx.x;
    int b = bh / NHD, h = bh % NHD;
    int tid = threadIdx.x;
    int q = blockIdx.y * 128 + tid;

    const float scale = 0.036084391824351615f;   // 1/sqrt(768)
    float qreg[HDD];
    size_t qbase = ((((size_t)b * TT + q) * 3 + 0) * NHD + h) * HDD;
    #pragma unroll
    for (int d = 0; d < HDD; d++) qreg[d] = qkv[qbase + d] * scale;

    float acc[HDD];
    #pragma unroll
    for (int d = 0; d < HDD; d++) acc[d] = 0.f;
    float m = -1e30f, l = 0.f;

    for (int kt = 0; kt < TT / 64; kt++) {
        #pragma unroll
        for (int i = 0; i < 32; i++) {
            int idx = tid + i * 128;
            int r = idx >> 6, c = idx & 63;
            size_t kb = ((((size_t)b * TT + kt * 64 + r) * 3 + 1) * NHD + h) * HDD + c;
            sK[r * 64 + c] = qkv[kb];
            sV[r * 64 + c] = qkv[kb + NHD * HDD];   // i=2 slab is +768 floats
        }
        __syncthreads();

        float mt = -1e30f;
        #pragma unroll 1
        for (int j = 0; j < 64; j++) {
            float s = 0.f;
            const float* kr = sK + j * 64;
            #pragma unroll
            for (int d = 0; d < HDD; d++) s += qreg[d] * kr[d];
            sS[tid * 65 + j] = s;
            mt = fmaxf(mt, s);
        }
        float mnew = fmaxf(m, mt);
        float corr = __expf(m - mnew);
        l *= corr;
        #pragma unroll
        for (int d = 0; d < HDD; d++) acc[d] *= corr;
        #pragma unroll 1
        for (int j = 0; j < 64; j++) {
            float p = __expf(sS[tid * 65 + j] - mnew);
            l += p;
            const float* vr = sV + j * 64;
            #pragma unroll
            for (int d = 0; d < HDD; d++) acc[d] += p * vr[d];
        }
        m = mnew;
        __syncthreads();
    }

    float inv = 1.0f / l;
    size_t ob = ((size_t)b * TT + q) * HH + h * HDD;
    #pragma unroll
    for (int d = 0; d < HDD; d++) o[ob + d] = acc[d] * inv;
}

// ------------------------------- launcher ----------------------------------
extern "C" void kernel_launch(void* const* d_in, const int* in_sizes, int n_in,
                              void* d_out, int out_size) {
    const float* x      = (const float*)d_in[0];
    const float* t      = (const float*)d_in[1];
    const float* w_qkv  = (const float*)d_in[2];
    const float* b_qkv  = (const float*)d_in[3];
    const float* w_m1   = (const float*)d_in[4];
    const float* b_m1   = (const float*)d_in[5];
    const float* w_m2   = (const float*)d_in[6];
    const float* b_m2   = (const float*)d_in[7];
    const float* w_ss1  = (const float*)d_in[8];
    const float* b_ss1  = (const float*)d_in[9];
    const float* w_ss2  = (const float*)d_in[10];
    const float* b_ss2  = (const float*)d_in[11];
    const float* ln1_g  = (const float*)d_in[12];
    const float* ln1_b  = (const float*)d_in[13];
    const float* ln2_g  = (const float*)d_in[14];
    const float* ln2_b  = (const float*)d_in[15];
    const float* w_f1   = (const float*)d_in[16];
    const float* b_f1   = (const float*)d_in[17];
    const float* w_f2   = (const float*)d_in[18];
    const float* b_f2   = (const float*)d_in[19];
    float* out = (float*)d_out;

    float *p_h, *p_qkv, *p_o, *p_u, *p_x1;
    cudaGetSymbolAddress((void**)&p_h,   g_h);
    cudaGetSymbolAddress((void**)&p_qkv, g_qkv);
    cudaGetSymbolAddress((void**)&p_o,   g_o);
    cudaGetSymbolAddress((void**)&p_u,   g_u);
    cudaGetSymbolAddress((void**)&p_x1,  g_x1);

    const int ATTN_SMEM = (2 * 64 * 64 + 128 * 65) * 4;   // 66048 bytes
    cudaFuncSetAttribute(attn_k, cudaFuncAttributeMaxDynamicSharedMemorySize, ATTN_SMEM);

    // 1) t_emb
    temb1_k<<<72, 128>>>(t, w_ss1, b_ss1);
    temb2_k<<<72, 128>>>(w_ss2, b_ss2);

    // 2) h = g1*LN(x)+be1
    ln_mod_k<<<MROWS, 256>>>(x, ln1_g, ln1_b, 0, p_h);

    // 3) qkv
    sgemm_k<0><<<dim3(2304 / 128, MROWS / 128), 256>>>(
        p_h, w_qkv, b_qkv, p_qkv, MROWS, 2304, 768, nullptr, 0);

    // 4) attention
    attn_k<<<dim3(BB * NHD, TT / 128), 128, ATTN_SMEM>>>(p_qkv, p_o);

    // 5) u = gelu(o@Wm1+b)
    sgemm_k<1><<<dim3(3072 / 128, MROWS / 128), 256>>>(
        p_o, w_m1, b_m1, p_u, MROWS, 3072, 768, nullptr, 0);

    // 6) x1 = x + a1*(u@Wm2+b)      (a1 at temb offset 1536)
    sgemm_k<2><<<dim3(768 / 128, MROWS / 128), 256>>>(
        p_u, w_m2, b_m2, p_x1, MROWS, 768, 3072, x, 1536);

    // 7) h = g2*LN(x1)+be2          (g2 at offset 2304)
    ln_mod_k<<<MROWS, 256>>>(p_x1, ln2_g, ln2_b, 2304, p_h);

    // 8) u = gelu(h@Wf1+b)
    sgemm_k<1><<<dim3(3072 / 128, MROWS / 128), 256>>>(
        p_h, w_f1, b_f1, p_u, MROWS, 3072, 768, nullptr, 0);

    // 9) out = x1 + a2*(u@Wf2+b)    (a2 at offset 3840)
    sgemm_k<2><<<dim3(768 / 128, MROWS / 128), 256>>>(
        p_u, w_f2, b_f2, out, MROWS, 768, 3072, p_x1, 3840);
}

// round 3
// speedup vs baseline: 2.2611x; 2.2611x over previous
#include <cuda_runtime.h>
#include <cuda_bf16.h>
#include <math.h>
#include <stdint.h>

// ---------------------------------------------------------------------------
// DiT block. GEMMs via mma.sync bf16 (2-term split -> ~fp32 accuracy),
// cp.async double-buffered pipeline. Attention fp32 flash. B=2,T=2048,H=768.
// ---------------------------------------------------------------------------

#define HH   768
#define NHD  12
#define HDD  64
#define TT   2048
#define BB   2
#define MROWS (BB*TT)          // 4096

// ------------------------- scratch (static device) -------------------------
__device__ float g_hid [BB*6*HH];
__device__ float g_temb[BB*6*HH];
__device__ float g_qkv [MROWS*3*HH];
__device__ float g_x1  [MROWS*HH];

__device__ __nv_bfloat16 g_h_h[MROWS*HH],   g_h_l[MROWS*HH];
__device__ __nv_bfloat16 g_o_h[MROWS*HH],   g_o_l[MROWS*HH];
__device__ __nv_bfloat16 g_u_h[MROWS*4*HH], g_u_l[MROWS*4*HH];

__device__ __nv_bfloat16 g_wqkv_h[3*HH*HH],  g_wqkv_l[3*HH*HH];
__device__ __nv_bfloat16 g_wm1_h [4*HH*HH],  g_wm1_l [4*HH*HH];
__device__ __nv_bfloat16 g_wm2_h [HH*4*HH],  g_wm2_l [HH*4*HH];
__device__ __nv_bfloat16 g_wf1_h [4*HH*HH],  g_wf1_l [4*HH*HH];
__device__ __nv_bfloat16 g_wf2_h [HH*4*HH],  g_wf2_l [HH*4*HH];

// ----------------------------- PTX helpers --------------------------------
__device__ __forceinline__ uint32_t smem_u32(const void* p) {
    uint32_t a;
    asm("{ .reg .u64 t; cvta.to.shared.u64 t, %1; cvt.u32.u64 %0, t; }" : "=r"(a) : "l"(p));
    return a;
}
__device__ __forceinline__ void ldsm4(uint32_t* r, uint32_t a) {
    asm volatile("ldmatrix.sync.aligned.m8n8.x4.shared.b16 {%0,%1,%2,%3}, [%4];"
        : "=r"(r[0]), "=r"(r[1]), "=r"(r[2]), "=r"(r[3]) : "r"(a));
}
__device__ __forceinline__ void mma16816(float* d, const uint32_t* a, const uint32_t* b) {
    asm volatile("mma.sync.aligned.m16n8k16.row.col.f32.bf16.bf16.f32 "
        "{%0,%1,%2,%3},{%4,%5,%6,%7},{%8,%9},{%0,%1,%2,%3};"
        : "+f"(d[0]), "+f"(d[1]), "+f"(d[2]), "+f"(d[3])
        : "r"(a[0]), "r"(a[1]), "r"(a[2]), "r"(a[3]), "r"(b[0]), "r"(b[1]));
}
__device__ __forceinline__ void cpasync16(uint32_t dst, const void* src) {
    asm volatile("cp.async.cg.shared.global [%0], [%1], 16;" :: "r"(dst), "l"(src) : "memory");
}
#define CP_COMMIT() asm volatile("cp.async.commit_group;" ::: "memory")
#define CP_WAIT(n)  asm volatile("cp.async.wait_group %0;" :: "n"(n) : "memory")

__device__ __forceinline__ float warp_sum(float v) {
    #pragma unroll
    for (int o = 16; o; o >>= 1) v += __shfl_xor_sync(0xffffffffu, v, o);
    return v;
}
__device__ __forceinline__ void split_store(float v, __nv_bfloat16* ph, __nv_bfloat16* pl) {
    __nv_bfloat16 hi = __float2bfloat16(v);
    *ph = hi;
    *pl = __float2bfloat16(v - __bfloat162float(hi));
}
__device__ __forceinline__ uint32_t pack_bf2(float x, float y) {
    __nv_bfloat162 t;
    t.x = __float2bfloat16(x); t.y = __float2bfloat16(y);
    return *(uint32_t*)&t;
}

// ------------------------------- temb path --------------------------------
__global__ void temb1_k(const float* __restrict__ t, const float* __restrict__ W,
                        const float* __restrict__ bias) {
    int gid = blockIdx.x * blockDim.x + threadIdx.x;
    int b = gid / 4608, n = gid % 4608;
    const float* tr = t + b * HH;
    float acc = bias[n];
    #pragma unroll 4
    for (int k = 0; k < HH; k++) acc += tr[k] * W[(size_t)k * 4608 + n];
    g_hid[gid] = acc / (1.0f + expf(-acc));
}
__global__ void temb2_k(const float* __restrict__ W, const float* __restrict__ bias) {
    int gid = blockIdx.x * blockDim.x + threadIdx.x;
    int b = gid / 4608, n = gid % 4608;
    const float* hr = g_hid + b * 4608;
    float acc = bias[n];
    #pragma unroll 4
    for (int k = 0; k < 4608; k++) acc += hr[k] * W[(size_t)k * 4608 + n];
    g_temb[gid] = acc;
}

// -------------------- weight transpose + bf16 split ------------------------
__global__ void wtconv_k(const float* __restrict__ W, __nv_bfloat16* __restrict__ Oh,
                         __nv_bfloat16* __restrict__ Ol, int K, int N) {
    __shared__ float s[32][33];
    int tx = threadIdx.x, ty = threadIdx.y;
    int n0 = blockIdx.x * 32, k0 = blockIdx.y * 32;
    #pragma unroll
    for (int j = 0; j < 32; j += 8)
        s[ty + j][tx] = W[(size_t)(k0 + ty + j) * N + n0 + tx];
    __syncthreads();
    #pragma unroll
    for (int j = 0; j < 32; j += 8) {
        float v = s[tx][ty + j];
        size_t o = (size_t)(n0 + ty + j) * K + k0 + tx;
        __nv_bfloat16 hi = __float2bfloat16(v);
        Oh[o] = hi;
        Ol[o] = __float2bfloat16(v - __bfloat162float(hi));
    }
}

// --------------------------- LayerNorm + modulate --------------------------
__global__ void ln_mod_k(const float* __restrict__ x,
                         const float* __restrict__ lng, const float* __restrict__ lnb,
                         int goff, __nv_bfloat16* __restrict__ yh,
                         __nv_bfloat16* __restrict__ yl) {
    int row = blockIdx.x;
    int b = row >> 11;
    const float* xr = x + (size_t)row * HH;
    int tid = threadIdx.x, lane = tid & 31, wid = tid >> 5;

    float s = 0.f, s2 = 0.f;
    #pragma unroll
    for (int i = tid; i < HH; i += 256) { float v = xr[i]; s += v; s2 += v * v; }
    s = warp_sum(s); s2 = warp_sum(s2);
    __shared__ float sh[2][8];
    if (lane == 0) { sh[0][wid] = s; sh[1][wid] = s2; }
    __syncthreads();
    if (wid == 0) {
        float a  = (lane < 8) ? sh[0][lane] : 0.f;
        float a2 = (lane < 8) ? sh[1][lane] : 0.f;
        a = warp_sum(a); a2 = warp_sum(a2);
        if (lane == 0) { sh[0][0] = a; sh[1][0] = a2; }
    }
    __syncthreads();
    const float inv = 1.0f / 768.0f;
    float mu  = sh[0][0] * inv;
    float var = sh[1][0] * inv - mu * mu;
    float rs  = rsqrtf(var + 1e-5f);
    const float* tb = g_temb + b * 4608;
    #pragma unroll
    for (int i = tid; i < HH; i += 256) {
        float v = (xr[i] - mu) * rs * lng[i] + lnb[i];
        v = tb[goff + i] * v + tb[goff + 768 + i];
        split_store(v, yh + (size_t)row * HH + i, yl + (size_t)row * HH + i);
    }
}

// ------------------------------ HMMA GEMM ----------------------------------
// C[4096,N] = (Ah+Al)[4096,K] @ (Bh+Bl)^T + bias.  B given as Bt[N,K].
// CTA 128x128, 8 warps of 32x64. K staged by 32, cp.async double buffer.
// smem tiles padded: row stride 40 bf16 (80B) -> conflict-free ldmatrix.
// EPI: 0=fp32 out, 1=gelu->bf16 split, 2=residual+gate->fp32
#define ATILE 10240             // 128 rows * 80B
#define STAGE (4*ATILE)         // Ah, Al, Bh, Bl
#define GEMM_SMEM (2*STAGE)     // 81920
template <int EPI>
__global__ void __launch_bounds__(256) hgemm_k(
    const __nv_bfloat16* __restrict__ Ah, const __nv_bfloat16* __restrict__ Al,
    const __nv_bfloat16* __restrict__ Bh, const __nv_bfloat16* __restrict__ Bl,
    const float* __restrict__ bias,
    float* __restrict__ Cf,
    __nv_bfloat16* __restrict__ Ch, __nv_bfloat16* __restrict__ Cl,
    int N, int K,
    const float* __restrict__ res, int gate_off) {

    extern __shared__ char sm[];
    const uint32_t sbase = smem_u32(sm);
    const int tid = threadIdx.x, lane = tid & 31, wid = tid >> 5;
    const int bm = blockIdx.y, bn = blockIdx.x;
    const int am0 = bm * 128, bn0 = bn * 128;
    const int wm0 = (wid >> 1) * 32, wn0 = (wid & 1) * 64;

    float acc[2][8][4];
    #pragma unroll
    for (int i = 0; i < 2; i++)
        #pragma unroll
        for (int j = 0; j < 8; j++)
            #pragma unroll
            for (int q = 0; q < 4; q++) acc[i][j][q] = 0.f;

    // cp.async assignments: 8 chunks of 16B per thread per stage
    const __nv_bfloat16* mats[4] = {Ah, Al, Bh, Bl};
    const __nv_bfloat16* srcb[8];
    uint32_t dstb[8];
    #pragma unroll
    for (int it = 0; it < 8; it++) {
        int idx = tid + it * 256;
        int mat = idx >> 9, r = (idx >> 2) & 127, c = idx & 3;
        int grow = (mat < 2 ? am0 : bn0) + r;
        srcb[it] = mats[mat] + (size_t)grow * K + c * 8;
        dstb[it] = sbase + mat * ATILE + r * 80 + c * 16;
    }

    // ldmatrix lane addresses (stage-0 base; add stage/ks offsets later)
    uint32_t aaddr[2][2];   // [term][mi]
    #pragma unroll
    for (int t = 0; t < 2; t++)
        #pragma unroll
        for (int mi = 0; mi < 2; mi++) {
            int row = wm0 + mi * 16 + (lane & 15);
            aaddr[t][mi] = sbase + t * ATILE + row * 80 + ((lane >> 4) << 4);
        }
    uint32_t baddr[2][4];   // [term][ng]
    #pragma unroll
    for (int t = 0; t < 2; t++)
        #pragma unroll
        for (int ng = 0; ng < 4; ng++) {
            int row = wn0 + ng * 16 + (lane & 7) + ((lane & 16) >> 1);
            baddr[t][ng] = sbase + (2 + t) * ATILE + row * 80 + ((lane & 8) ? 16 : 0);
        }

    const int KB = K >> 5;

    // prologue
    {
        #pragma unroll
        for (int it = 0; it < 8; it++) cpasync16(dstb[it], srcb[it]);
        CP_COMMIT();
    }

    for (int kb = 0; kb < KB; kb++) {
        const uint32_t so = (kb & 1) * STAGE;
        if (kb + 1 < KB) {
            const uint32_t so2 = ((kb + 1) & 1) * STAGE;
            const int ko = (kb + 1) << 5;
            #pragma unroll
            for (int it = 0; it < 8; it++) cpasync16(dstb[it] + so2, srcb[it] + ko);
            CP_COMMIT();
            CP_WAIT(1);
        } else {
            CP_WAIT(0);
        }
        __syncthreads();

        #pragma unroll
        for (int ks = 0; ks < 2; ks++) {
            const uint32_t ko = so + ks * 32;
            uint32_t ah[2][4], al[2][4];
            ldsm4(ah[0], aaddr[0][0] + ko);
            ldsm4(ah[1], aaddr[0][1] + ko);
            ldsm4(al[0], aaddr[1][0] + ko);
            ldsm4(al[1], aaddr[1][1] + ko);

            uint32_t b[8][2];
            #pragma unroll
            for (int ng = 0; ng < 4; ng++) {
                uint32_t r[4];
                ldsm4(r, baddr[0][ng] + ko);
                b[2*ng][0] = r[0]; b[2*ng][1] = r[1];
                b[2*ng+1][0] = r[2]; b[2*ng+1][1] = r[3];
            }
            #pragma unroll
            for (int mi = 0; mi < 2; mi++)
                #pragma unroll
                for (int ni = 0; ni < 8; ni++) {
                    mma16816(acc[mi][ni], ah[mi], b[ni]);   // Ah*Bh
                    mma16816(acc[mi][ni], al[mi], b[ni]);   // Al*Bh
                }
            #pragma unroll
            for (int ng = 0; ng < 4; ng++) {
                uint32_t r[4];
                ldsm4(r, baddr[1][ng] + ko);
                b[2*ng][0] = r[0]; b[2*ng][1] = r[1];
                b[2*ng+1][0] = r[2]; b[2*ng+1][1] = r[3];
            }
            #pragma unroll
            for (int mi = 0; mi < 2; mi++)
                #pragma unroll
                for (int ni = 0; ni < 8; ni++)
                    mma16816(acc[mi][ni], ah[mi], b[ni]);   // Ah*Bl
        }
        __syncthreads();
    }

    // ----------------------------- epilogue -------------------------------
    const int rbase = am0 + wm0 + (lane >> 2);
    const int cbase = bn0 + wn0 + (lane & 3) * 2;
    #pragma unroll
    for (int mi = 0; mi < 2; mi++) {
        #pragma unroll
        for (int ni = 0; ni < 8; ni++) {
            int col = cbase + ni * 8;
            float2 bb = *(const float2*)&bias[col];
            #pragma unroll
            for (int half = 0; half < 2; half++) {
                int row = rbase + mi * 16 + half * 8;
                float v0 = acc[mi][ni][2*half]   + bb.x;
                float v1 = acc[mi][ni][2*half+1] + bb.y;
                if (EPI == 1) {
                    v0 = 0.5f * v0 * (1.0f + erff(v0 * 0.70710678118654752f));
                    v1 = 0.5f * v1 * (1.0f + erff(v1 * 0.70710678118654752f));
                    __nv_bfloat16 h0 = __float2bfloat16(v0), h1 = __float2bfloat16(v1);
                    float l0 = v0 - __bfloat162float(h0), l1 = v1 - __bfloat162float(h1);
                    size_t o = (size_t)row * N + col;
                    __nv_bfloat162 hp; hp.x = h0; hp.y = h1;
                    *(__nv_bfloat162*)(Ch + o) = hp;
                    *(uint32_t*)(Cl + o) = pack_bf2(l0, l1);
                } else {
                    if (EPI == 2) {
                        const float* tb = g_temb + (row >> 11) * 4608 + gate_off;
                        float2 rr = *(const float2*)&res[(size_t)row * N + col];
                        float2 gg = *(const float2*)&tb[col];
                        v0 = rr.x + gg.x * v0;
                        v1 = rr.y + gg.y * v1;
                    }
                    float2 o2; o2.x = v0; o2.y = v1;
                    *(float2*)&Cf[(size_t)row * N + col] = o2;
                }
            }
        }
    }
}

// ----------------------------- flash attention ------------------------------
__global__ void __launch_bounds__(128) attn_k(const float* __restrict__ qkv,
                                              __nv_bfloat16* __restrict__ oh,
                                              __nv_bfloat16* __restrict__ ol) {
    extern __shared__ float smf[];
    float* sK = smf;
    float* sV = smf + 64 * 64;
    float* sS = smf + 2 * 64 * 64;
    int bh = blockIdx.x;
    int b = bh / NHD, h = bh % NHD;
    int tid = threadIdx.x;
    int q = blockIdx.y * 128 + tid;

    const float scale = 0.036084391824351615f;   // 1/sqrt(768)
    float qreg[HDD];
    size_t qbase = ((((size_t)b * TT + q) * 3 + 0) * NHD + h) * HDD;
    #pragma unroll
    for (int d = 0; d < HDD; d++) qreg[d] = qkv[qbase + d] * scale;

    float acc[HDD];
    #pragma unroll
    for (int d = 0; d < HDD; d++) acc[d] = 0.f;
    float m = -1e30f, l = 0.f;

    for (int kt = 0; kt < TT / 64; kt++) {
        #pragma unroll
        for (int i = 0; i < 8; i++) {
            int idx = tid + i * 128;
            int r = idx >> 4, c = (idx & 15) << 2;
            size_t kb = ((((size_t)b * TT + kt * 64 + r) * 3 + 1) * NHD + h) * HDD + c;
            *(float4*)(sK + r * 64 + c) = *(const float4*)(qkv + kb);
            *(float4*)(sV + r * 64 + c) = *(const float4*)(qkv + kb + NHD * HDD);
        }
        __syncthreads();

        float mt = -1e30f;
        #pragma unroll 1
        for (int j = 0; j < 64; j++) {
            const float4* kr = (const float4*)(sK + j * 64);
            float s = 0.f;
            #pragma unroll
            for (int d4 = 0; d4 < 16; d4++) {
                float4 kv = kr[d4];
                s += qreg[4*d4] * kv.x + qreg[4*d4+1] * kv.y
                   + qreg[4*d4+2] * kv.z + qreg[4*d4+3] * kv.w;
            }
            sS[tid * 65 + j] = s;
            mt = fmaxf(mt, s);
        }
        float mnew = fmaxf(m, mt);
        float corr = __expf(m - mnew);
        l *= corr;
        #pragma unroll
        for (int d = 0; d < HDD; d++) acc[d] *= corr;
        #pragma unroll 1
        for (int j = 0; j < 64; j++) {
            float p = __expf(sS[tid * 65 + j] - mnew);
            l += p;
            const float4* vr = (const float4*)(sV + j * 64);
            #pragma unroll
            for (int d4 = 0; d4 < 16; d4++) {
                float4 vv = vr[d4];
                acc[4*d4]   += p * vv.x;
                acc[4*d4+1] += p * vv.y;
                acc[4*d4+2] += p * vv.z;
                acc[4*d4+3] += p * vv.w;
            }
        }
        m = mnew;
        __syncthreads();
    }

    float inv = 1.0f / l;
    size_t ob = ((size_t)b * TT + q) * HH + h * HDD;
    #pragma unroll
    for (int d = 0; d < HDD; d++) {
        float v = acc[d] * inv;
        __nv_bfloat16 hi = __float2bfloat16(v);
        oh[ob + d] = hi;
        ol[ob + d] = __float2bfloat16(v - __bfloat162float(hi));
    }
}

// ------------------------------- launcher ----------------------------------
extern "C" void kernel_launch(void* const* d_in, const int* in_sizes, int n_in,
                              void* d_out, int out_size) {
    const float* x      = (const float*)d_in[0];
    const float* t      = (const float*)d_in[1];
    const float* w_qkv  = (const float*)d_in[2];
    const float* b_qkv  = (const float*)d_in[3];
    const float* w_m1   = (const float*)d_in[4];
    const float* b_m1   = (const float*)d_in[5];
    const float* w_m2   = (const float*)d_in[6];
    const float* b_m2   = (const float*)d_in[7];
    const float* w_ss1  = (const float*)d_in[8];
    const float* b_ss1  = (const float*)d_in[9];
    const float* w_ss2  = (const float*)d_in[10];
    const float* b_ss2  = (const float*)d_in[11];
    const float* ln1_g  = (const float*)d_in[12];
    const float* ln1_b  = (const float*)d_in[13];
    const float* ln2_g  = (const float*)d_in[14];
    const float* ln2_b  = (const float*)d_in[15];
    const float* w_f1   = (const float*)d_in[16];
    const float* b_f1   = (const float*)d_in[17];
    const float* w_f2   = (const float*)d_in[18];
    const float* b_f2   = (const float*)d_in[19];
    float* out = (float*)d_out;

    float *p_qkv, *p_x1;
    __nv_bfloat16 *p_hh, *p_hl, *p_oh, *p_ol, *p_uh, *p_ul;
    __nv_bfloat16 *p_wqh, *p_wql, *p_wm1h, *p_wm1l, *p_wm2h, *p_wm2l,
                  *p_wf1h, *p_wf1l, *p_wf2h, *p_wf2l;
    cudaGetSymbolAddress((void**)&p_qkv, g_qkv);
    cudaGetSymbolAddress((void**)&p_x1,  g_x1);
    cudaGetSymbolAddress((void**)&p_hh,  g_h_h);  cudaGetSymbolAddress((void**)&p_hl, g_h_l);
    cudaGetSymbolAddress((void**)&p_oh,  g_o_h);  cudaGetSymbolAddress((void**)&p_ol, g_o_l);
    cudaGetSymbolAddress((void**)&p_uh,  g_u_h);  cudaGetSymbolAddress((void**)&p_ul, g_u_l);
    cudaGetSymbolAddress((void**)&p_wqh, g_wqkv_h);  cudaGetSymbolAddress((void**)&p_wql, g_wqkv_l);
    cudaGetSymbolAddress((void**)&p_wm1h, g_wm1_h);  cudaGetSymbolAddress((void**)&p_wm1l, g_wm1_l);
    cudaGetSymbolAddress((void**)&p_wm2h, g_wm2_h);  cudaGetSymbolAddress((void**)&p_wm2l, g_wm2_l);
    cudaGetSymbolAddress((void**)&p_wf1h, g_wf1_h);  cudaGetSymbolAddress((void**)&p_wf1l, g_wf1_l);
    cudaGetSymbolAddress((void**)&p_wf2h, g_wf2_h);  cudaGetSymbolAddress((void**)&p_wf2l, g_wf2_l);

    const int ATTN_SMEM = (2 * 64 * 64 + 128 * 65) * 4;   // 66048
    cudaFuncSetAttribute(attn_k, cudaFuncAttributeMaxDynamicSharedMemorySize, ATTN_SMEM);
    cudaFuncSetAttribute(hgemm_k<0>, cudaFuncAttributeMaxDynamicSharedMemorySize, GEMM_SMEM);
    cudaFuncSetAttribute(hgemm_k<1>, cudaFuncAttributeMaxDynamicSharedMemorySize, GEMM_SMEM);
    cudaFuncSetAttribute(hgemm_k<2>, cudaFuncAttributeMaxDynamicSharedMemorySize, GEMM_SMEM);

    dim3 cb(32, 8);
    wtconv_k<<<dim3(2304/32, 768/32),  cb>>>(w_qkv, p_wqh,  p_wql,  768,  2304);
    wtconv_k<<<dim3(3072/32, 768/32),  cb>>>(w_m1,  p_wm1h, p_wm1l, 768,  3072);
    wtconv_k<<<dim3(768/32,  3072/32), cb>>>(w_m2,  p_wm2h, p_wm2l, 3072, 768);
    wtconv_k<<<dim3(3072/32, 768/32),  cb>>>(w_f1,  p_wf1h, p_wf1l, 768,  3072);
    wtconv_k<<<dim3(768/32,  3072/32), cb>>>(w_f2,  p_wf2h, p_wf2l, 3072, 768);

    temb1_k<<<72, 128>>>(t, w_ss1, b_ss1);
    temb2_k<<<72, 128>>>(w_ss2, b_ss2);

    ln_mod_k<<<MROWS, 256>>>(x, ln1_g, ln1_b, 0, p_hh, p_hl);

    hgemm_k<0><<<dim3(2304/128, MROWS/128), 256, GEMM_SMEM>>>(
        p_hh, p_hl, p_wqh, p_wql, b_qkv, p_qkv, nullptr, nullptr, 2304, 768, nullptr, 0);

    attn_k<<<dim3(BB * NHD, TT / 128), 128, ATTN_SMEM>>>(p_qkv, p_oh, p_ol);

    hgemm_k<1><<<dim3(3072/128, MROWS/128), 256, GEMM_SMEM>>>(
        p_oh, p_ol, p_wm1h, p_wm1l, b_m1, nullptr, p_uh, p_ul, 3072, 768, nullptr, 0);

    hgemm_k<2><<<dim3(768/128, MROWS/128), 256, GEMM_SMEM>>>(
        p_uh, p_ul, p_wm2h, p_wm2l, b_m2, p_x1, nullptr, nullptr, 768, 3072, x, 1536);

    ln_mod_k<<<MROWS, 256>>>(p_x1, ln2_g, ln2_b, 2304, p_hh, p_hl);

    hgemm_k<1><<<dim3(3072/128, MROWS/128), 256, GEMM_SMEM>>>(
        p_hh, p_hl, p_wf1h, p_wf1l, b_f1, nullptr, p_uh, p_ul, 3072, 768, nullptr, 0);

    hgemm_k<2><<<dim3(768/128, MROWS/128), 256, GEMM_SMEM>>>(
        p_uh, p_ul, p_wf2h, p_wf2l, b_f2, out, nullptr, nullptr, 768, 3072, p_x1, 3840);
}

// round 4
// speedup vs baseline: 2.9871x; 1.3211x over previous
#include <cuda_runtime.h>
#include <cuda_bf16.h>
#include <math.h>
#include <stdint.h>

// ---------------------------------------------------------------------------
// DiT block. GEMMs + flash attention on mma.sync bf16 (2-term split),
// FFMA-based exp2 softmax. B=2, T=2048, H=768, NH=12, HD=64.
// ---------------------------------------------------------------------------

#define HH   768
#define NHD  12
#define HDD  64
#define TT   2048
#define BB   2
#define MROWS (BB*TT)          // 4096

// qscale = log2(e)/sqrt(768)
#define QSCALE 0.05205877172640942f

// ------------------------- scratch (static device) -------------------------
__device__ float g_hid [BB*6*HH];
__device__ float g_temb[BB*6*HH];
__device__ float g_x1  [MROWS*HH];

__device__ __nv_bfloat16 g_h_h[MROWS*HH],   g_h_l[MROWS*HH];
__device__ __nv_bfloat16 g_o_h[MROWS*HH],   g_o_l[MROWS*HH];
__device__ __nv_bfloat16 g_u_h[MROWS*4*HH], g_u_l[MROWS*4*HH];

// attention operands, head-major [b][h][T][64]
__device__ __nv_bfloat16 g_q_h[MROWS*HH], g_q_l[MROWS*HH];
__device__ __nv_bfloat16 g_k_h[MROWS*HH], g_k_l[MROWS*HH];
__device__ __nv_bfloat16 g_v_h[MROWS*HH], g_v_l[MROWS*HH];

__device__ __nv_bfloat16 g_wqkv_h[3*HH*HH],  g_wqkv_l[3*HH*HH];
__device__ __nv_bfloat16 g_wm1_h [4*HH*HH],  g_wm1_l [4*HH*HH];
__device__ __nv_bfloat16 g_wm2_h [HH*4*HH],  g_wm2_l [HH*4*HH];
__device__ __nv_bfloat16 g_wf1_h [4*HH*HH],  g_wf1_l [4*HH*HH];
__device__ __nv_bfloat16 g_wf2_h [HH*4*HH],  g_wf2_l [HH*4*HH];

// ----------------------------- PTX helpers --------------------------------
__device__ __forceinline__ uint32_t smem_u32(const void* p) {
    uint32_t a;
    asm("{ .reg .u64 t; cvta.to.shared.u64 t, %1; cvt.u32.u64 %0, t; }" : "=r"(a) : "l"(p));
    return a;
}
__device__ __forceinline__ void ldsm4(uint32_t* r, uint32_t a) {
    asm volatile("ldmatrix.sync.aligned.m8n8.x4.shared.b16 {%0,%1,%2,%3}, [%4];"
        : "=r"(r[0]), "=r"(r[1]), "=r"(r[2]), "=r"(r[3]) : "r"(a));
}
__device__ __forceinline__ void ldsm4t(uint32_t* r, uint32_t a) {
    asm volatile("ldmatrix.sync.aligned.m8n8.x4.trans.shared.b16 {%0,%1,%2,%3}, [%4];"
        : "=r"(r[0]), "=r"(r[1]), "=r"(r[2]), "=r"(r[3]) : "r"(a));
}
__device__ __forceinline__ void mma16816(float* d, const uint32_t* a, const uint32_t* b) {
    asm volatile("mma.sync.aligned.m16n8k16.row.col.f32.bf16.bf16.f32 "
        "{%0,%1,%2,%3},{%4,%5,%6,%7},{%8,%9},{%0,%1,%2,%3};"
        : "+f"(d[0]), "+f"(d[1]), "+f"(d[2]), "+f"(d[3])
        : "r"(a[0]), "r"(a[1]), "r"(a[2]), "r"(a[3]), "r"(b[0]), "r"(b[1]));
}
__device__ __forceinline__ void cpasync16(uint32_t dst, const void* src) {
    asm volatile("cp.async.cg.shared.global [%0], [%1], 16;" :: "r"(dst), "l"(src) : "memory");
}
#define CP_COMMIT() asm volatile("cp.async.commit_group;" ::: "memory")
#define CP_WAIT(n)  asm volatile("cp.async.wait_group %0;" :: "n"(n) : "memory")

__device__ __forceinline__ float warp_sum(float v) {
    #pragma unroll
    for (int o = 16; o; o >>= 1) v += __shfl_xor_sync(0xffffffffu, v, o);
    return v;
}
__device__ __forceinline__ void split_store(float v, __nv_bfloat16* ph, __nv_bfloat16* pl) {
    __nv_bfloat16 hi = __float2bfloat16(v);
    *ph = hi;
    *pl = __float2bfloat16(v - __bfloat162float(hi));
}
// pack two floats into bf16x2 hi and lo-residual words
__device__ __forceinline__ void split2(float x, float y, uint32_t& hi, uint32_t& lo) {
    __nv_bfloat162 h;
    h.x = __float2bfloat16(x); h.y = __float2bfloat16(y);
    hi = *(uint32_t*)&h;
    __nv_bfloat162 l;
    l.x = __float2bfloat16(x - __bfloat162float(h.x));
    l.y = __float2bfloat16(y - __bfloat162float(h.y));
    lo = *(uint32_t*)&l;
}
// FFMA-pipe exp2 for t <= 0 (7-term Taylor for 2^f, f in [0,1)); err ~1e-5
__device__ __forceinline__ float exp2fast(float t) {
    t = fmaxf(t, -126.0f);
    float fi = floorf(t);
    float f = t - fi;
    float p = 1.5435291e-4f;
    p = p * f + 1.3333558e-3f;
    p = p * f + 9.6181291e-3f;
    p = p * f + 5.5504109e-2f;
    p = p * f + 2.4022651e-1f;
    p = p * f + 6.9314718e-1f;
    p = p * f + 1.0f;
    return __int_as_float(((int)fi + 127) << 23) * p;
}

// ------------------------------- temb path --------------------------------
__global__ void temb1_k(const float* __restrict__ t, const float* __restrict__ W,
                        const float* __restrict__ bias) {
    int gid = blockIdx.x * blockDim.x + threadIdx.x;
    int b = gid / 4608, n = gid % 4608;
    const float* tr = t + b * HH;
    float acc = bias[n];
    #pragma unroll 4
    for (int k = 0; k < HH; k++) acc += tr[k] * W[(size_t)k * 4608 + n];
    g_hid[gid] = acc / (1.0f + expf(-acc));
}
__global__ void temb2_k(const float* __restrict__ W, const float* __restrict__ bias) {
    int gid = blockIdx.x * blockDim.x + threadIdx.x;
    int b = gid / 4608, n = gid % 4608;
    const float* hr = g_hid + b * 4608;
    float acc = bias[n];
    #pragma unroll 4
    for (int k = 0; k < 4608; k++) acc += hr[k] * W[(size_t)k * 4608 + n];
    g_temb[gid] = acc;
}

// -------------------- weight transpose + bf16 split ------------------------
__global__ void wtconv_k(const float* __restrict__ W, __nv_bfloat16* __restrict__ Oh,
                         __nv_bfloat16* __restrict__ Ol, int K, int N) {
    __shared__ float s[32][33];
    int tx = threadIdx.x, ty = threadIdx.y;
    int n0 = blockIdx.x * 32, k0 = blockIdx.y * 32;
    #pragma unroll
    for (int j = 0; j < 32; j += 8)
        s[ty + j][tx] = W[(size_t)(k0 + ty + j) * N + n0 + tx];
    __syncthreads();
    #pragma unroll
    for (int j = 0; j < 32; j += 8) {
        float v = s[tx][ty + j];
        size_t o = (size_t)(n0 + ty + j) * K + k0 + tx;
        __nv_bfloat16 hi = __float2bfloat16(v);
        Oh[o] = hi;
        Ol[o] = __float2bfloat16(v - __bfloat162float(hi));
    }
}

// --------------------------- LayerNorm + modulate --------------------------
__global__ void ln_mod_k(const float* __restrict__ x,
                         const float* __restrict__ lng, const float* __restrict__ lnb,
                         int goff, __nv_bfloat16* __restrict__ yh,
                         __nv_bfloat16* __restrict__ yl) {
    int row = blockIdx.x;
    int b = row >> 11;
    const float* xr = x + (size_t)row * HH;
    int tid = threadIdx.x, lane = tid & 31, wid = tid >> 5;

    float s = 0.f, s2 = 0.f;
    #pragma unroll
    for (int i = tid; i < HH; i += 256) { float v = xr[i]; s += v; s2 += v * v; }
    s = warp_sum(s); s2 = warp_sum(s2);
    __shared__ float sh[2][8];
    if (lane == 0) { sh[0][wid] = s; sh[1][wid] = s2; }
    __syncthreads();
    if (wid == 0) {
        float a  = (lane < 8) ? sh[0][lane] : 0.f;
        float a2 = (lane < 8) ? sh[1][lane] : 0.f;
        a = warp_sum(a); a2 = warp_sum(a2);
        if (lane == 0) { sh[0][0] = a; sh[1][0] = a2; }
    }
    __syncthreads();
    const float inv = 1.0f / 768.0f;
    float mu  = sh[0][0] * inv;
    float var = sh[1][0] * inv - mu * mu;
    float rs  = rsqrtf(var + 1e-5f);
    const float* tb = g_temb + b * 4608;
    #pragma unroll
    for (int i = tid; i < HH; i += 256) {
        float v = (xr[i] - mu) * rs * lng[i] + lnb[i];
        v = tb[goff + i] * v + tb[goff + 768 + i];
        split_store(v, yh + (size_t)row * HH + i, yl + (size_t)row * HH + i);
    }
}

// ------------------------------ HMMA GEMM ----------------------------------
// EPI: 1=gelu->bf16 split, 2=residual+gate->fp32, 3=qkv->scaled split q/k/v
#define ATILE 10240             // 128 rows * 80B
#define STAGE (4*ATILE)
#define GEMM_SMEM (2*STAGE)     // 81920
template <int EPI>
__global__ void __launch_bounds__(256) hgemm_k(
    const __nv_bfloat16* __restrict__ Ah, const __nv_bfloat16* __restrict__ Al,
    const __nv_bfloat16* __restrict__ Bh, const __nv_bfloat16* __restrict__ Bl,
    const float* __restrict__ bias,
    float* __restrict__ Cf,
    __nv_bfloat16* __restrict__ Ch, __nv_bfloat16* __restrict__ Cl,
    int N, int K,
    const float* __restrict__ res, int gate_off) {

    extern __shared__ char sm[];
    const uint32_t sbase = smem_u32(sm);
    const int tid = threadIdx.x, lane = tid & 31, wid = tid >> 5;
    const int bm = blockIdx.y, bn = blockIdx.x;
    const int am0 = bm * 128, bn0 = bn * 128;
    const int wm0 = (wid >> 1) * 32, wn0 = (wid & 1) * 64;

    float acc[2][8][4];
    #pragma unroll
    for (int i = 0; i < 2; i++)
        #pragma unroll
        for (int j = 0; j < 8; j++)
            #pragma unroll
            for (int q = 0; q < 4; q++) acc[i][j][q] = 0.f;

    const __nv_bfloat16* mats[4] = {Ah, Al, Bh, Bl};
    const __nv_bfloat16* srcb[8];
    uint32_t dstb[8];
    #pragma unroll
    for (int it = 0; it < 8; it++) {
        int idx = tid + it * 256;
        int mat = idx >> 9, r = (idx >> 2) & 127, c = idx & 3;
        int grow = (mat < 2 ? am0 : bn0) + r;
        srcb[it] = mats[mat] + (size_t)grow * K + c * 8;
        dstb[it] = sbase + mat * ATILE + r * 80 + c * 16;
    }

    uint32_t aaddr[2][2];
    #pragma unroll
    for (int t = 0; t < 2; t++)
        #pragma unroll
        for (int mi = 0; mi < 2; mi++) {
            int row = wm0 + mi * 16 + (lane & 15);
            aaddr[t][mi] = sbase + t * ATILE + row * 80 + ((lane >> 4) << 4);
        }
    uint32_t baddr[2][4];
    #pragma unroll
    for (int t = 0; t < 2; t++)
        #pragma unroll
        for (int ng = 0; ng < 4; ng++) {
            int row = wn0 + ng * 16 + (lane & 7) + ((lane & 16) >> 1);
            baddr[t][ng] = sbase + (2 + t) * ATILE + row * 80 + ((lane & 8) ? 16 : 0);
        }

    const int KB = K >> 5;
    {
        #pragma unroll
        for (int it = 0; it < 8; it++) cpasync16(dstb[it], srcb[it]);
        CP_COMMIT();
    }

    for (int kb = 0; kb < KB; kb++) {
        const uint32_t so = (kb & 1) * STAGE;
        if (kb + 1 < KB) {
            const uint32_t so2 = ((kb + 1) & 1) * STAGE;
            const int ko = (kb + 1) << 5;
            #pragma unroll
            for (int it = 0; it < 8; it++) cpasync16(dstb[it] + so2, srcb[it] + ko);
            CP_COMMIT();
            CP_WAIT(1);
        } else {
            CP_WAIT(0);
        }
        __syncthreads();

        #pragma unroll
        for (int ks = 0; ks < 2; ks++) {
            const uint32_t ko = so + ks * 32;
            uint32_t ah[2][4], al[2][4];
            ldsm4(ah[0], aaddr[0][0] + ko);
            ldsm4(ah[1], aaddr[0][1] + ko);
            ldsm4(al[0], aaddr[1][0] + ko);
            ldsm4(al[1], aaddr[1][1] + ko);

            uint32_t b[8][2];
            #pragma unroll
            for (int ng = 0; ng < 4; ng++) {
                uint32_t r[4];
                ldsm4(r, baddr[0][ng] + ko);
                b[2*ng][0] = r[0]; b[2*ng][1] = r[1];
                b[2*ng+1][0] = r[2]; b[2*ng+1][1] = r[3];
            }
            #pragma unroll
            for (int mi = 0; mi < 2; mi++)
                #pragma unroll
                for (int ni = 0; ni < 8; ni++) {
                    mma16816(acc[mi][ni], ah[mi], b[ni]);
                    mma16816(acc[mi][ni], al[mi], b[ni]);
                }
            #pragma unroll
            for (int ng = 0; ng < 4; ng++) {
                uint32_t r[4];
                ldsm4(r, baddr[1][ng] + ko);
                b[2*ng][0] = r[0]; b[2*ng][1] = r[1];
                b[2*ng+1][0] = r[2]; b[2*ng+1][1] = r[3];
            }
            #pragma unroll
            for (int mi = 0; mi < 2; mi++)
                #pragma unroll
                for (int ni = 0; ni < 8; ni++)
                    mma16816(acc[mi][ni], ah[mi], b[ni]);
        }
        __syncthreads();
    }

    // ----------------------------- epilogue -------------------------------
    const int rbase = am0 + wm0 + (lane >> 2);
    const int cbase = bn0 + wn0 + (lane & 3) * 2;
    #pragma unroll
    for (int mi = 0; mi < 2; mi++) {
        #pragma unroll
        for (int ni = 0; ni < 8; ni++) {
            int col = cbase + ni * 8;
            float2 bb = *(const float2*)&bias[col];
            #pragma unroll
            for (int half = 0; half < 2; half++) {
                int row = rbase + mi * 16 + half * 8;
                float v0 = acc[mi][ni][2*half]   + bb.x;
                float v1 = acc[mi][ni][2*half+1] + bb.y;
                if (EPI == 1) {
                    v0 = 0.5f * v0 * (1.0f + erff(v0 * 0.70710678118654752f));
                    v1 = 0.5f * v1 * (1.0f + erff(v1 * 0.70710678118654752f));
                    uint32_t hi, lo;
                    split2(v0, v1, hi, lo);
                    size_t o = (size_t)row * N + col;
                    *(uint32_t*)(Ch + o) = hi;
                    *(uint32_t*)(Cl + o) = lo;
                } else if (EPI == 3) {
                    int i3 = col / 768;
                    int rem = col - i3 * 768;
                    int hh = rem >> 6, d = rem & 63;
                    int b2 = row >> 11, t2 = row & 2047;
                    size_t idx = ((size_t)((b2 * NHD + hh) * TT + t2)) * HDD + d;
                    if (i3 == 0) { v0 *= QSCALE; v1 *= QSCALE; }
                    uint32_t hi, lo;
                    split2(v0, v1, hi, lo);
                    __nv_bfloat16* dh = (i3 == 0) ? g_q_h : (i3 == 1) ? g_k_h : g_v_h;
                    __nv_bfloat16* dl = (i3 == 0) ? g_q_l : (i3 == 1) ? g_k_l : g_v_l;
                    *(uint32_t*)(dh + idx) = hi;
                    *(uint32_t*)(dl + idx) = lo;
                } else {
                    if (EPI == 2) {
                        const float* tb = g_temb + (row >> 11) * 4608 + gate_off;
                        float2 rr = *(const float2*)&res[(size_t)row * N + col];
                        float2 gg = *(const float2*)&tb[col];
                        v0 = rr.x + gg.x * v0;
                        v1 = rr.y + gg.y * v1;
                    }
                    float2 o2; o2.x = v0; o2.y = v1;
                    *(float2*)&Cf[(size_t)row * N + col] = o2;
                }
            }
        }
    }
}

// -------------------- tensor-core flash attention --------------------------
// CTA: one (b,h) x 128 queries; 8 warps x 16 rows. KV tiles of 64 keys.
// smem rows padded to 72 bf16 (144B) for conflict-free ldmatrix.
#define RS   144                 // row stride bytes
#define QB   (128*RS)            // 18432 per Q matrix
#define KVT  (64*RS)             // 9216 per KV matrix tile
#define STG  (4*KVT)             // 36864 per stage
#define ATTN_SMEM (2*QB + 2*STG) // 110592
__global__ void __launch_bounds__(256) attn_tc(void) {
    extern __shared__ char sm[];
    const uint32_t sbase = smem_u32(sm);
    const int tid = threadIdx.x, lane = tid & 31, wid = tid >> 5;
    const int bh = blockIdx.x;            // 0..23
    const int qb = blockIdx.y;            // 0..15
    const size_t headbase = (size_t)bh * TT * HDD;

    // cp.async assignments
    const __nv_bfloat16* qmats[2] = {g_q_h, g_q_l};
    const __nv_bfloat16* kvmats[4] = {g_k_h, g_k_l, g_v_h, g_v_l};

    // load Q block [128][64] hi/lo
    #pragma unroll
    for (int it = 0; it < 8; it++) {
        int idx = tid + it * 256;
        int mat = idx >> 10, r = (idx >> 3) & 127, c = idx & 7;
        cpasync16(sbase + mat * QB + r * RS + c * 16,
                  qmats[mat] + headbase + (size_t)(qb * 128 + r) * HDD + c * 8);
    }
    // stage 0
    #pragma unroll
    for (int it = 0; it < 8; it++) {
        int idx = tid + it * 256;
        int mat = idx >> 9, r = (idx >> 3) & 63, c = idx & 7;
        cpasync16(sbase + 2 * QB + mat * KVT + r * RS + c * 16,
                  kvmats[mat] + headbase + (size_t)r * HDD + c * 8);
    }
    CP_COMMIT();

    // per-warp frag addresses
    uint32_t qoff = (uint32_t)((wid * 16 + (lane & 15)) * RS + ((lane & 16) ? 16 : 0));
    uint32_t koff[4], voff[4];
    #pragma unroll
    for (int ng = 0; ng < 4; ng++) {
        koff[ng] = (uint32_t)((ng * 16 + (lane & 7) + ((lane & 16) >> 1)) * RS
                              + ((lane & 8) ? 16 : 0));
        voff[ng] = (uint32_t)(((lane & 7) + (lane & 8)) * RS + ng * 32
                              + ((lane & 16) ? 16 : 0));
    }

    uint32_t qh[4][4], ql[4][4];
    float o[8][4];
    #pragma unroll
    for (int n = 0; n < 8; n++)
        #pragma unroll
        for (int j = 0; j < 4; j++) o[n][j] = 0.f;
    float m0 = -1e30f, m1 = -1e30f, l0 = 0.f, l1 = 0.f;

    const int NT = TT / 64;   // 32
    for (int t = 0; t < NT; t++) {
        if (t + 1 < NT) {
            const uint32_t sb2 = sbase + 2 * QB + ((t + 1) & 1) * STG;
            const size_t kvb = headbase + (size_t)(t + 1) * 64 * HDD;
            #pragma unroll
            for (int it = 0; it < 8; it++) {
                int idx = tid + it * 256;
                int mat = idx >> 9, r = (idx >> 3) & 63, c = idx & 7;
                cpasync16(sb2 + mat * KVT + r * RS + c * 16,
                          kvmats[mat] + kvb + (size_t)r * HDD + c * 8);
            }
            CP_COMMIT();
            CP_WAIT(1);
        } else {
            CP_WAIT(0);
        }
        __syncthreads();

        if (t == 0) {
            #pragma unroll
            for (int kc = 0; kc < 4; kc++) {
                ldsm4(qh[kc], sbase + qoff + kc * 32);
                ldsm4(ql[kc], sbase + QB + qoff + kc * 32);
            }
        }

        const uint32_t stb = sbase + 2 * QB + (t & 1) * STG;

        // ---- S = Qh*Kh + Ql*Kh + Qh*Kl ----
        float c[8][4];
        #pragma unroll
        for (int n = 0; n < 8; n++)
            #pragma unroll
            for (int j = 0; j < 4; j++) c[n][j] = 0.f;

        #pragma unroll
        for (int kc = 0; kc < 4; kc++) {
            uint32_t b[8][2];
            #pragma unroll
            for (int ng = 0; ng < 4; ng++) {
                uint32_t r[4];
                ldsm4(r, stb + koff[ng] + kc * 32);
                b[2*ng][0] = r[0]; b[2*ng][1] = r[1];
                b[2*ng+1][0] = r[2]; b[2*ng+1][1] = r[3];
            }
            #pragma unroll
            for (int n = 0; n < 8; n++) mma16816(c[n], qh[kc], b[n]);
            #pragma unroll
            for (int n = 0; n < 8; n++) mma16816(c[n], ql[kc], b[n]);
            #pragma unroll
            for (int ng = 0; ng < 4; ng++) {
                uint32_t r[4];
                ldsm4(r, stb + KVT + koff[ng] + kc * 32);
                b[2*ng][0] = r[0]; b[2*ng][1] = r[1];
                b[2*ng+1][0] = r[2]; b[2*ng+1][1] = r[3];
            }
            #pragma unroll
            for (int n = 0; n < 8; n++) mma16816(c[n], qh[kc], b[n]);
        }

        // ---- online softmax (log2 domain; scale folded into Q) ----
        float mx0 = -1e30f, mx1 = -1e30f;
        #pragma unroll
        for (int n = 0; n < 8; n++) {
            mx0 = fmaxf(mx0, fmaxf(c[n][0], c[n][1]));
            mx1 = fmaxf(mx1, fmaxf(c[n][2], c[n][3]));
        }
        mx0 = fmaxf(mx0, __shfl_xor_sync(0xffffffffu, mx0, 1));
        mx0 = fmaxf(mx0, __shfl_xor_sync(0xffffffffu, mx0, 2));
        mx1 = fmaxf(mx1, __shfl_xor_sync(0xffffffffu, mx1, 1));
        mx1 = fmaxf(mx1, __shfl_xor_sync(0xffffffffu, mx1, 2));
        float mn0 = fmaxf(m0, mx0), mn1 = fmaxf(m1, mx1);
        float cr0 = exp2fast(m0 - mn0), cr1 = exp2fast(m1 - mn1);
        m0 = mn0; m1 = mn1;
        l0 *= cr0; l1 *= cr1;
        #pragma unroll
        for (int n = 0; n < 8; n++) {
            o[n][0] *= cr0; o[n][1] *= cr0;
            o[n][2] *= cr1; o[n][3] *= cr1;
        }
        uint32_t pah[4][4], pal[4][4];
        #pragma unroll
        for (int n = 0; n < 8; n++) {
            float p00 = exp2fast(c[n][0] - mn0);
            float p01 = exp2fast(c[n][1] - mn0);
            float p10 = exp2fast(c[n][2] - mn1);
            float p11 = exp2fast(c[n][3] - mn1);
            l0 += p00 + p01; l1 += p10 + p11;
            int kc = n >> 1, s = (n & 1) * 2;
            split2(p00, p01, pah[kc][s],     pal[kc][s]);
            split2(p10, p11, pah[kc][s + 1], pal[kc][s + 1]);
        }

        // ---- O += Ph*Vh + Pl*Vh + Ph*Vl ----
        #pragma unroll
        for (int kc = 0; kc < 4; kc++) {
            uint32_t b[8][2];
            #pragma unroll
            for (int ng = 0; ng < 4; ng++) {
                uint32_t r[4];
                ldsm4t(r, stb + 2 * KVT + voff[ng] + kc * 16 * RS);
                b[2*ng][0] = r[0]; b[2*ng][1] = r[1];
                b[2*ng+1][0] = r[2]; b[2*ng+1][1] = r[3];
            }
            #pragma unroll
            for (int n = 0; n < 8; n++) mma16816(o[n], pah[kc], b[n]);
            #pragma unroll
            for (int n = 0; n < 8; n++) mma16816(o[n], pal[kc], b[n]);
            #pragma unroll
            for (int ng = 0; ng < 4; ng++) {
                uint32_t r[4];
                ldsm4t(r, stb + 3 * KVT + voff[ng] + kc * 16 * RS);
                b[2*ng][0] = r[0]; b[2*ng][1] = r[1];
                b[2*ng+1][0] = r[2]; b[2*ng+1][1] = r[3];
            }
            #pragma unroll
            for (int n = 0; n < 8; n++) mma16816(o[n], pah[kc], b[n]);
        }
        __syncthreads();
    }

    // final normalize + write split O to [token][768]
    l0 += __shfl_xor_sync(0xffffffffu, l0, 1);
    l0 += __shfl_xor_sync(0xffffffffu, l0, 2);
    l1 += __shfl_xor_sync(0xffffffffu, l1, 1);
    l1 += __shfl_xor_sync(0xffffffffu, l1, 2);
    float i0 = 1.0f / l0, i1 = 1.0f / l1;

    const int b2 = bh / NHD, h2 = bh % NHD;
    const int r0 = qb * 128 + wid * 16 + (lane >> 2);
    const int cb = h2 * 64 + (lane & 3) * 2;
    #pragma unroll
    for (int n = 0; n < 8; n++) {
        int col = cb + n * 8;
        uint32_t hi, lo;
        size_t o0 = (size_t)(b2 * TT + r0) * HH + col;
        split2(o[n][0] * i0, o[n][1] * i0, hi, lo);
        *(uint32_t*)(g_o_h + o0) = hi;
        *(uint32_t*)(g_o_l + o0) = lo;
        size_t o1 = (size_t)(b2 * TT + r0 + 8) * HH + col;
        split2(o[n][2] * i1, o[n][3] * i1, hi, lo);
        *(uint32_t*)(g_o_h + o1) = hi;
        *(uint32_t*)(g_o_l + o1) = lo;
    }
}

// ------------------------------- launcher ----------------------------------
extern "C" void kernel_launch(void* const* d_in, const int* in_sizes, int n_in,
                              void* d_out, int out_size) {
    const float* x      = (const float*)d_in[0];
    const float* t      = (const float*)d_in[1];
    const float* w_qkv  = (const float*)d_in[2];
    const float* b_qkv  = (const float*)d_in[3];
    const float* w_m1   = (const float*)d_in[4];
    const float* b_m1   = (const float*)d_in[5];
    const float* w_m2   = (const float*)d_in[6];
    const float* b_m2   = (const float*)d_in[7];
    const float* w_ss1  = (const float*)d_in[8];
    const float* b_ss1  = (const float*)d_in[9];
    const float* w_ss2  = (const float*)d_in[10];
    const float* b_ss2  = (const float*)d_in[11];
    const float* ln1_g  = (const float*)d_in[12];
    const float* ln1_b  = (const float*)d_in[13];
    const float* ln2_g  = (const float*)d_in[14];
    const float* ln2_b  = (const float*)d_in[15];
    const float* w_f1   = (const float*)d_in[16];
    const float* b_f1   = (const float*)d_in[17];
    const float* w_f2   = (const float*)d_in[18];
    const float* b_f2   = (const float*)d_in[19];
    float* out = (float*)d_out;

    float *p_x1;
    __nv_bfloat16 *p_hh, *p_hl, *p_oh, *p_ol, *p_uh, *p_ul;
    __nv_bfloat16 *p_wqh, *p_wql, *p_wm1h, *p_wm1l, *p_wm2h, *p_wm2l,
                  *p_wf1h, *p_wf1l, *p_wf2h, *p_wf2l;
    cudaGetSymbolAddress((void**)&p_x1,  g_x1);
    cudaGetSymbolAddress((void**)&p_hh,  g_h_h);  cudaGetSymbolAddress((void**)&p_hl, g_h_l);
    cudaGetSymbolAddress((void**)&p_oh,  g_o_h);  cudaGetSymbolAddress((void**)&p_ol, g_o_l);
    cudaGetSymbolAddress((void**)&p_uh,  g_u_h);  cudaGetSymbolAddress((void**)&p_ul, g_u_l);
    cudaGetSymbolAddress((void**)&p_wqh, g_wqkv_h);  cudaGetSymbolAddress((void**)&p_wql, g_wqkv_l);
    cudaGetSymbolAddress((void**)&p_wm1h, g_wm1_h);  cudaGetSymbolAddress((void**)&p_wm1l, g_wm1_l);
    cudaGetSymbolAddress((void**)&p_wm2h, g_wm2_h);  cudaGetSymbolAddress((void**)&p_wm2l, g_wm2_l);
    cudaGetSymbolAddress((void**)&p_wf1h, g_wf1_h);  cudaGetSymbolAddress((void**)&p_wf1l, g_wf1_l);
    cudaGetSymbolAddress((void**)&p_wf2h, g_wf2_h);  cudaGetSymbolAddress((void**)&p_wf2l, g_wf2_l);

    cudaFuncSetAttribute(attn_tc, cudaFuncAttributeMaxDynamicSharedMemorySize, ATTN_SMEM);
    cudaFuncSetAttribute(hgemm_k<1>, cudaFuncAttributeMaxDynamicSharedMemorySize, GEMM_SMEM);
    cudaFuncSetAttribute(hgemm_k<2>, cudaFuncAttributeMaxDynamicSharedMemorySize, GEMM_SMEM);
    cudaFuncSetAttribute(hgemm_k<3>, cudaFuncAttributeMaxDynamicSharedMemorySize, GEMM_SMEM);

    dim3 cb(32, 8);
    wtconv_k<<<dim3(2304/32, 768/32),  cb>>>(w_qkv, p_wqh,  p_wql,  768,  2304);
    wtconv_k<<<dim3(3072/32, 768/32),  cb>>>(w_m1,  p_wm1h, p_wm1l, 768,  3072);
    wtconv_k<<<dim3(768/32,  3072/32), cb>>>(w_m2,  p_wm2h, p_wm2l, 3072, 768);
    wtconv_k<<<dim3(3072/32, 768/32),  cb>>>(w_f1,  p_wf1h, p_wf1l, 768,  3072);
    wtconv_k<<<dim3(768/32,  3072/32), cb>>>(w_f2,  p_wf2h, p_wf2l, 3072, 768);

    temb1_k<<<72, 128>>>(t, w_ss1, b_ss1);
    temb2_k<<<72, 128>>>(w_ss2, b_ss2);

    ln_mod_k<<<MROWS, 256>>>(x, ln1_g, ln1_b, 0, p_hh, p_hl);

    // qkv = h @ Wqkv + b -> split q(scaled)/k/v head-major
    hgemm_k<3><<<dim3(2304/128, MROWS/128), 256, GEMM_SMEM>>>(
        p_hh, p_hl, p_wqh, p_wql, b_qkv, nullptr, nullptr, nullptr, 2304, 768, nullptr, 0);

    attn_tc<<<dim3(BB * NHD, TT / 128), 256, ATTN_SMEM>>>();

    hgemm_k<1><<<dim3(3072/128, MROWS/128), 256, GEMM_SMEM>>>(
        p_oh, p_ol, p_wm1h, p_wm1l, b_m1, nullptr, p_uh, p_ul, 3072, 768, nullptr, 0);

    hgemm_k<2><<<dim3(768/128, MROWS/128), 256, GEMM_SMEM>>>(
        p_uh, p_ul, p_wm2h, p_wm2l, b_m2, p_x1, nullptr, nullptr, 768, 3072, x, 1536);

    ln_mod_k<<<MROWS, 256>>>(p_x1, ln2_g, ln2_b, 2304, p_hh, p_hl);

    hgemm_k<1><<<dim3(3072/128, MROWS/128), 256, GEMM_SMEM>>>(
        p_hh, p_hl, p_wf1h, p_wf1l, b_f1, nullptr, p_uh, p_ul, 3072, 768, nullptr, 0);

    hgemm_k<2><<<dim3(768/128, MROWS/128), 256, GEMM_SMEM>>>(
        p_uh, p_ul, p_wf2h, p_wf2l, b_f2, out, nullptr, nullptr, 768, 3072, p_x1, 3840);
}

// round 5
// speedup vs baseline: 5.1760x; 1.7328x over previous
#include <cuda_runtime.h>
#include <cuda_fp16.h>
#include <math.h>
#include <stdint.h>

// ---------------------------------------------------------------------------
// DiT block. GEMMs + flash attention on plain fp16 mma.sync (f32 accum),
// FFMA exp2 softmax. B=2, T=2048, H=768, NH=12, HD=64.
// ---------------------------------------------------------------------------

#define HH   768
#define NHD  12
#define HDD  64
#define TT   2048
#define BB   2
#define MROWS (BB*TT)          // 4096

// qscale = log2(e)/sqrt(768)
#define QSCALE 0.05205877172640942f

// ------------------------- scratch (static device) -------------------------
__device__ float g_hid [BB*6*HH];
__device__ float g_temb[BB*6*HH];
__device__ float g_x1  [MROWS*HH];

__device__ __half g_h[MROWS*HH];
__device__ __half g_o[MROWS*HH];
__device__ __half g_u[MROWS*4*HH];

// attention operands, head-major [b][h][T][64]
__device__ __half g_q[MROWS*HH];
__device__ __half g_k[MROWS*HH];
__device__ __half g_v[MROWS*HH];

// transposed fp16 weights  W[K,N] -> Wt[N,K]
__device__ __half g_wqkv[3*HH*HH];
__device__ __half g_wm1 [4*HH*HH];
__device__ __half g_wm2 [HH*4*HH];
__device__ __half g_wf1 [4*HH*HH];
__device__ __half g_wf2 [HH*4*HH];

// ----------------------------- PTX helpers --------------------------------
__device__ __forceinline__ uint32_t smem_u32(const void* p) {
    uint32_t a;
    asm("{ .reg .u64 t; cvta.to.shared.u64 t, %1; cvt.u32.u64 %0, t; }" : "=r"(a) : "l"(p));
    return a;
}
__device__ __forceinline__ void ldsm4(uint32_t* r, uint32_t a) {
    asm volatile("ldmatrix.sync.aligned.m8n8.x4.shared.b16 {%0,%1,%2,%3}, [%4];"
        : "=r"(r[0]), "=r"(r[1]), "=r"(r[2]), "=r"(r[3]) : "r"(a));
}
__device__ __forceinline__ void ldsm4t(uint32_t* r, uint32_t a) {
    asm volatile("ldmatrix.sync.aligned.m8n8.x4.trans.shared.b16 {%0,%1,%2,%3}, [%4];"
        : "=r"(r[0]), "=r"(r[1]), "=r"(r[2]), "=r"(r[3]) : "r"(a));
}
__device__ __forceinline__ void mma16816(float* d, const uint32_t* a, const uint32_t* b) {
    asm volatile("mma.sync.aligned.m16n8k16.row.col.f32.f16.f16.f32 "
        "{%0,%1,%2,%3},{%4,%5,%6,%7},{%8,%9},{%0,%1,%2,%3};"
        : "+f"(d[0]), "+f"(d[1]), "+f"(d[2]), "+f"(d[3])
        : "r"(a[0]), "r"(a[1]), "r"(a[2]), "r"(a[3]), "r"(b[0]), "r"(b[1]));
}
__device__ __forceinline__ void cpasync16(uint32_t dst, const void* src) {
    asm volatile("cp.async.cg.shared.global [%0], [%1], 16;" :: "r"(dst), "l"(src) : "memory");
}
#define CP_COMMIT() asm volatile("cp.async.commit_group;" ::: "memory")
#define CP_WAIT(n)  asm volatile("cp.async.wait_group %0;" :: "n"(n) : "memory")

__device__ __forceinline__ float warp_sum(float v) {
    #pragma unroll
    for (int o = 16; o; o >>= 1) v += __shfl_xor_sync(0xffffffffu, v, o);
    return v;
}
__device__ __forceinline__ uint32_t pack_h2(float x, float y) {
    __half2 h = __floats2half2_rn(x, y);
    return *(uint32_t*)&h;
}
// FFMA-pipe exp2 for t <= 0; err ~1e-5
__device__ __forceinline__ float exp2fast(float t) {
    t = fmaxf(t, -126.0f);
    float fi = floorf(t);
    float f = t - fi;
    float p = 1.5435291e-4f;
    p = p * f + 1.3333558e-3f;
    p = p * f + 9.6181291e-3f;
    p = p * f + 5.5504109e-2f;
    p = p * f + 2.4022651e-1f;
    p = p * f + 6.9314718e-1f;
    p = p * f + 1.0f;
    return __int_as_float(((int)fi + 127) << 23) * p;
}

// ------------------------------- temb path --------------------------------
__global__ void temb1_k(const float* __restrict__ t, const float* __restrict__ W,
                        const float* __restrict__ bias) {
    int gid = blockIdx.x * blockDim.x + threadIdx.x;
    int b = gid / 4608, n = gid % 4608;
    const float* tr = t + b * HH;
    float acc = bias[n];
    #pragma unroll 4
    for (int k = 0; k < HH; k++) acc += tr[k] * W[(size_t)k * 4608 + n];
    g_hid[gid] = acc / (1.0f + expf(-acc));
}
__global__ void temb2_k(const float* __restrict__ W, const float* __restrict__ bias) {
    int gid = blockIdx.x * blockDim.x + threadIdx.x;
    int b = gid / 4608, n = gid % 4608;
    const float* hr = g_hid + b * 4608;
    float acc = bias[n];
    #pragma unroll 4
    for (int k = 0; k < 4608; k++) acc += hr[k] * W[(size_t)k * 4608 + n];
    g_temb[gid] = acc;
}

// -------------------- weight transpose + fp16 convert ----------------------
__global__ void wtconv_k(const float* __restrict__ W, __half* __restrict__ O,
                         int K, int N) {
    __shared__ float s[32][33];
    int tx = threadIdx.x, ty = threadIdx.y;
    int n0 = blockIdx.x * 32, k0 = blockIdx.y * 32;
    #pragma unroll
    for (int j = 0; j < 32; j += 8)
        s[ty + j][tx] = W[(size_t)(k0 + ty + j) * N + n0 + tx];
    __syncthreads();
    #pragma unroll
    for (int j = 0; j < 32; j += 8)
        O[(size_t)(n0 + ty + j) * K + k0 + tx] = __float2half(s[tx][ty + j]);
}

// --------------------------- LayerNorm + modulate --------------------------
__global__ void ln_mod_k(const float* __restrict__ x,
                         const float* __restrict__ lng, const float* __restrict__ lnb,
                         int goff, __half* __restrict__ y) {
    int row = blockIdx.x;
    int b = row >> 11;
    const float* xr = x + (size_t)row * HH;
    int tid = threadIdx.x, lane = tid & 31, wid = tid >> 5;

    float s = 0.f, s2 = 0.f;
    #pragma unroll
    for (int i = tid; i < HH; i += 256) { float v = xr[i]; s += v; s2 += v * v; }
    s = warp_sum(s); s2 = warp_sum(s2);
    __shared__ float sh[2][8];
    if (lane == 0) { sh[0][wid] = s; sh[1][wid] = s2; }
    __syncthreads();
    if (wid == 0) {
        float a  = (lane < 8) ? sh[0][lane] : 0.f;
        float a2 = (lane < 8) ? sh[1][lane] : 0.f;
        a = warp_sum(a); a2 = warp_sum(a2);
        if (lane == 0) { sh[0][0] = a; sh[1][0] = a2; }
    }
    __syncthreads();
    const float inv = 1.0f / 768.0f;
    float mu  = sh[0][0] * inv;
    float var = sh[1][0] * inv - mu * mu;
    float rs  = rsqrtf(var + 1e-5f);
    const float* tb = g_temb + b * 4608;
    #pragma unroll
    for (int i = tid; i < HH; i += 256) {
        float v = (xr[i] - mu) * rs * lng[i] + lnb[i];
        y[(size_t)row * HH + i] = __float2half(tb[goff + i] * v + tb[goff + 768 + i]);
    }
}

// ------------------------------ HMMA GEMM ----------------------------------
// C[4096,N] = A[4096,K] @ Bt[N,K]^T + bias (fp16 in, fp32 accum)
// CTA 128x128, 8 warps of 32x64; K staged by 32; 4-stage cp.async ring.
// EPI: 1=gelu->fp16, 2=residual+gate->fp32, 3=qkv->scaled fp16 q/k/v
#define ATILE 10240             // 128 rows * 80B
#define STAGE (2*ATILE)         // A tile + B tile = 20480
#define GEMM_SMEM (4*STAGE)     // 81920
template <int EPI>
__global__ void __launch_bounds__(256) hgemm_k(
    const __half* __restrict__ A, const __half* __restrict__ Bt,
    const float* __restrict__ bias,
    float* __restrict__ Cf, __half* __restrict__ Ch,
    int N, int K,
    const float* __restrict__ res, int gate_off) {

    extern __shared__ char sm[];
    const uint32_t sbase = smem_u32(sm);
    const int tid = threadIdx.x, lane = tid & 31, wid = tid >> 5;
    const int bm = blockIdx.y, bn = blockIdx.x;
    const int am0 = bm * 128, bn0 = bn * 128;
    const int wm0 = (wid >> 1) * 32, wn0 = (wid & 1) * 64;

    float acc[2][8][4];
    #pragma unroll
    for (int i = 0; i < 2; i++)
        #pragma unroll
        for (int j = 0; j < 8; j++)
            #pragma unroll
            for (int q = 0; q < 4; q++) acc[i][j][q] = 0.f;

    // cp.async: 4 x 16B chunks per thread per stage
    const __half* mats[2] = {A, Bt};
    const __half* srcb[4];
    uint32_t dstb[4];
    #pragma unroll
    for (int it = 0; it < 4; it++) {
        int idx = tid + it * 256;
        int mat = idx >> 9, r = (idx >> 2) & 127, c = idx & 3;
        int grow = (mat == 0 ? am0 : bn0) + r;
        srcb[it] = mats[mat] + (size_t)grow * K + c * 8;
        dstb[it] = sbase + mat * ATILE + r * 80 + c * 16;
    }

    uint32_t aaddr[2];
    #pragma unroll
    for (int mi = 0; mi < 2; mi++) {
        int row = wm0 + mi * 16 + (lane & 15);
        aaddr[mi] = sbase + row * 80 + ((lane >> 4) << 4);
    }
    uint32_t baddr[4];
    #pragma unroll
    for (int ng = 0; ng < 4; ng++) {
        int row = wn0 + ng * 16 + (lane & 7) + ((lane & 16) >> 1);
        baddr[ng] = sbase + ATILE + row * 80 + ((lane & 8) ? 16 : 0);
    }

    const int KB = K >> 5;
    // prologue: stages 0,1
    #pragma unroll
    for (int pf = 0; pf < 2; pf++) {
        #pragma unroll
        for (int it = 0; it < 4; it++)
            cpasync16(dstb[it] + pf * STAGE, srcb[it] + pf * 32);
        CP_COMMIT();
    }

    for (int kb = 0; kb < KB; kb++) {
        if (kb + 2 < KB) {
            const uint32_t so2 = ((kb + 2) & 3) * STAGE;
            const int ko = (kb + 2) << 5;
            #pragma unroll
            for (int it = 0; it < 4; it++) cpasync16(dstb[it] + so2, srcb[it] + ko);
            CP_COMMIT();
            CP_WAIT(2);
        } else {
            CP_WAIT(0);
        }
        __syncthreads();

        const uint32_t so = (kb & 3) * STAGE;
        #pragma unroll
        for (int ks = 0; ks < 2; ks++) {
            const uint32_t ko = so + ks * 32;
            uint32_t a[2][4];
            ldsm4(a[0], aaddr[0] + ko);
            ldsm4(a[1], aaddr[1] + ko);
            uint32_t b[8][2];
            #pragma unroll
            for (int ng = 0; ng < 4; ng++) {
                uint32_t r[4];
                ldsm4(r, baddr[ng] + ko);
                b[2*ng][0] = r[0]; b[2*ng][1] = r[1];
                b[2*ng+1][0] = r[2]; b[2*ng+1][1] = r[3];
            }
            #pragma unroll
            for (int mi = 0; mi < 2; mi++)
                #pragma unroll
                for (int ni = 0; ni < 8; ni++)
                    mma16816(acc[mi][ni], a[mi], b[ni]);
        }
    }

    // ----------------------------- epilogue -------------------------------
    const int rbase = am0 + wm0 + (lane >> 2);
    const int cbase = bn0 + wn0 + (lane & 3) * 2;
    #pragma unroll
    for (int mi = 0; mi < 2; mi++) {
        #pragma unroll
        for (int ni = 0; ni < 8; ni++) {
            int col = cbase + ni * 8;
            float2 bb = *(const float2*)&bias[col];
            #pragma unroll
            for (int half2i = 0; half2i < 2; half2i++) {
                int row = rbase + mi * 16 + half2i * 8;
                float v0 = acc[mi][ni][2*half2i]   + bb.x;
                float v1 = acc[mi][ni][2*half2i+1] + bb.y;
                if (EPI == 1) {
                    v0 = 0.5f * v0 * (1.0f + erff(v0 * 0.70710678118654752f));
                    v1 = 0.5f * v1 * (1.0f + erff(v1 * 0.70710678118654752f));
                    *(uint32_t*)(Ch + (size_t)row * N + col) = pack_h2(v0, v1);
                } else if (EPI == 3) {
                    int i3 = col / 768;
                    int rem = col - i3 * 768;
                    int hh = rem >> 6, d = rem & 63;
                    int b2 = row >> 11, t2 = row & 2047;
                    size_t idx = ((size_t)((b2 * NHD + hh) * TT + t2)) * HDD + d;
                    if (i3 == 0) { v0 *= QSCALE; v1 *= QSCALE; }
                    __half* dh = (i3 == 0) ? g_q : (i3 == 1) ? g_k : g_v;
                    *(uint32_t*)(dh + idx) = pack_h2(v0, v1);
                } else {
                    if (EPI == 2) {
                        const float* tb = g_temb + (row >> 11) * 4608 + gate_off;
                        float2 rr = *(const float2*)&res[(size_t)row * N + col];
                        float2 gg = *(const float2*)&tb[col];
                        v0 = rr.x + gg.x * v0;
                        v1 = rr.y + gg.y * v1;
                    }
                    float2 o2; o2.x = v0; o2.y = v1;
                    *(float2*)&Cf[(size_t)row * N + col] = o2;
                }
            }
        }
    }
}

// -------------------- tensor-core flash attention --------------------------
// CTA: one (b,h) x 128 queries; 8 warps x 16 rows. KV tiles of 64 keys.
#define RS   144                 // padded row stride bytes (64 fp16 = 128B)
#define QB   (128*RS)            // 18432
#define KVT  (64*RS)             // 9216
#define STG  (2*KVT)             // 18432 (K + V)
#define ATTN_SMEM (QB + 2*STG)   // 55296
__global__ void __launch_bounds__(256) attn_tc(void) {
    extern __shared__ char sm[];
    const uint32_t sbase = smem_u32(sm);
    const int tid = threadIdx.x, lane = tid & 31, wid = tid >> 5;
    const int bh = blockIdx.x;            // 0..23
    const int qb = blockIdx.y;            // 0..15
    const size_t headbase = (size_t)bh * TT * HDD;

    const __half* kvmats[2] = {g_k, g_v};

    // load Q block [128][64]
    #pragma unroll
    for (int it = 0; it < 4; it++) {
        int idx = tid + it * 256;
        int r = idx >> 3, c = idx & 7;
        cpasync16(sbase + r * RS + c * 16,
                  g_q + headbase + (size_t)(qb * 128 + r) * HDD + c * 8);
    }
    // KV stage 0
    #pragma unroll
    for (int it = 0; it < 4; it++) {
        int idx = tid + it * 256;
        int mat = idx >> 9, r = (idx >> 3) & 63, c = idx & 7;
        cpasync16(sbase + QB + mat * KVT + r * RS + c * 16,
                  kvmats[mat] + headbase + (size_t)r * HDD + c * 8);
    }
    CP_COMMIT();

    uint32_t qoff = (uint32_t)((wid * 16 + (lane & 15)) * RS + ((lane & 16) ? 16 : 0));
    uint32_t koff[4], voff[4];
    #pragma unroll
    for (int ng = 0; ng < 4; ng++) {
        koff[ng] = (uint32_t)((ng * 16 + (lane & 7) + ((lane & 16) >> 1)) * RS
                              + ((lane & 8) ? 16 : 0));
        voff[ng] = (uint32_t)(((lane & 7) + (lane & 8)) * RS + ng * 32
                              + ((lane & 16) ? 16 : 0));
    }

    uint32_t qh[4][4];
    float o[8][4];
    #pragma unroll
    for (int n = 0; n < 8; n++)
        #pragma unroll
        for (int j = 0; j < 4; j++) o[n][j] = 0.f;
    float m0 = -1e30f, m1 = -1e30f, l0 = 0.f, l1 = 0.f;

    const int NT = TT / 64;   // 32
    for (int t = 0; t < NT; t++) {
        if (t + 1 < NT) {
            const uint32_t sb2 = sbase + QB + ((t + 1) & 1) * STG;
            const size_t kvb = headbase + (size_t)(t + 1) * 64 * HDD;
            #pragma unroll
            for (int it = 0; it < 4; it++) {
                int idx = tid + it * 256;
                int mat = idx >> 9, r = (idx >> 3) & 63, c = idx & 7;
                cpasync16(sb2 + mat * KVT + r * RS + c * 16,
                          kvmats[mat] + kvb + (size_t)r * HDD + c * 8);
            }
            CP_COMMIT();
            CP_WAIT(1);
        } else {
            CP_WAIT(0);
        }
        __syncthreads();

        if (t == 0) {
            #pragma unroll
            for (int kc = 0; kc < 4; kc++) ldsm4(qh[kc], sbase + qoff + kc * 32);
        }

        const uint32_t stb = sbase + QB + (t & 1) * STG;

        // ---- S = Q K^T ----
        float c[8][4];
        #pragma unroll
        for (int n = 0; n < 8; n++)
            #pragma unroll
            for (int j = 0; j < 4; j++) c[n][j] = 0.f;
        #pragma unroll
        for (int kc = 0; kc < 4; kc++) {
            uint32_t b[8][2];
            #pragma unroll
            for (int ng = 0; ng < 4; ng++) {
                uint32_t r[4];
                ldsm4(r, stb + koff[ng] + kc * 32);
                b[2*ng][0] = r[0]; b[2*ng][1] = r[1];
                b[2*ng+1][0] = r[2]; b[2*ng+1][1] = r[3];
            }
            #pragma unroll
            for (int n = 0; n < 8; n++) mma16816(c[n], qh[kc], b[n]);
        }

        // ---- online softmax (log2 domain) ----
        float mx0 = -1e30f, mx1 = -1e30f;
        #pragma unroll
        for (int n = 0; n < 8; n++) {
            mx0 = fmaxf(mx0, fmaxf(c[n][0], c[n][1]));
            mx1 = fmaxf(mx1, fmaxf(c[n][2], c[n][3]));
        }
        mx0 = fmaxf(mx0, __shfl_xor_sync(0xffffffffu, mx0, 1));
        mx0 = fmaxf(mx0, __shfl_xor_sync(0xffffffffu, mx0, 2));
        mx1 = fmaxf(mx1, __shfl_xor_sync(0xffffffffu, mx1, 1));
        mx1 = fmaxf(mx1, __shfl_xor_sync(0xffffffffu, mx1, 2));
        float mn0 = fmaxf(m0, mx0), mn1 = fmaxf(m1, mx1);
        float cr0 = exp2fast(m0 - mn0), cr1 = exp2fast(m1 - mn1);
        m0 = mn0; m1 = mn1;
        l0 *= cr0; l1 *= cr1;
        #pragma unroll
        for (int n = 0; n < 8; n++) {
            o[n][0] *= cr0; o[n][1] *= cr0;
            o[n][2] *= cr1; o[n][3] *= cr1;
        }
        uint32_t pa[4][4];
        #pragma unroll
        for (int n = 0; n < 8; n++) {
            float p00 = exp2fast(c[n][0] - mn0);
            float p01 = exp2fast(c[n][1] - mn0);
            float p10 = exp2fast(c[n][2] - mn1);
            float p11 = exp2fast(c[n][3] - mn1);
            l0 += p00 + p01; l1 += p10 + p11;
            int kc = n >> 1, s = (n & 1) * 2;
            pa[kc][s]     = pack_h2(p00, p01);
            pa[kc][s + 1] = pack_h2(p10, p11);
        }

        // ---- O += P V ----
        #pragma unroll
        for (int kc = 0; kc < 4; kc++) {
            uint32_t b[8][2];
            #pragma unroll
            for (int ng = 0; ng < 4; ng++) {
                uint32_t r[4];
                ldsm4t(r, stb + KVT + voff[ng] + kc * 16 * RS);
                b[2*ng][0] = r[0]; b[2*ng][1] = r[1];
                b[2*ng+1][0] = r[2]; b[2*ng+1][1] = r[3];
            }
            #pragma unroll
            for (int n = 0; n < 8; n++) mma16816(o[n], pa[kc], b[n]);
        }
        __syncthreads();
    }

    l0 += __shfl_xor_sync(0xffffffffu, l0, 1);
    l0 += __shfl_xor_sync(0xffffffffu, l0, 2);
    l1 += __shfl_xor_sync(0xffffffffu, l1, 1);
    l1 += __shfl_xor_sync(0xffffffffu, l1, 2);
    float i0 = 1.0f / l0, i1 = 1.0f / l1;

    const int b2 = bh / NHD, h2 = bh % NHD;
    const int r0 = qb * 128 + wid * 16 + (lane >> 2);
    const int cb = h2 * 64 + (lane & 3) * 2;
    #pragma unroll
    for (int n = 0; n < 8; n++) {
        int col = cb + n * 8;
        size_t o0 = (size_t)(b2 * TT + r0) * HH + col;
        *(uint32_t*)(g_o + o0) = pack_h2(o[n][0] * i0, o[n][1] * i0);
        size_t o1 = (size_t)(b2 * TT + r0 + 8) * HH + col;
        *(uint32_t*)(g_o + o1) = pack_h2(o[n][2] * i1, o[n][3] * i1);
    }
}

// ------------------------------- launcher ----------------------------------
extern "C" void kernel_launch(void* const* d_in, const int* in_sizes, int n_in,
                              void* d_out, int out_size) {
    const float* x      = (const float*)d_in[0];
    const float* t      = (const float*)d_in[1];
    const float* w_qkv  = (const float*)d_in[2];
    const float* b_qkv  = (const float*)d_in[3];
    const float* w_m1   = (const float*)d_in[4];
    const float* b_m1   = (const float*)d_in[5];
    const float* w_m2   = (const float*)d_in[6];
    const float* b_m2   = (const float*)d_in[7];
    const float* w_ss1  = (const float*)d_in[8];
    const float* b_ss1  = (const float*)d_in[9];
    const float* w_ss2  = (const float*)d_in[10];
    const float* b_ss2  = (const float*)d_in[11];
    const float* ln1_g  = (const float*)d_in[12];
    const float* ln1_b  = (const float*)d_in[13];
    const float* ln2_g  = (const float*)d_in[14];
    const float* ln2_b  = (const float*)d_in[15];
    const float* w_f1   = (const float*)d_in[16];
    const float* b_f1   = (const float*)d_in[17];
    const float* w_f2   = (const float*)d_in[18];
    const float* b_f2   = (const float*)d_in[19];
    float* out = (float*)d_out;

    float *p_x1;
    __half *p_h, *p_o, *p_u;
    __half *p_wq, *p_wm1, *p_wm2, *p_wf1, *p_wf2;
    cudaGetSymbolAddress((void**)&p_x1,  g_x1);
    cudaGetSymbolAddress((void**)&p_h,   g_h);
    cudaGetSymbolAddress((void**)&p_o,   g_o);
    cudaGetSymbolAddress((void**)&p_u,   g_u);
    cudaGetSymbolAddress((void**)&p_wq,  g_wqkv);
    cudaGetSymbolAddress((void**)&p_wm1, g_wm1);
    cudaGetSymbolAddress((void**)&p_wm2, g_wm2);
    cudaGetSymbolAddress((void**)&p_wf1, g_wf1);
    cudaGetSymbolAddress((void**)&p_wf2, g_wf2);

    cudaFuncSetAttribute(attn_tc, cudaFuncAttributeMaxDynamicSharedMemorySize, ATTN_SMEM);
    cudaFuncSetAttribute(hgemm_k<1>, cudaFuncAttributeMaxDynamicSharedMemorySize, GEMM_SMEM);
    cudaFuncSetAttribute(hgemm_k<2>, cudaFuncAttributeMaxDynamicSharedMemorySize, GEMM_SMEM);
    cudaFuncSetAttribute(hgemm_k<3>, cudaFuncAttributeMaxDynamicSharedMemorySize, GEMM_SMEM);

    dim3 cb(32, 8);
    wtconv_k<<<dim3(2304/32, 768/32),  cb>>>(w_qkv, p_wq,  768,  2304);
    wtconv_k<<<dim3(3072/32, 768/32),  cb>>>(w_m1,  p_wm1, 768,  3072);
    wtconv_k<<<dim3(768/32,  3072/32), cb>>>(w_m2,  p_wm2, 3072, 768);
    wtconv_k<<<dim3(3072/32, 768/32),  cb>>>(w_f1,  p_wf1, 768,  3072);
    wtconv_k<<<dim3(768/32,  3072/32), cb>>>(w_f2,  p_wf2, 3072, 768);

    temb1_k<<<72, 128>>>(t, w_ss1, b_ss1);
    temb2_k<<<72, 128>>>(w_ss2, b_ss2);

    ln_mod_k<<<MROWS, 256>>>(x, ln1_g, ln1_b, 0, p_h);

    // qkv = h @ Wqkv + b -> fp16 q(scaled)/k/v head-major
    hgemm_k<3><<<dim3(2304/128, MROWS/128), 256, GEMM_SMEM>>>(
        p_h, p_wq, b_qkv, nullptr, nullptr, 2304, 768, nullptr, 0);

    attn_tc<<<dim3(BB * NHD, TT / 128), 256, ATTN_SMEM>>>();

    hgemm_k<1><<<dim3(3072/128, MROWS/128), 256, GEMM_SMEM>>>(
        p_o, p_wm1, b_m1, nullptr, p_u, 3072, 768, nullptr, 0);

    hgemm_k<2><<<dim3(768/128, MROWS/128), 256, GEMM_SMEM>>>(
        p_u, p_wm2, b_m2, p_x1, nullptr, 768, 3072, x, 1536);

    ln_mod_k<<<MROWS, 256>>>(p_x1, ln2_g, ln2_b, 2304, p_h);

    hgemm_k<1><<<dim3(3072/128, MROWS/128), 256, GEMM_SMEM>>>(
        p_h, p_wf1, b_f1, nullptr, p_u, 3072, 768, nullptr, 0);

    hgemm_k<2><<<dim3(768/128, MROWS/128), 256, GEMM_SMEM>>>(
        p_u, p_wf2, b_f2, out, nullptr, 768, 3072, p_x1, 3840);
}

// round 6
// speedup vs baseline: 9.8556x; 1.9041x over previous
#include <cuda_runtime.h>
#include <cuda_fp16.h>
#include <math.h>
#include <stdint.h>

// ---------------------------------------------------------------------------
// DiT block. GEMMs + flash attention on fp16 mma.sync (f32 accum),
// FFMA exp2 softmax, parallelized temb, warp-per-row LN.
// B=2, T=2048, H=768, NH=12, HD=64.
// ---------------------------------------------------------------------------

#define HH   768
#define NHD  12
#define HDD  64
#define TT   2048
#define BB   2
#define MROWS (BB*TT)          // 4096

// qscale = log2(e)/sqrt(768)
#define QSCALE 0.05205877172640942f

// ------------------------- scratch (static device) -------------------------
__device__ float g_hid [BB*6*HH];
__device__ float g_temb[BB*6*HH];
__device__ float g_x1  [MROWS*HH];

__device__ __half g_h[MROWS*HH];
__device__ __half g_o[MROWS*HH];
__device__ __half g_u[MROWS*4*HH];

// attention operands, head-major [b][h][T][64]
__device__ __half g_q[MROWS*HH];
__device__ __half g_k[MROWS*HH];
__device__ __half g_v[MROWS*HH];

// transposed fp16 weights  W[K,N] -> Wt[N,K]
__device__ __half g_wqkv[3*HH*HH];
__device__ __half g_wm1 [4*HH*HH];
__device__ __half g_wm2 [HH*4*HH];
__device__ __half g_wf1 [4*HH*HH];
__device__ __half g_wf2 [HH*4*HH];

// ----------------------------- PTX helpers --------------------------------
__device__ __forceinline__ uint32_t smem_u32(const void* p) {
    uint32_t a;
    asm("{ .reg .u64 t; cvta.to.shared.u64 t, %1; cvt.u32.u64 %0, t; }" : "=r"(a) : "l"(p));
    return a;
}
__device__ __forceinline__ void ldsm4(uint32_t* r, uint32_t a) {
    asm volatile("ldmatrix.sync.aligned.m8n8.x4.shared.b16 {%0,%1,%2,%3}, [%4];"
        : "=r"(r[0]), "=r"(r[1]), "=r"(r[2]), "=r"(r[3]) : "r"(a));
}
__device__ __forceinline__ void ldsm4t(uint32_t* r, uint32_t a) {
    asm volatile("ldmatrix.sync.aligned.m8n8.x4.trans.shared.b16 {%0,%1,%2,%3}, [%4];"
        : "=r"(r[0]), "=r"(r[1]), "=r"(r[2]), "=r"(r[3]) : "r"(a));
}
__device__ __forceinline__ void mma16816(float* d, const uint32_t* a, const uint32_t* b) {
    asm volatile("mma.sync.aligned.m16n8k16.row.col.f32.f16.f16.f32 "
        "{%0,%1,%2,%3},{%4,%5,%6,%7},{%8,%9},{%0,%1,%2,%3};"
        : "+f"(d[0]), "+f"(d[1]), "+f"(d[2]), "+f"(d[3])
        : "r"(a[0]), "r"(a[1]), "r"(a[2]), "r"(a[3]), "r"(b[0]), "r"(b[1]));
}
__device__ __forceinline__ void cpasync16(uint32_t dst, const void* src) {
    asm volatile("cp.async.cg.shared.global [%0], [%1], 16;" :: "r"(dst), "l"(src) : "memory");
}
#define CP_COMMIT() asm volatile("cp.async.commit_group;" ::: "memory")
#define CP_WAIT(n)  asm volatile("cp.async.wait_group %0;" :: "n"(n) : "memory")

__device__ __forceinline__ uint32_t pack_h2(float x, float y) {
    __half2 h = __floats2half2_rn(x, y);
    return *(uint32_t*)&h;
}
// FFMA-pipe exp2 for t <= 0; err ~1e-5
__device__ __forceinline__ float exp2fast(float t) {
    t = fmaxf(t, -126.0f);
    float fi = floorf(t);
    float f = t - fi;
    float p = 1.5435291e-4f;
    p = p * f + 1.3333558e-3f;
    p = p * f + 9.6181291e-3f;
    p = p * f + 5.5504109e-2f;
    p = p * f + 2.4022651e-1f;
    p = p * f + 6.9314718e-1f;
    p = p * f + 1.0f;
    return __int_as_float(((int)fi + 127) << 23) * p;
}

// ------------------------------- temb path --------------------------------
// grid (36, 2), block 1024 = 128 n-lanes x 8 k-slices
__global__ void __launch_bounds__(1024) temb1_k(
        const float* __restrict__ t, const float* __restrict__ W,
        const float* __restrict__ bias) {
    __shared__ float red[8][128];
    const int n0 = blockIdx.x * 128, b = blockIdx.y;
    const int n = threadIdx.x & 127, ks = threadIdx.x >> 7;
    const float* tr = t + b * HH;
    float acc = 0.f;
    const int kbeg = ks * 96;
    #pragma unroll 4
    for (int k = kbeg; k < kbeg + 96; k++)
        acc += tr[k] * W[(size_t)k * 4608 + n0 + n];
    red[ks][n] = acc;
    __syncthreads();
    if (ks == 0) {
        float s = bias[n0 + n];
        #pragma unroll
        for (int i = 0; i < 8; i++) s += red[i][n];
        g_hid[b * 4608 + n0 + n] = s / (1.0f + expf(-s));
    }
}
__global__ void __launch_bounds__(1024) temb2_k(
        const float* __restrict__ W, const float* __restrict__ bias) {
    __shared__ float red[8][128];
    const int n0 = blockIdx.x * 128, b = blockIdx.y;
    const int n = threadIdx.x & 127, ks = threadIdx.x >> 7;
    const float* hr = g_hid + b * 4608;
    float acc = 0.f;
    const int kbeg = ks * 576;
    #pragma unroll 4
    for (int k = kbeg; k < kbeg + 576; k++)
        acc += hr[k] * W[(size_t)k * 4608 + n0 + n];
    red[ks][n] = acc;
    __syncthreads();
    if (ks == 0) {
        float s = bias[n0 + n];
        #pragma unroll
        for (int i = 0; i < 8; i++) s += red[i][n];
        g_temb[b * 4608 + n0 + n] = s;
    }
}

// -------------------- weight transpose + fp16 convert ----------------------
__global__ void wtconv_k(const float* __restrict__ W, __half* __restrict__ O,
                         int K, int N) {
    __shared__ float s[32][33];
    int tx = threadIdx.x, ty = threadIdx.y;
    int n0 = blockIdx.x * 32, k0 = blockIdx.y * 32;
    #pragma unroll
    for (int j = 0; j < 32; j += 8)
        s[ty + j][tx] = W[(size_t)(k0 + ty + j) * N + n0 + tx];
    __syncthreads();
    #pragma unroll
    for (int j = 0; j < 32; j += 8)
        O[(size_t)(n0 + ty + j) * K + k0 + tx] = __float2half(s[tx][ty + j]);
}

// --------------------------- LayerNorm + modulate --------------------------
// warp per row; block 256 = 8 rows; grid 512
__global__ void __launch_bounds__(256) ln_mod_k(
        const float* __restrict__ x,
        const float* __restrict__ lng, const float* __restrict__ lnb,
        int goff, __half* __restrict__ y) {
    const int row = blockIdx.x * 8 + (threadIdx.x >> 5);
    const int lane = threadIdx.x & 31;
    const float* xr = x + (size_t)row * HH;
    float v[24];
    float s = 0.f, s2 = 0.f;
    #pragma unroll
    for (int j = 0; j < 24; j++) {
        v[j] = xr[lane + j * 32];
        s += v[j]; s2 += v[j] * v[j];
    }
    #pragma unroll
    for (int o = 16; o; o >>= 1) {
        s  += __shfl_xor_sync(0xffffffffu, s, o);
        s2 += __shfl_xor_sync(0xffffffffu, s2, o);
    }
    const float inv = 1.0f / 768.0f;
    float mu = s * inv;
    float var = s2 * inv - mu * mu;
    float rs = rsqrtf(var + 1e-5f);
    const float* tb = g_temb + (row >> 11) * 4608 + goff;
    #pragma unroll
    for (int j = 0; j < 24; j++) {
        int i = lane + j * 32;
        float val = (v[j] - mu) * rs * lng[i] + lnb[i];
        y[(size_t)row * HH + i] = __float2half(tb[i] * val + tb[768 + i]);
    }
}

// ------------------------------ HMMA GEMM ----------------------------------
// C[4096,N] = A[4096,K] @ Bt[N,K]^T + bias (fp16 in, fp32 accum)
// CTA 128x128, 8 warps of 32x64; K staged by 32; 4-stage cp.async ring.
// EPI: 1=gelu->fp16, 2=residual+gate->fp32, 3=qkv->scaled fp16 q/k/v
#define ATILE 10240             // 128 rows * 80B
#define STAGE (2*ATILE)         // 20480
#define GEMM_SMEM (4*STAGE)     // 81920
template <int EPI>
__global__ void __launch_bounds__(256, 2) hgemm_k(
    const __half* __restrict__ A, const __half* __restrict__ Bt,
    const float* __restrict__ bias,
    float* __restrict__ Cf, __half* __restrict__ Ch,
    int N, int K,
    const float* __restrict__ res, int gate_off) {

    extern __shared__ char sm[];
    const uint32_t sbase = smem_u32(sm);
    const int tid = threadIdx.x, lane = tid & 31, wid = tid >> 5;
    const int bm = blockIdx.y, bn = blockIdx.x;
    const int am0 = bm * 128, bn0 = bn * 128;
    const int wm0 = (wid >> 1) * 32, wn0 = (wid & 1) * 64;

    float acc[2][8][4];
    #pragma unroll
    for (int i = 0; i < 2; i++)
        #pragma unroll
        for (int j = 0; j < 8; j++)
            #pragma unroll
            for (int q = 0; q < 4; q++) acc[i][j][q] = 0.f;

    const __half* mats[2] = {A, Bt};
    const __half* srcb[4];
    uint32_t dstb[4];
    #pragma unroll
    for (int it = 0; it < 4; it++) {
        int idx = tid + it * 256;
        int mat = idx >> 9, r = (idx >> 2) & 127, c = idx & 3;
        int grow = (mat == 0 ? am0 : bn0) + r;
        srcb[it] = mats[mat] + (size_t)grow * K + c * 8;
        dstb[it] = sbase + mat * ATILE + r * 80 + c * 16;
    }

    uint32_t aaddr[2];
    #pragma unroll
    for (int mi = 0; mi < 2; mi++) {
        int row = wm0 + mi * 16 + (lane & 15);
        aaddr[mi] = sbase + row * 80 + ((lane >> 4) << 4);
    }
    uint32_t baddr[4];
    #pragma unroll
    for (int ng = 0; ng < 4; ng++) {
        int row = wn0 + ng * 16 + (lane & 7) + ((lane & 16) >> 1);
        baddr[ng] = sbase + ATILE + row * 80 + ((lane & 8) ? 16 : 0);
    }

    const int KB = K >> 5;
    #pragma unroll
    for (int pf = 0; pf < 2; pf++) {
        #pragma unroll
        for (int it = 0; it < 4; it++)
            cpasync16(dstb[it] + pf * STAGE, srcb[it] + pf * 32);
        CP_COMMIT();
    }

    for (int kb = 0; kb < KB; kb++) {
        if (kb + 2 < KB) {
            const uint32_t so2 = ((kb + 2) & 3) * STAGE;
            const int ko = (kb + 2) << 5;
            #pragma unroll
            for (int it = 0; it < 4; it++) cpasync16(dstb[it] + so2, srcb[it] + ko);
            CP_COMMIT();
            CP_WAIT(2);
        } else {
            CP_WAIT(0);
        }
        __syncthreads();

        const uint32_t so = (kb & 3) * STAGE;
        #pragma unroll
        for (int ks = 0; ks < 2; ks++) {
            const uint32_t ko = so + ks * 32;
            uint32_t a[2][4];
            ldsm4(a[0], aaddr[0] + ko);
            ldsm4(a[1], aaddr[1] + ko);
            uint32_t b[8][2];
            #pragma unroll
            for (int ng = 0; ng < 4; ng++) {
                uint32_t r[4];
                ldsm4(r, baddr[ng] + ko);
                b[2*ng][0] = r[0]; b[2*ng][1] = r[1];
                b[2*ng+1][0] = r[2]; b[2*ng+1][1] = r[3];
            }
            #pragma unroll
            for (int mi = 0; mi < 2; mi++)
                #pragma unroll
                for (int ni = 0; ni < 8; ni++)
                    mma16816(acc[mi][ni], a[mi], b[ni]);
        }
    }

    // ----------------------------- epilogue -------------------------------
    const int rbase = am0 + wm0 + (lane >> 2);
    const int cbase = bn0 + wn0 + (lane & 3) * 2;
    #pragma unroll
    for (int mi = 0; mi < 2; mi++) {
        #pragma unroll
        for (int ni = 0; ni < 8; ni++) {
            int col = cbase + ni * 8;
            float2 bb = *(const float2*)&bias[col];
            #pragma unroll
            for (int half2i = 0; half2i < 2; half2i++) {
                int row = rbase + mi * 16 + half2i * 8;
                float v0 = acc[mi][ni][2*half2i]   + bb.x;
                float v1 = acc[mi][ni][2*half2i+1] + bb.y;
                if (EPI == 1) {
                    v0 = 0.5f * v0 * (1.0f + erff(v0 * 0.70710678118654752f));
                    v1 = 0.5f * v1 * (1.0f + erff(v1 * 0.70710678118654752f));
                    *(uint32_t*)(Ch + (size_t)row * N + col) = pack_h2(v0, v1);
                } else if (EPI == 3) {
                    int i3 = col / 768;
                    int rem = col - i3 * 768;
                    int hh = rem >> 6, d = rem & 63;
                    int b2 = row >> 11, t2 = row & 2047;
                    size_t idx = ((size_t)((b2 * NHD + hh) * TT + t2)) * HDD + d;
                    if (i3 == 0) { v0 *= QSCALE; v1 *= QSCALE; }
                    __half* dh = (i3 == 0) ? g_q : (i3 == 1) ? g_k : g_v;
                    *(uint32_t*)(dh + idx) = pack_h2(v0, v1);
                } else {
                    if (EPI == 2) {
                        const float* tb = g_temb + (row >> 11) * 4608 + gate_off;
                        float2 rr = *(const float2*)&res[(size_t)row * N + col];
                        float2 gg = *(const float2*)&tb[col];
                        v0 = rr.x + gg.x * v0;
                        v1 = rr.y + gg.y * v1;
                    }
                    float2 o2; o2.x = v0; o2.y = v1;
                    *(float2*)&Cf[(size_t)row * N + col] = o2;
                }
            }
        }
    }
}

// -------------------- tensor-core flash attention --------------------------
#define RS   144                 // padded row stride bytes
#define QB   (128*RS)            // 18432
#define KVT  (64*RS)             // 9216
#define STG  (2*KVT)             // 18432
#define ATTN_SMEM (QB + 2*STG)   // 55296
__global__ void __launch_bounds__(256, 2) attn_tc(void) {
    extern __shared__ char sm[];
    const uint32_t sbase = smem_u32(sm);
    const int tid = threadIdx.x, lane = tid & 31, wid = tid >> 5;
    const int bh = blockIdx.x;            // 0..23
    const int qb = blockIdx.y;            // 0..15
    const size_t headbase = (size_t)bh * TT * HDD;

    const __half* kvmats[2] = {g_k, g_v};

    #pragma unroll
    for (int it = 0; it < 4; it++) {
        int idx = tid + it * 256;
        int r = idx >> 3, c = idx & 7;
        cpasync16(sbase + r * RS + c * 16,
                  g_q + headbase + (size_t)(qb * 128 + r) * HDD + c * 8);
    }
    #pragma unroll
    for (int it = 0; it < 4; it++) {
        int idx = tid + it * 256;
        int mat = idx >> 9, r = (idx >> 3) & 63, c = idx & 7;
        cpasync16(sbase + QB + mat * KVT + r * RS + c * 16,
                  kvmats[mat] + headbase + (size_t)r * HDD + c * 8);
    }
    CP_COMMIT();

    uint32_t qoff = (uint32_t)((wid * 16 + (lane & 15)) * RS + ((lane & 16) ? 16 : 0));
    uint32_t koff[4], voff[4];
    #pragma unroll
    for (int ng = 0; ng < 4; ng++) {
        koff[ng] = (uint32_t)((ng * 16 + (lane & 7) + ((lane & 16) >> 1)) * RS
                              + ((lane & 8) ? 16 : 0));
        voff[ng] = (uint32_t)(((lane & 7) + (lane & 8)) * RS + ng * 32
                              + ((lane & 16) ? 16 : 0));
    }

    uint32_t qh[4][4];
    float o[8][4];
    #pragma unroll
    for (int n = 0; n < 8; n++)
        #pragma unroll
        for (int j = 0; j < 4; j++) o[n][j] = 0.f;
    float m0 = -1e30f, m1 = -1e30f, l0 = 0.f, l1 = 0.f;

    const int NT = TT / 64;   // 32
    for (int t = 0; t < NT; t++) {
        if (t + 1 < NT) {
            const uint32_t sb2 = sbase + QB + ((t + 1) & 1) * STG;
            const size_t kvb = headbase + (size_t)(t + 1) * 64 * HDD;
            #pragma unroll
            for (int it = 0; it < 4; it++) {
                int idx = tid + it * 256;
                int mat = idx >> 9, r = (idx >> 3) & 63, c = idx & 7;
                cpasync16(sb2 + mat * KVT + r * RS + c * 16,
                          kvmats[mat] + kvb + (size_t)r * HDD + c * 8);
            }
            CP_COMMIT();
            CP_WAIT(1);
        } else {
            CP_WAIT(0);
        }
        __syncthreads();

        if (t == 0) {
            #pragma unroll
            for (int kc = 0; kc < 4; kc++) ldsm4(qh[kc], sbase + qoff + kc * 32);
        }

        const uint32_t stb = sbase + QB + (t & 1) * STG;

        float c[8][4];
        #pragma unroll
        for (int n = 0; n < 8; n++)
            #pragma unroll
            for (int j = 0; j < 4; j++) c[n][j] = 0.f;
        #pragma unroll
        for (int kc = 0; kc < 4; kc++) {
            uint32_t b[8][2];
            #pragma unroll
            for (int ng = 0; ng < 4; ng++) {
                uint32_t r[4];
                ldsm4(r, stb + koff[ng] + kc * 32);
                b[2*ng][0] = r[0]; b[2*ng][1] = r[1];
                b[2*ng+1][0] = r[2]; b[2*ng+1][1] = r[3];
            }
            #pragma unroll
            for (int n = 0; n < 8; n++) mma16816(c[n], qh[kc], b[n]);
        }

        float mx0 = -1e30f, mx1 = -1e30f;
        #pragma unroll
        for (int n = 0; n < 8; n++) {
            mx0 = fmaxf(mx0, fmaxf(c[n][0], c[n][1]));
            mx1 = fmaxf(mx1, fmaxf(c[n][2], c[n][3]));
        }
        mx0 = fmaxf(mx0, __shfl_xor_sync(0xffffffffu, mx0, 1));
        mx0 = fmaxf(mx0, __shfl_xor_sync(0xffffffffu, mx0, 2));
        mx1 = fmaxf(mx1, __shfl_xor_sync(0xffffffffu, mx1, 1));
        mx1 = fmaxf(mx1, __shfl_xor_sync(0xffffffffu, mx1, 2));
        float mn0 = fmaxf(m0, mx0), mn1 = fmaxf(m1, mx1);
        float cr0 = exp2fast(m0 - mn0), cr1 = exp2fast(m1 - mn1);
        m0 = mn0; m1 = mn1;
        l0 *= cr0; l1 *= cr1;
        #pragma unroll
        for (int n = 0; n < 8; n++) {
            o[n][0] *= cr0; o[n][1] *= cr0;
            o[n][2] *= cr1; o[n][3] *= cr1;
        }
        uint32_t pa[4][4];
        #pragma unroll
        for (int n = 0; n < 8; n++) {
            float p00 = exp2fast(c[n][0] - mn0);
            float p01 = exp2fast(c[n][1] - mn0);
            float p10 = exp2fast(c[n][2] - mn1);
            float p11 = exp2fast(c[n][3] - mn1);
            l0 += p00 + p01; l1 += p10 + p11;
            int kc = n >> 1, s = (n & 1) * 2;
            pa[kc][s]     = pack_h2(p00, p01);
            pa[kc][s + 1] = pack_h2(p10, p11);
        }

        #pragma unroll
        for (int kc = 0; kc < 4; kc++) {
            uint32_t b[8][2];
            #pragma unroll
            for (int ng = 0; ng < 4; ng++) {
                uint32_t r[4];
                ldsm4t(r, stb + KVT + voff[ng] + kc * 16 * RS);
                b[2*ng][0] = r[0]; b[2*ng][1] = r[1];
                b[2*ng+1][0] = r[2]; b[2*ng+1][1] = r[3];
            }
            #pragma unroll
            for (int n = 0; n < 8; n++) mma16816(o[n], pa[kc], b[n]);
        }
        __syncthreads();
    }

    l0 += __shfl_xor_sync(0xffffffffu, l0, 1);
    l0 += __shfl_xor_sync(0xffffffffu, l0, 2);
    l1 += __shfl_xor_sync(0xffffffffu, l1, 1);
    l1 += __shfl_xor_sync(0xffffffffu, l1, 2);
    float i0 = 1.0f / l0, i1 = 1.0f / l1;

    const int b2 = bh / NHD, h2 = bh % NHD;
    const int r0 = qb * 128 + wid * 16 + (lane >> 2);
    const int cb = h2 * 64 + (lane & 3) * 2;
    #pragma unroll
    for (int n = 0; n < 8; n++) {
        int col = cb + n * 8;
        size_t o0 = (size_t)(b2 * TT + r0) * HH + col;
        *(uint32_t*)(g_o + o0) = pack_h2(o[n][0] * i0, o[n][1] * i0);
        size_t o1 = (size_t)(b2 * TT + r0 + 8) * HH + col;
        *(uint32_t*)(g_o + o1) = pack_h2(o[n][2] * i1, o[n][3] * i1);
    }
}

// ------------------------------- launcher ----------------------------------
extern "C" void kernel_launch(void* const* d_in, const int* in_sizes, int n_in,
                              void* d_out, int out_size) {
    const float* x      = (const float*)d_in[0];
    const float* t      = (const float*)d_in[1];
    const float* w_qkv  = (const float*)d_in[2];
    const float* b_qkv  = (const float*)d_in[3];
    const float* w_m1   = (const float*)d_in[4];
    const float* b_m1   = (const float*)d_in[5];
    const float* w_m2   = (const float*)d_in[6];
    const float* b_m2   = (const float*)d_in[7];
    const float* w_ss1  = (const float*)d_in[8];
    const float* b_ss1  = (const float*)d_in[9];
    const float* w_ss2  = (const float*)d_in[10];
    const float* b_ss2  = (const float*)d_in[11];
    const float* ln1_g  = (const float*)d_in[12];
    const float* ln1_b  = (const float*)d_in[13];
    const float* ln2_g  = (const float*)d_in[14];
    const float* ln2_b  = (const float*)d_in[15];
    const float* w_f1   = (const float*)d_in[16];
    const float* b_f1   = (const float*)d_in[17];
    const float* w_f2   = (const float*)d_in[18];
    const float* b_f2   = (const float*)d_in[19];
    float* out = (float*)d_out;

    float *p_x1;
    __half *p_h, *p_o, *p_u;
    __half *p_wq, *p_wm1, *p_wm2, *p_wf1, *p_wf2;
    cudaGetSymbolAddress((void**)&p_x1,  g_x1);
    cudaGetSymbolAddress((void**)&p_h,   g_h);
    cudaGetSymbolAddress((void**)&p_o,   g_o);
    cudaGetSymbolAddress((void**)&p_u,   g_u);
    cudaGetSymbolAddress((void**)&p_wq,  g_wqkv);
    cudaGetSymbolAddress((void**)&p_wm1, g_wm1);
    cudaGetSymbolAddress((void**)&p_wm2, g_wm2);
    cudaGetSymbolAddress((void**)&p_wf1, g_wf1);
    cudaGetSymbolAddress((void**)&p_wf2, g_wf2);

    cudaFuncSetAttribute(attn_tc, cudaFuncAttributeMaxDynamicSharedMemorySize, ATTN_SMEM);
    cudaFuncSetAttribute(hgemm_k<1>, cudaFuncAttributeMaxDynamicSharedMemorySize, GEMM_SMEM);
    cudaFuncSetAttribute(hgemm_k<2>, cudaFuncAttributeMaxDynamicSharedMemorySize, GEMM_SMEM);
    cudaFuncSetAttribute(hgemm_k<3>, cudaFuncAttributeMaxDynamicSharedMemorySize, GEMM_SMEM);

    dim3 cb(32, 8);
    wtconv_k<<<dim3(2304/32, 768/32),  cb>>>(w_qkv, p_wq,  768,  2304);
    wtconv_k<<<dim3(3072/32, 768/32),  cb>>>(w_m1,  p_wm1, 768,  3072);
    wtconv_k<<<dim3(768/32,  3072/32), cb>>>(w_m2,  p_wm2, 3072, 768);
    wtconv_k<<<dim3(3072/32, 768/32),  cb>>>(w_f1,  p_wf1, 768,  3072);
    wtconv_k<<<dim3(768/32,  3072/32), cb>>>(w_f2,  p_wf2, 3072, 768);

    temb1_k<<<dim3(36, 2), 1024>>>(t, w_ss1, b_ss1);
    temb2_k<<<dim3(36, 2), 1024>>>(w_ss2, b_ss2);

    ln_mod_k<<<512, 256>>>(x, ln1_g, ln1_b, 0, p_h);

    hgemm_k<3><<<dim3(2304/128, MROWS/128), 256, GEMM_SMEM>>>(
        p_h, p_wq, b_qkv, nullptr, nullptr, 2304, 768, nullptr, 0);

    attn_tc<<<dim3(BB * NHD, TT / 128), 256, ATTN_SMEM>>>();

    hgemm_k<1><<<dim3(3072/128, MROWS/128), 256, GEMM_SMEM>>>(
        p_o, p_wm1, b_m1, nullptr, p_u, 3072, 768, nullptr, 0);

    hgemm_k<2><<<dim3(768/128, MROWS/128), 256, GEMM_SMEM>>>(
        p_u, p_wm2, b_m2, p_x1, nullptr, 768, 3072, x, 1536);

    ln_mod_k<<<512, 256>>>(p_x1, ln2_g, ln2_b, 2304, p_h);

    hgemm_k<1><<<dim3(3072/128, MROWS/128), 256, GEMM_SMEM>>>(
        p_h, p_wf1, b_f1, nullptr, p_u, 3072, 768, nullptr, 0);

    hgemm_k<2><<<dim3(768/128, MROWS/128), 256, GEMM_SMEM>>>(
        p_u, p_wf2, b_f2, out, nullptr, 768, 3072, p_x1, 3840);
}

// round 7
// speedup vs baseline: 10.8666x; 1.1026x over previous
#include <cuda_runtime.h>
#include <cuda_fp16.h>
#include <math.h>
#include <stdint.h>

// ---------------------------------------------------------------------------
// DiT block. fp16 mma.sync GEMMs (SW128 swizzle, 3-stage cp.async ring),
// fp16 tensor-core flash attention (128-key stages), FFMA exp2 softmax.
// B=2, T=2048, H=768, NH=12, HD=64.
// ---------------------------------------------------------------------------

#define HH   768
#define NHD  12
#define HDD  64
#define TT   2048
#define BB   2
#define MROWS (BB*TT)          // 4096

#define QSCALE 0.05205877172640942f   // log2(e)/sqrt(768)

// ------------------------- scratch (static device) -------------------------
__device__ float g_hid [BB*6*HH];
__device__ float g_temb[BB*6*HH];
__device__ float g_x1  [MROWS*HH];

__device__ __half g_h[MROWS*HH];
__device__ __half g_o[MROWS*HH];
__device__ __half g_u[MROWS*4*HH];

// attention operands, head-major [b][h][T][64]
__device__ __half g_q[MROWS*HH];
__device__ __half g_k[MROWS*HH];
__device__ __half g_v[MROWS*HH];

// transposed fp16 weights  W[K,N] -> Wt[N,K]
__device__ __half g_wqkv[3*HH*HH];
__device__ __half g_wm1 [4*HH*HH];
__device__ __half g_wm2 [HH*4*HH];
__device__ __half g_wf1 [4*HH*HH];
__device__ __half g_wf2 [HH*4*HH];

// ----------------------------- PTX helpers --------------------------------
__device__ __forceinline__ uint32_t smem_u32(const void* p) {
    uint32_t a;
    asm("{ .reg .u64 t; cvta.to.shared.u64 t, %1; cvt.u32.u64 %0, t; }" : "=r"(a) : "l"(p));
    return a;
}
__device__ __forceinline__ void ldsm4(uint32_t* r, uint32_t a) {
    asm volatile("ldmatrix.sync.aligned.m8n8.x4.shared.b16 {%0,%1,%2,%3}, [%4];"
        : "=r"(r[0]), "=r"(r[1]), "=r"(r[2]), "=r"(r[3]) : "r"(a));
}
__device__ __forceinline__ void ldsm4t(uint32_t* r, uint32_t a) {
    asm volatile("ldmatrix.sync.aligned.m8n8.x4.trans.shared.b16 {%0,%1,%2,%3}, [%4];"
        : "=r"(r[0]), "=r"(r[1]), "=r"(r[2]), "=r"(r[3]) : "r"(a));
}
__device__ __forceinline__ void mma16816(float* d, const uint32_t* a, const uint32_t* b) {
    asm volatile("mma.sync.aligned.m16n8k16.row.col.f32.f16.f16.f32 "
        "{%0,%1,%2,%3},{%4,%5,%6,%7},{%8,%9},{%0,%1,%2,%3};"
        : "+f"(d[0]), "+f"(d[1]), "+f"(d[2]), "+f"(d[3])
        : "r"(a[0]), "r"(a[1]), "r"(a[2]), "r"(a[3]), "r"(b[0]), "r"(b[1]));
}
__device__ __forceinline__ void cpasync16(uint32_t dst, const void* src) {
    asm volatile("cp.async.cg.shared.global [%0], [%1], 16;" :: "r"(dst), "l"(src) : "memory");
}
#define CP_COMMIT() asm volatile("cp.async.commit_group;" ::: "memory")
#define CP_WAIT(n)  asm volatile("cp.async.wait_group %0;" :: "n"(n) : "memory")

// SW128 swizzle: 128B rows; colu = 16B unit index 0..7
__device__ __forceinline__ uint32_t swz(uint32_t row, uint32_t colu) {
    return row * 128 + (((colu ^ row) & 7) << 4) + ((colu & ~7u) << 4);
}
__device__ __forceinline__ uint32_t pack_h2(float x, float y) {
    __half2 h = __floats2half2_rn(x, y);
    return *(uint32_t*)&h;
}
// FFMA-pipe exp2 for t <= 0; err ~1e-5
__device__ __forceinline__ float exp2fast(float t) {
    t = fmaxf(t, -126.0f);
    float fi = floorf(t);
    float f = t - fi;
    float p = 1.5435291e-4f;
    p = p * f + 1.3333558e-3f;
    p = p * f + 9.6181291e-3f;
    p = p * f + 5.5504109e-2f;
    p = p * f + 2.4022651e-1f;
    p = p * f + 6.9314718e-1f;
    p = p * f + 1.0f;
    return __int_as_float(((int)fi + 127) << 23) * p;
}

// ------------------------------- temb path --------------------------------
__global__ void __launch_bounds__(1024) temb1_k(
        const float* __restrict__ t, const float* __restrict__ W,
        const float* __restrict__ bias) {
    __shared__ float red[8][128];
    const int n0 = blockIdx.x * 128, b = blockIdx.y;
    const int n = threadIdx.x & 127, ks = threadIdx.x >> 7;
    const float* tr = t + b * HH;
    float acc = 0.f;
    const int kbeg = ks * 96;
    #pragma unroll 4
    for (int k = kbeg; k < kbeg + 96; k++)
        acc += tr[k] * W[(size_t)k * 4608 + n0 + n];
    red[ks][n] = acc;
    __syncthreads();
    if (ks == 0) {
        float s = bias[n0 + n];
        #pragma unroll
        for (int i = 0; i < 8; i++) s += red[i][n];
        g_hid[b * 4608 + n0 + n] = s / (1.0f + expf(-s));
    }
}
__global__ void __launch_bounds__(1024) temb2_k(
        const float* __restrict__ W, const float* __restrict__ bias) {
    __shared__ float red[8][128];
    const int n0 = blockIdx.x * 128, b = blockIdx.y;
    const int n = threadIdx.x & 127, ks = threadIdx.x >> 7;
    const float* hr = g_hid + b * 4608;
    float acc = 0.f;
    const int kbeg = ks * 576;
    #pragma unroll 4
    for (int k = kbeg; k < kbeg + 576; k++)
        acc += hr[k] * W[(size_t)k * 4608 + n0 + n];
    red[ks][n] = acc;
    __syncthreads();
    if (ks == 0) {
        float s = bias[n0 + n];
        #pragma unroll
        for (int i = 0; i < 8; i++) s += red[i][n];
        g_temb[b * 4608 + n0 + n] = s;
    }
}

// ------------- merged weight transpose + fp16 convert (one launch) ---------
// tiles: qkv 1728 | m1 2304 | m2 2304 | f1 2304 | f2 2304  (total 10944)
__global__ void wtconv_all(const float* __restrict__ wq, const float* __restrict__ wm1,
                           const float* __restrict__ wm2, const float* __restrict__ wf1,
                           const float* __restrict__ wf2) {
    __shared__ float s[32][33];
    int gid = blockIdx.x;
    const float* W; __half* O; int K, N;
    if (gid < 1728)      { W = wq;  O = g_wqkv; K = 768;  N = 2304; }
    else if (gid < 4032) { W = wm1; O = g_wm1;  K = 768;  N = 3072; gid -= 1728; }
    else if (gid < 6336) { W = wm2; O = g_wm2;  K = 3072; N = 768;  gid -= 4032; }
    else if (gid < 8640) { W = wf1; O = g_wf1;  K = 768;  N = 3072; gid -= 6336; }
    else                 { W = wf2; O = g_wf2;  K = 3072; N = 768;  gid -= 8640; }
    int nx = N >> 5;
    int n0 = (gid % nx) * 32, k0 = (gid / nx) * 32;
    int tx = threadIdx.x, ty = threadIdx.y;
    #pragma unroll
    for (int j = 0; j < 32; j += 8)
        s[ty + j][tx] = W[(size_t)(k0 + ty + j) * N + n0 + tx];
    __syncthreads();
    #pragma unroll
    for (int j = 0; j < 32; j += 8)
        O[(size_t)(n0 + ty + j) * K + k0 + tx] = __float2half(s[tx][ty + j]);
}

// --------------------------- LayerNorm + modulate --------------------------
__global__ void __launch_bounds__(256) ln_mod_k(
        const float* __restrict__ x,
        const float* __restrict__ lng, const float* __restrict__ lnb,
        int goff, __half* __restrict__ y) {
    const int row = blockIdx.x * 8 + (threadIdx.x >> 5);
    const int lane = threadIdx.x & 31;
    const float* xr = x + (size_t)row * HH;
    float v[24];
    float s = 0.f, s2 = 0.f;
    #pragma unroll
    for (int j = 0; j < 24; j++) {
        v[j] = xr[lane + j * 32];
        s += v[j]; s2 += v[j] * v[j];
    }
    #pragma unroll
    for (int o = 16; o; o >>= 1) {
        s  += __shfl_xor_sync(0xffffffffu, s, o);
        s2 += __shfl_xor_sync(0xffffffffu, s2, o);
    }
    const float inv = 1.0f / 768.0f;
    float mu = s * inv;
    float var = s2 * inv - mu * mu;
    float rs = rsqrtf(var + 1e-5f);
    const float* tb = g_temb + (row >> 11) * 4608 + goff;
    #pragma unroll
    for (int j = 0; j < 24; j++) {
        int i = lane + j * 32;
        float val = (v[j] - mu) * rs * lng[i] + lnb[i];
        y[(size_t)row * HH + i] = __float2half(tb[i] * val + tb[768 + i]);
    }
}

// ------------------------------ HMMA GEMM ----------------------------------
// SW128 swizzled tiles, K-chunk 64, 3-stage ring, loads issued post-barrier.
// EPI: 1=gelu->fp16, 2=residual+gate->fp32, 3=qkv->scaled fp16 q/k/v
#define MTILE 16384             // 128 rows * 128B
#define STAGE (2*MTILE)         // A + B = 32768
#define GEMM_SMEM (3*STAGE)     // 98304
template <int EPI>
__global__ void __launch_bounds__(256, 2) hgemm_k(
    const __half* __restrict__ A, const __half* __restrict__ Bt,
    const float* __restrict__ bias,
    float* __restrict__ Cf, __half* __restrict__ Ch,
    int N, int K,
    const float* __restrict__ res, int gate_off) {

    extern __shared__ char sm[];
    const uint32_t sbase = smem_u32(sm);
    const int tid = threadIdx.x, lane = tid & 31, wid = tid >> 5;
    const int bm = blockIdx.y, bn = blockIdx.x;
    const int am0 = bm * 128, bn0 = bn * 128;
    const int wm0 = (wid >> 1) * 32, wn0 = (wid & 1) * 64;

    float acc[2][8][4];
    #pragma unroll
    for (int i = 0; i < 2; i++)
        #pragma unroll
        for (int j = 0; j < 8; j++)
            #pragma unroll
            for (int q = 0; q < 4; q++) acc[i][j][q] = 0.f;

    // cp.async: 8 x 16B chunks per thread per stage (A 128x64h + B 128x64h)
    const __half* mats[2] = {A, Bt};
    const __half* srcb[8];
    uint32_t dstb[8];
    #pragma unroll
    for (int it = 0; it < 8; it++) {
        int idx = tid + it * 256;
        int mat = idx >> 10, r = (idx >> 3) & 127, c = idx & 7;
        int grow = (mat == 0 ? am0 : bn0) + r;
        srcb[it] = mats[mat] + (size_t)grow * K + c * 8;
        dstb[it] = sbase + mat * MTILE + swz(r, c);
    }

    // ldsm lane geometry
    uint32_t arowb[2]; int arl[2];
    #pragma unroll
    for (int mi = 0; mi < 2; mi++) {
        int row = wm0 + mi * 16 + (lane & 15);
        arowb[mi] = row * 128; arl[mi] = row & 7;
    }
    const int acol = lane >> 4;
    uint32_t browb[4]; int brl[4];
    #pragma unroll
    for (int ng = 0; ng < 4; ng++) {
        int row = wn0 + ng * 16 + (lane & 7) + ((lane & 16) >> 1);
        browb[ng] = MTILE + row * 128; brl[ng] = row & 7;
    }
    const int bcol = (lane >> 3) & 1;

    const int KB = K >> 6;
    // prologue: stages 0,1
    #pragma unroll
    for (int pf = 0; pf < 2; pf++) {
        #pragma unroll
        for (int it = 0; it < 8; it++)
            cpasync16(dstb[it] + pf * STAGE, srcb[it] + pf * 64);
        CP_COMMIT();
    }

    int slot = 0;
    for (int kb = 0; kb < KB; kb++) {
        if (kb + 1 < KB) { CP_WAIT(1); } else { CP_WAIT(0); }
        __syncthreads();
        if (kb + 2 < KB) {
            int wslot = slot + 2; if (wslot >= 3) wslot -= 3;
            const uint32_t so2 = wslot * STAGE;
            const int ko = (kb + 2) << 6;
            #pragma unroll
            for (int it = 0; it < 8; it++) cpasync16(dstb[it] + so2, srcb[it] + ko);
            CP_COMMIT();
        }
        const uint32_t so = sbase + slot * STAGE;
        #pragma unroll
        for (int kc = 0; kc < 4; kc++) {
            uint32_t a[2][4];
            #pragma unroll
            for (int mi = 0; mi < 2; mi++)
                ldsm4(a[mi], so + arowb[mi] + ((((kc*2 + acol) ^ arl[mi]) & 7) << 4));
            uint32_t b[8][2];
            #pragma unroll
            for (int ng = 0; ng < 4; ng++) {
                uint32_t r[4];
                ldsm4(r, so + browb[ng] + ((((kc*2 + bcol) ^ brl[ng]) & 7) << 4));
                b[2*ng][0] = r[0]; b[2*ng][1] = r[1];
                b[2*ng+1][0] = r[2]; b[2*ng+1][1] = r[3];
            }
            #pragma unroll
            for (int mi = 0; mi < 2; mi++)
                #pragma unroll
                for (int ni = 0; ni < 8; ni++)
                    mma16816(acc[mi][ni], a[mi], b[ni]);
        }
        if (++slot == 3) slot = 0;
    }

    // ----------------------------- epilogue -------------------------------
    const int rbase = am0 + wm0 + (lane >> 2);
    const int cbase = bn0 + wn0 + (lane & 3) * 2;
    #pragma unroll
    for (int mi = 0; mi < 2; mi++) {
        #pragma unroll
        for (int ni = 0; ni < 8; ni++) {
            int col = cbase + ni * 8;
            float2 bb = *(const float2*)&bias[col];
            #pragma unroll
            for (int half2i = 0; half2i < 2; half2i++) {
                int row = rbase + mi * 16 + half2i * 8;
                float v0 = acc[mi][ni][2*half2i]   + bb.x;
                float v1 = acc[mi][ni][2*half2i+1] + bb.y;
                if (EPI == 1) {
                    v0 = 0.5f * v0 * (1.0f + erff(v0 * 0.70710678118654752f));
                    v1 = 0.5f * v1 * (1.0f + erff(v1 * 0.70710678118654752f));
                    *(uint32_t*)(Ch + (size_t)row * N + col) = pack_h2(v0, v1);
                } else if (EPI == 3) {
                    int i3 = col / 768;
                    int rem = col - i3 * 768;
                    int hh = rem >> 6, d = rem & 63;
                    int b2 = row >> 11, t2 = row & 2047;
                    size_t idx = ((size_t)((b2 * NHD + hh) * TT + t2)) * HDD + d;
                    if (i3 == 0) { v0 *= QSCALE; v1 *= QSCALE; }
                    __half* dh = (i3 == 0) ? g_q : (i3 == 1) ? g_k : g_v;
                    *(uint32_t*)(dh + idx) = pack_h2(v0, v1);
                } else {
                    if (EPI == 2) {
                        const float* tb = g_temb + (row >> 11) * 4608 + gate_off;
                        float2 rr = *(const float2*)&res[(size_t)row * N + col];
                        float2 gg = *(const float2*)&tb[col];
                        v0 = rr.x + gg.x * v0;
                        v1 = rr.y + gg.y * v1;
                    }
                    float2 o2; o2.x = v0; o2.y = v1;
                    *(float2*)&Cf[(size_t)row * N + col] = o2;
                }
            }
        }
    }
}

// -------------------- tensor-core flash attention --------------------------
// 128-key stages (two 64-key softmax sub-passes), double-buffered.
#define QB    16384              // 128 rows * 128B
#define KVST  32768              // K(128x128B) + V(128x128B)
#define ATTN_SMEM (QB + 2*KVST)  // 81920
__global__ void __launch_bounds__(256, 2) attn_tc(void) {
    extern __shared__ char sm[];
    const uint32_t sbase = smem_u32(sm);
    const int tid = threadIdx.x, lane = tid & 31, wid = tid >> 5;
    const int bh = blockIdx.x;            // 0..23
    const int qb = blockIdx.y;            // 0..15
    const size_t headbase = (size_t)bh * TT * HDD;

    const __half* kvmats[2] = {g_k, g_v};

    // prologue: Q + KV stage 0 (one group)
    #pragma unroll
    for (int it = 0; it < 4; it++) {
        int idx = tid + it * 256;
        int r = idx >> 3, c = idx & 7;
        cpasync16(sbase + swz(r, c),
                  g_q + headbase + (size_t)(qb * 128 + r) * HDD + c * 8);
    }
    #pragma unroll
    for (int it = 0; it < 8; it++) {
        int idx = tid + it * 256;
        int mat = idx >> 10, r = (idx >> 3) & 127, c = idx & 7;
        cpasync16(sbase + QB + mat * MTILE + swz(r, c),
                  kvmats[mat] + headbase + (size_t)r * HDD + c * 8);
    }
    CP_COMMIT();

    // lane geometry
    const int qrow = wid * 16 + (lane & 15);
    const uint32_t qrowb = qrow * 128; const int qrl = qrow & 7;
    const int qcol = lane >> 4;
    int krow[4];
    #pragma unroll
    for (int ng = 0; ng < 4; ng++)
        krow[ng] = ng * 16 + (lane & 7) + ((lane & 16) >> 1);
    const int kcol = (lane >> 3) & 1;
    const int vrowl = (lane & 7) + (lane & 8);    // + kc*16 + s*64
    const int vcol0 = (lane >> 4) & 1;            // + ng*2

    uint32_t qh[4][4];
    float o[8][4];
    #pragma unroll
    for (int n = 0; n < 8; n++)
        #pragma unroll
        for (int j = 0; j < 4; j++) o[n][j] = 0.f;
    float m0 = -1e30f, m1 = -1e30f, l0 = 0.f, l1 = 0.f;

    const int NT = TT / 128;   // 16
    for (int t = 0; t < NT; t++) {
        CP_WAIT(0);
        __syncthreads();
        if (t == 0) {
            #pragma unroll
            for (int kc = 0; kc < 4; kc++)
                ldsm4(qh[kc], sbase + qrowb + ((((kc*2 + qcol) ^ qrl) & 7) << 4));
        }
        if (t + 1 < NT) {
            const uint32_t sb2 = sbase + QB + ((t + 1) & 1) * KVST;
            const size_t kvb = headbase + (size_t)(t + 1) * 128 * HDD;
            #pragma unroll
            for (int it = 0; it < 8; it++) {
                int idx = tid + it * 256;
                int mat = idx >> 10, r = (idx >> 3) & 127, c = idx & 7;
                cpasync16(sb2 + mat * MTILE + swz(r, c),
                          kvmats[mat] + kvb + (size_t)r * HDD + c * 8);
            }
            CP_COMMIT();
        }

        const uint32_t stb = sbase + QB + (t & 1) * KVST;
        #pragma unroll
        for (int s = 0; s < 2; s++) {
            const uint32_t kb2 = stb + s * 64 * 128;          // K sub-tile
            const uint32_t vb2 = stb + MTILE + s * 64 * 128;  // V sub-tile

            // ---- S = Q K^T ----
            float c[8][4];
            #pragma unroll
            for (int n = 0; n < 8; n++)
                #pragma unroll
                for (int j = 0; j < 4; j++) c[n][j] = 0.f;
            #pragma unroll
            for (int kc = 0; kc < 4; kc++) {
                uint32_t b[8][2];
                #pragma unroll
                for (int ng = 0; ng < 4; ng++) {
                    uint32_t r[4];
                    ldsm4(r, kb2 + krow[ng] * 128
                              + ((((kc*2 + kcol) ^ krow[ng]) & 7) << 4));
                    b[2*ng][0] = r[0]; b[2*ng][1] = r[1];
                    b[2*ng+1][0] = r[2]; b[2*ng+1][1] = r[3];
                }
                #pragma unroll
                for (int n = 0; n < 8; n++) mma16816(c[n], qh[kc], b[n]);
            }

            // ---- online softmax (log2 domain) ----
            float mx0 = -1e30f, mx1 = -1e30f;
            #pragma unroll
            for (int n = 0; n < 8; n++) {
                mx0 = fmaxf(mx0, fmaxf(c[n][0], c[n][1]));
                mx1 = fmaxf(mx1, fmaxf(c[n][2], c[n][3]));
            }
            mx0 = fmaxf(mx0, __shfl_xor_sync(0xffffffffu, mx0, 1));
            mx0 = fmaxf(mx0, __shfl_xor_sync(0xffffffffu, mx0, 2));
            mx1 = fmaxf(mx1, __shfl_xor_sync(0xffffffffu, mx1, 1));
            mx1 = fmaxf(mx1, __shfl_xor_sync(0xffffffffu, mx1, 2));
            float mn0 = fmaxf(m0, mx0), mn1 = fmaxf(m1, mx1);
            float cr0 = exp2fast(m0 - mn0), cr1 = exp2fast(m1 - mn1);
            m0 = mn0; m1 = mn1;
            l0 *= cr0; l1 *= cr1;
            #pragma unroll
            for (int n = 0; n < 8; n++) {
                o[n][0] *= cr0; o[n][1] *= cr0;
                o[n][2] *= cr1; o[n][3] *= cr1;
            }
            uint32_t pa[4][4];
            #pragma unroll
            for (int n = 0; n < 8; n++) {
                float p00 = exp2fast(c[n][0] - mn0);
                float p01 = exp2fast(c[n][1] - mn0);
                float p10 = exp2fast(c[n][2] - mn1);
                float p11 = exp2fast(c[n][3] - mn1);
                l0 += p00 + p01; l1 += p10 + p11;
                int kc2 = n >> 1, ss = (n & 1) * 2;
                pa[kc2][ss]     = pack_h2(p00, p01);
                pa[kc2][ss + 1] = pack_h2(p10, p11);
            }

            // ---- O += P V ----
            #pragma unroll
            for (int kc = 0; kc < 4; kc++) {
                uint32_t b[8][2];
                int vrow = vrowl + kc * 16;
                #pragma unroll
                for (int ng = 0; ng < 4; ng++) {
                    uint32_t r[4];
                    ldsm4t(r, vb2 + vrow * 128
                               + ((((ng*2 + vcol0) ^ vrow) & 7) << 4));
                    b[2*ng][0] = r[0]; b[2*ng][1] = r[1];
                    b[2*ng+1][0] = r[2]; b[2*ng+1][1] = r[3];
                }
                #pragma unroll
                for (int n = 0; n < 8; n++) mma16816(o[n], pa[kc], b[n]);
            }
        }
        __syncthreads();
    }

    l0 += __shfl_xor_sync(0xffffffffu, l0, 1);
    l0 += __shfl_xor_sync(0xffffffffu, l0, 2);
    l1 += __shfl_xor_sync(0xffffffffu, l1, 1);
    l1 += __shfl_xor_sync(0xffffffffu, l1, 2);
    float i0 = 1.0f / l0, i1 = 1.0f / l1;

    const int b2 = bh / NHD, h2 = bh % NHD;
    const int r0 = qb * 128 + wid * 16 + (lane >> 2);
    const int cb = h2 * 64 + (lane & 3) * 2;
    #pragma unroll
    for (int n = 0; n < 8; n++) {
        int col = cb + n * 8;
        size_t o0 = (size_t)(b2 * TT + r0) * HH + col;
        *(uint32_t*)(g_o + o0) = pack_h2(o[n][0] * i0, o[n][1] * i0);
        size_t o1 = (size_t)(b2 * TT + r0 + 8) * HH + col;
        *(uint32_t*)(g_o + o1) = pack_h2(o[n][2] * i1, o[n][3] * i1);
    }
}

// ------------------------------- launcher ----------------------------------
extern "C" void kernel_launch(void* const* d_in, const int* in_sizes, int n_in,
                              void* d_out, int out_size) {
    const float* x      = (const float*)d_in[0];
    const float* t      = (const float*)d_in[1];
    const float* w_qkv  = (const float*)d_in[2];
    const float* b_qkv  = (const float*)d_in[3];
    const float* w_m1   = (const float*)d_in[4];
    const float* b_m1   = (const float*)d_in[5];
    const float* w_m2   = (const float*)d_in[6];
    const float* b_m2   = (const float*)d_in[7];
    const float* w_ss1  = (const float*)d_in[8];
    const float* b_ss1  = (const float*)d_in[9];
    const float* w_ss2  = (const float*)d_in[10];
    const float* b_ss2  = (const float*)d_in[11];
    const float* ln1_g  = (const float*)d_in[12];
    const float* ln1_b  = (const float*)d_in[13];
    const float* ln2_g  = (const float*)d_in[14];
    const float* ln2_b  = (const float*)d_in[15];
    const float* w_f1   = (const float*)d_in[16];
    const float* b_f1   = (const float*)d_in[17];
    const float* w_f2   = (const float*)d_in[18];
    const float* b_f2   = (const float*)d_in[19];
    float* out = (float*)d_out;

    float *p_x1;
    __half *p_h, *p_o, *p_u;
    __half *p_wq, *p_wm1, *p_wm2, *p_wf1, *p_wf2;
    cudaGetSymbolAddress((void**)&p_x1,  g_x1);
    cudaGetSymbolAddress((void**)&p_h,   g_h);
    cudaGetSymbolAddress((void**)&p_o,   g_o);
    cudaGetSymbolAddress((void**)&p_u,   g_u);
    cudaGetSymbolAddress((void**)&p_wq,  g_wqkv);
    cudaGetSymbolAddress((void**)&p_wm1, g_wm1);
    cudaGetSymbolAddress((void**)&p_wm2, g_wm2);
    cudaGetSymbolAddress((void**)&p_wf1, g_wf1);
    cudaGetSymbolAddress((void**)&p_wf2, g_wf2);

    cudaFuncSetAttribute(attn_tc, cudaFuncAttributeMaxDynamicSharedMemorySize, ATTN_SMEM);
    cudaFuncSetAttribute(hgemm_k<1>, cudaFuncAttributeMaxDynamicSharedMemorySize, GEMM_SMEM);
    cudaFuncSetAttribute(hgemm_k<2>, cudaFuncAttributeMaxDynamicSharedMemorySize, GEMM_SMEM);
    cudaFuncSetAttribute(hgemm_k<3>, cudaFuncAttributeMaxDynamicSharedMemorySize, GEMM_SMEM);

    wtconv_all<<<10944, dim3(32, 8)>>>(w_qkv, w_m1, w_m2, w_f1, w_f2);

    temb1_k<<<dim3(36, 2), 1024>>>(t, w_ss1, b_ss1);
    temb2_k<<<dim3(36, 2), 1024>>>(w_ss2, b_ss2);

    ln_mod_k<<<512, 256>>>(x, ln1_g, ln1_b, 0, p_h);

    hgemm_k<3><<<dim3(2304/128, MROWS/128), 256, GEMM_SMEM>>>(
        p_h, p_wq, b_qkv, nullptr, nullptr, 2304, 768, nullptr, 0);

    attn_tc<<<dim3(BB * NHD, TT / 128), 256, ATTN_SMEM>>>();

    hgemm_k<1><<<dim3(3072/128, MROWS/128), 256, GEMM_SMEM>>>(
        p_o, p_wm1, b_m1, nullptr, p_u, 3072, 768, nullptr, 0);

    hgemm_k<2><<<dim3(768/128, MROWS/128), 256, GEMM_SMEM>>>(
        p_u, p_wm2, b_m2, p_x1, nullptr, 768, 3072, x, 1536);

    ln_mod_k<<<512, 256>>>(p_x1, ln2_g, ln2_b, 2304, p_h);

    hgemm_k<1><<<dim3(3072/128, MROWS/128), 256, GEMM_SMEM>>>(
        p_h, p_wf1, b_f1, nullptr, p_u, 3072, 768, nullptr, 0);

    hgemm_k<2><<<dim3(768/128, MROWS/128), 256, GEMM_SMEM>>>(
        p_u, p_wf2, b_f2, out, nullptr, 768, 3072, p_x1, 3840);
}

// round 10
// speedup vs baseline: 11.1132x; 1.0227x over previous
#include <cuda_runtime.h>
#include <cuda_fp16.h>
#include <math.h>
#include <stdint.h>

// ---------------------------------------------------------------------------
// DiT block. fp16 mma.sync GEMMs (SW128 swizzle, 3-stage cp.async ring),
// fp16 tensor-core flash attention (128-key stages), FFMA exp2 softmax.
// B=2, T=2048, H=768, NH=12, HD=64.
// ---------------------------------------------------------------------------

#define HH   768
#define NHD  12
#define HDD  64
#define TT   2048
#define BB   2
#define MROWS (BB*TT)          // 4096

#define QSCALE 0.05205877172640942f   // log2(e)/sqrt(768)

// ------------------------- scratch (static device) -------------------------
__device__ float g_hid [BB*6*HH];
__device__ float g_temb[BB*6*HH];
__device__ float g_x1  [MROWS*HH];

__device__ __half g_h[MROWS*HH];
__device__ __half g_o[MROWS*HH];
__device__ __half g_u[MROWS*4*HH];

// attention operands, head-major [b][h][T][64]
__device__ __half g_q[MROWS*HH];
__device__ __half g_k[MROWS*HH];
__device__ __half g_v[MROWS*HH];

// transposed fp16 weights  W[K,N] -> Wt[N,K]
__device__ __half g_wqkv[3*HH*HH];
__device__ __half g_wm1 [4*HH*HH];
__device__ __half g_wm2 [HH*4*HH];
__device__ __half g_wf1 [4*HH*HH];
__device__ __half g_wf2 [HH*4*HH];

// ----------------------------- PTX helpers --------------------------------
__device__ __forceinline__ uint32_t smem_u32(const void* p) {
    uint32_t a;
    asm("{ .reg .u64 t; cvta.to.shared.u64 t, %1; cvt.u32.u64 %0, t; }" : "=r"(a) : "l"(p));
    return a;
}
__device__ __forceinline__ void ldsm4(uint32_t* r, uint32_t a) {
    asm volatile("ldmatrix.sync.aligned.m8n8.x4.shared.b16 {%0,%1,%2,%3}, [%4];"
        : "=r"(r[0]), "=r"(r[1]), "=r"(r[2]), "=r"(r[3]) : "r"(a));
}
__device__ __forceinline__ void ldsm4t(uint32_t* r, uint32_t a) {
    asm volatile("ldmatrix.sync.aligned.m8n8.x4.trans.shared.b16 {%0,%1,%2,%3}, [%4];"
        : "=r"(r[0]), "=r"(r[1]), "=r"(r[2]), "=r"(r[3]) : "r"(a));
}
__device__ __forceinline__ void mma16816(float* d, const uint32_t* a, const uint32_t* b) {
    asm volatile("mma.sync.aligned.m16n8k16.row.col.f32.f16.f16.f32 "
        "{%0,%1,%2,%3},{%4,%5,%6,%7},{%8,%9},{%0,%1,%2,%3};"
        : "+f"(d[0]), "+f"(d[1]), "+f"(d[2]), "+f"(d[3])
        : "r"(a[0]), "r"(a[1]), "r"(a[2]), "r"(a[3]), "r"(b[0]), "r"(b[1]));
}
__device__ __forceinline__ void cpasync16(uint32_t dst, const void* src) {
    asm volatile("cp.async.cg.shared.global [%0], [%1], 16;" :: "r"(dst), "l"(src) : "memory");
}
#define CP_COMMIT() asm volatile("cp.async.commit_group;" ::: "memory")
#define CP_WAIT(n)  asm volatile("cp.async.wait_group %0;" :: "n"(n) : "memory")

// SW128 swizzle: 128B rows; colu = 16B unit index 0..7
__device__ __forceinline__ uint32_t swz(uint32_t row, uint32_t colu) {
    return row * 128 + (((colu ^ row) & 7) << 4) + ((colu & ~7u) << 4);
}
__device__ __forceinline__ uint32_t pack_h2(float x, float y) {
    __half2 h = __floats2half2_rn(x, y);
    return *(uint32_t*)&h;
}
// FFMA-pipe exp2 for t <= 0; err ~1e-5
__device__ __forceinline__ float exp2fast(float t) {
    t = fmaxf(t, -126.0f);
    float fi = floorf(t);
    float f = t - fi;
    float p = 1.5435291e-4f;
    p = p * f + 1.3333558e-3f;
    p = p * f + 9.6181291e-3f;
    p = p * f + 5.5504109e-2f;
    p = p * f + 2.4022651e-1f;
    p = p * f + 6.9314718e-1f;
    p = p * f + 1.0f;
    return __int_as_float(((int)fi + 127) << 23) * p;
}

// ------------------------------- temb path --------------------------------
// grid 36, block 1024 = 128 n-lanes x 8 k-slices; both batches per block.
__global__ void __launch_bounds__(1024) temb1_k(
        const float* __restrict__ t, const float* __restrict__ W,
        const float* __restrict__ bias) {
    __shared__ float red[8][2][128];
    const int n0 = blockIdx.x * 128;
    const int n = threadIdx.x & 127, ks = threadIdx.x >> 7;
    float a0 = 0.f, a1 = 0.f;
    const int kbeg = ks * 96;
    #pragma unroll 4
    for (int k = kbeg; k < kbeg + 96; k++) {
        float w = W[(size_t)k * 4608 + n0 + n];
        a0 += t[k] * w;
        a1 += t[HH + k] * w;
    }
    red[ks][0][n] = a0; red[ks][1][n] = a1;
    __syncthreads();
    if (ks < 2) {
        float s = bias[n0 + n];
        #pragma unroll
        for (int i = 0; i < 8; i++) s += red[i][ks][n];
        g_hid[ks * 4608 + n0 + n] = s / (1.0f + expf(-s));
    }
}
__global__ void __launch_bounds__(1024) temb2_k(
        const float* __restrict__ W, const float* __restrict__ bias) {
    __shared__ float red[8][2][128];
    const int n0 = blockIdx.x * 128;
    const int n = threadIdx.x & 127, ks = threadIdx.x >> 7;
    float a0 = 0.f, a1 = 0.f;
    const int kbeg = ks * 576;
    #pragma unroll 4
    for (int k = kbeg; k < kbeg + 576; k++) {
        float w = W[(size_t)k * 4608 + n0 + n];
        a0 += g_hid[k] * w;
        a1 += g_hid[4608 + k] * w;
    }
    red[ks][0][n] = a0; red[ks][1][n] = a1;
    __syncthreads();
    if (ks < 2) {
        float s = bias[n0 + n];
        #pragma unroll
        for (int i = 0; i < 8; i++) s += red[i][ks][n];
        g_temb[ks * 4608 + n0 + n] = s;
    }
}

// ------------- merged weight transpose + fp16 convert (one launch) ---------
// tiles: qkv 1728 | m1 2304 | m2 2304 | f1 2304 | f2 2304  (total 10944)
__global__ void wtconv_all(const float* __restrict__ wq, const float* __restrict__ wm1,
                           const float* __restrict__ wm2, const float* __restrict__ wf1,
                           const float* __restrict__ wf2) {
    __shared__ float s[32][33];
    int gid = blockIdx.x;
    const float* W; __half* O; int K, N;
    if (gid < 1728)      { W = wq;  O = g_wqkv; K = 768;  N = 2304; }
    else if (gid < 4032) { W = wm1; O = g_wm1;  K = 768;  N = 3072; gid -= 1728; }
    else if (gid < 6336) { W = wm2; O = g_wm2;  K = 3072; N = 768;  gid -= 4032; }
    else if (gid < 8640) { W = wf1; O = g_wf1;  K = 768;  N = 3072; gid -= 6336; }
    else                 { W = wf2; O = g_wf2;  K = 3072; N = 768;  gid -= 8640; }
    int nx = N >> 5;
    int n0 = (gid % nx) * 32, k0 = (gid / nx) * 32;
    int tx = threadIdx.x, ty = threadIdx.y;
    #pragma unroll
    for (int j = 0; j < 32; j += 8)
        s[ty + j][tx] = W[(size_t)(k0 + ty + j) * N + n0 + tx];
    __syncthreads();
    // half2 stores: 32 rows x 16 half2-cols = 512 stores over 256 threads
    const int t = ty * 32 + tx;
    #pragma unroll
    for (int it = 0; it < 2; it++) {
        int idx = t + it * 256;
        int r = idx >> 4, kp = idx & 15;
        __half2 hv = __floats2half2_rn(s[2*kp][r], s[2*kp + 1][r]);
        *(__half2*)(O + (size_t)(n0 + r) * K + k0 + 2*kp) = hv;
    }
}

// --------------------------- LayerNorm + modulate --------------------------
// warp per row; float4 loads, half2x2 stores. block 256 = 8 rows; grid 512.
__global__ void __launch_bounds__(256) ln_mod_k(
        const float* __restrict__ x,
        const float* __restrict__ lng, const float* __restrict__ lnb,
        int goff, __half* __restrict__ y) {
    const int row = blockIdx.x * 8 + (threadIdx.x >> 5);
    const int lane = threadIdx.x & 31;
    const float4* xr = (const float4*)(x + (size_t)row * HH);
    float4 v[6];
    float s = 0.f, s2 = 0.f;
    #pragma unroll
    for (int j = 0; j < 6; j++) {
        v[j] = xr[lane + j * 32];
        s  += v[j].x + v[j].y + v[j].z + v[j].w;
        s2 += v[j].x*v[j].x + v[j].y*v[j].y + v[j].z*v[j].z + v[j].w*v[j].w;
    }
    #pragma unroll
    for (int o = 16; o; o >>= 1) {
        s  += __shfl_xor_sync(0xffffffffu, s, o);
        s2 += __shfl_xor_sync(0xffffffffu, s2, o);
    }
    const float inv = 1.0f / 768.0f;
    float mu = s * inv;
    float var = s2 * inv - mu * mu;
    float rs = rsqrtf(var + 1e-5f);
    const float4* g4 = (const float4*)lng;
    const float4* b4 = (const float4*)lnb;
    const float* tbb = g_temb + (row >> 11) * 4608 + goff;
    const float4* t4 = (const float4*)tbb;
    const float4* a4 = (const float4*)(tbb + 768);
    #pragma unroll
    for (int j = 0; j < 6; j++) {
        int i = lane + j * 32;
        float4 gg = g4[i], bb = b4[i], tt = t4[i], aa = a4[i];
        float r0 = ((v[j].x - mu) * rs * gg.x + bb.x) * tt.x + aa.x;
        float r1 = ((v[j].y - mu) * rs * gg.y + bb.y) * tt.y + aa.y;
        float r2 = ((v[j].z - mu) * rs * gg.z + bb.z) * tt.z + aa.z;
        float r3 = ((v[j].w - mu) * rs * gg.w + bb.w) * tt.w + aa.w;
        uint2 o2;
        o2.x = pack_h2(r0, r1);
        o2.y = pack_h2(r2, r3);
        *(uint2*)(y + (size_t)row * HH + i * 4) = o2;
    }
}

// ------------------------------ HMMA GEMM ----------------------------------
// SW128 swizzled tiles, K-chunk 64, 3-stage ring, loads issued post-barrier.
// EPI: 1=gelu->fp16, 2=residual+gate->fp32, 3=qkv->scaled fp16 q/k/v
#define MTILE 16384             // 128 rows * 128B
#define STAGE (2*MTILE)         // A + B = 32768
#define GEMM_SMEM (3*STAGE)     // 98304
template <int EPI>
__global__ void __launch_bounds__(256, 2) hgemm_k(
    const __half* __restrict__ A, const __half* __restrict__ Bt,
    const float* __restrict__ bias,
    float* __restrict__ Cf, __half* __restrict__ Ch,
    int N, int K,
    const float* __restrict__ res, int gate_off) {

    extern __shared__ char sm[];
    const uint32_t sbase = smem_u32(sm);
    const int tid = threadIdx.x, lane = tid & 31, wid = tid >> 5;
    const int bm = blockIdx.y, bn = blockIdx.x;
    const int am0 = bm * 128, bn0 = bn * 128;
    const int wm0 = (wid >> 1) * 32, wn0 = (wid & 1) * 64;

    float acc[2][8][4];
    #pragma unroll
    for (int i = 0; i < 2; i++)
        #pragma unroll
        for (int j = 0; j < 8; j++)
            #pragma unroll
            for (int q = 0; q < 4; q++) acc[i][j][q] = 0.f;

    const __half* mats[2] = {A, Bt};
    const __half* srcb[8];
    uint32_t dstb[8];
    #pragma unroll
    for (int it = 0; it < 8; it++) {
        int idx = tid + it * 256;
        int mat = idx >> 10, r = (idx >> 3) & 127, c = idx & 7;
        int grow = (mat == 0 ? am0 : bn0) + r;
        srcb[it] = mats[mat] + (size_t)grow * K + c * 8;
        dstb[it] = sbase + mat * MTILE + swz(r, c);
    }

    uint32_t arowb[2]; int arl[2];
    #pragma unroll
    for (int mi = 0; mi < 2; mi++) {
        int row = wm0 + mi * 16 + (lane & 15);
        arowb[mi] = row * 128; arl[mi] = row & 7;
    }
    const int acol = lane >> 4;
    uint32_t browb[4]; int brl[4];
    #pragma unroll
    for (int ng = 0; ng < 4; ng++) {
        int row = wn0 + ng * 16 + (lane & 7) + ((lane & 16) >> 1);
        browb[ng] = MTILE + row * 128; brl[ng] = row & 7;
    }
    const int bcol = (lane >> 3) & 1;

    const int KB = K >> 6;
    #pragma unroll
    for (int pf = 0; pf < 2; pf++) {
        #pragma unroll
        for (int it = 0; it < 8; it++)
            cpasync16(dstb[it] + pf * STAGE, srcb[it] + pf * 64);
        CP_COMMIT();
    }

    int slot = 0;
    for (int kb = 0; kb < KB; kb++) {
        if (kb + 1 < KB) { CP_WAIT(1); } else { CP_WAIT(0); }
        __syncthreads();
        if (kb + 2 < KB) {
            int wslot = slot + 2; if (wslot >= 3) wslot -= 3;
            const uint32_t so2 = wslot * STAGE;
            const int ko = (kb + 2) << 6;
            #pragma unroll
            for (int it = 0; it < 8; it++) cpasync16(dstb[it] + so2, srcb[it] + ko);
            CP_COMMIT();
        }
        const uint32_t so = sbase + slot * STAGE;
        #pragma unroll
        for (int kc = 0; kc < 4; kc++) {
            uint32_t a[2][4];
            #pragma unroll
            for (int mi = 0; mi < 2; mi++)
                ldsm4(a[mi], so + arowb[mi] + ((((kc*2 + acol) ^ arl[mi]) & 7) << 4));
            uint32_t b[8][2];
            #pragma unroll
            for (int ng = 0; ng < 4; ng++) {
                uint32_t r[4];
                ldsm4(r, so + browb[ng] + ((((kc*2 + bcol) ^ brl[ng]) & 7) << 4));
                b[2*ng][0] = r[0]; b[2*ng][1] = r[1];
                b[2*ng+1][0] = r[2]; b[2*ng+1][1] = r[3];
            }
            #pragma unroll
            for (int mi = 0; mi < 2; mi++)
                #pragma unroll
                for (int ni = 0; ni < 8; ni++)
                    mma16816(acc[mi][ni], a[mi], b[ni]);
        }
        if (++slot == 3) slot = 0;
    }

    // ----------------------------- epilogue -------------------------------
    const int rbase = am0 + wm0 + (lane >> 2);
    const int cbase = bn0 + wn0 + (lane & 3) * 2;
    #pragma unroll
    for (int mi = 0; mi < 2; mi++) {
        #pragma unroll
        for (int ni = 0; ni < 8; ni++) {
            int col = cbase + ni * 8;
            float2 bb = *(const float2*)&bias[col];
            #pragma unroll
            for (int half2i = 0; half2i < 2; half2i++) {
                int row = rbase + mi * 16 + half2i * 8;
                float v0 = acc[mi][ni][2*half2i]   + bb.x;
                float v1 = acc[mi][ni][2*half2i+1] + bb.y;
                if (EPI == 1) {
                    v0 = 0.5f * v0 * (1.0f + erff(v0 * 0.70710678118654752f));
                    v1 = 0.5f * v1 * (1.0f + erff(v1 * 0.70710678118654752f));
                    *(uint32_t*)(Ch + (size_t)row * N + col) = pack_h2(v0, v1);
                } else if (EPI == 3) {
                    int i3 = col / 768;
                    int rem = col - i3 * 768;
                    int hh = rem >> 6, d = rem & 63;
                    int b2 = row >> 11, t2 = row & 2047;
                    size_t idx = ((size_t)((b2 * NHD + hh) * TT + t2)) * HDD + d;
                    if (i3 == 0) { v0 *= QSCALE; v1 *= QSCALE; }
                    __half* dh = (i3 == 0) ? g_q : (i3 == 1) ? g_k : g_v;
                    *(uint32_t*)(dh + idx) = pack_h2(v0, v1);
                } else {
                    if (EPI == 2) {
                        const float* tb = g_temb + (row >> 11) * 4608 + gate_off;
                        float2 rr = *(const float2*)&res[(size_t)row * N + col];
                        float2 gg = *(const float2*)&tb[col];
                        v0 = rr.x + gg.x * v0;
                        v1 = rr.y + gg.y * v1;
                    }
                    float2 o2; o2.x = v0; o2.y = v1;
                    *(float2*)&Cf[(size_t)row * N + col] = o2;
                }
            }
        }
    }
}

// -------------------- tensor-core flash attention --------------------------
// 128-key stages (two 64-key softmax sub-passes), double-buffered.
#define QB    16384              // 128 rows * 128B
#define KVST  32768              // K(128x128B) + V(128x128B)
#define ATTN_SMEM (QB + 2*KVST)  // 81920
__global__ void __launch_bounds__(256, 2) attn_tc(void) {
    extern __shared__ char sm[];
    const uint32_t sbase = smem_u32(sm);
    const int tid = threadIdx.x, lane = tid & 31, wid = tid >> 5;
    const int bh = blockIdx.x;            // 0..23
    const int qb = blockIdx.y;            // 0..15
    const size_t headbase = (size_t)bh * TT * HDD;

    const __half* kvmats[2] = {g_k, g_v};

    #pragma unroll
    for (int it = 0; it < 4; it++) {
        int idx = tid + it * 256;
        int r = idx >> 3, c = idx & 7;
        cpasync16(sbase + swz(r, c),
                  g_q + headbase + (size_t)(qb * 128 + r) * HDD + c * 8);
    }
    #pragma unroll
    for (int it = 0; it < 8; it++) {
        int idx = tid + it * 256;
        int mat = idx >> 10, r = (idx >> 3) & 127, c = idx & 7;
        cpasync16(sbase + QB + mat * MTILE + swz(r, c),
                  kvmats[mat] + headbase + (size_t)r * HDD + c * 8);
    }
    CP_COMMIT();

    const int qrow = wid * 16 + (lane & 15);
    const uint32_t qrowb = qrow * 128; const int qrl = qrow & 7;
    const int qcol = lane >> 4;
    int krow[4];
    #pragma unroll
    for (int ng = 0; ng < 4; ng++)
        krow[ng] = ng * 16 + (lane & 7) + ((lane & 16) >> 1);
    const int kcol = (lane >> 3) & 1;
    const int vrowl = (lane & 7) + (lane & 8);
    const int vcol0 = (lane >> 4) & 1;

    uint32_t qh[4][4];
    float o[8][4];
    #pragma unroll
    for (int n = 0; n < 8; n++)
        #pragma unroll
        for (int j = 0; j < 4; j++) o[n][j] = 0.f;
    float m0 = -1e30f, m1 = -1e30f, l0 = 0.f, l1 = 0.f;

    const int NT = TT / 128;   // 16
    for (int t = 0; t < NT; t++) {
        CP_WAIT(0);
        __syncthreads();
        if (t == 0) {
            #pragma unroll
            for (int kc = 0; kc < 4; kc++)
                ldsm4(qh[kc], sbase + qrowb + ((((kc*2 + qcol) ^ qrl) & 7) << 4));
        }
        if (t + 1 < NT) {
            const uint32_t sb2 = sbase + QB + ((t + 1) & 1) * KVST;
            const size_t kvb = headbase + (size_t)(t + 1) * 128 * HDD;
            #pragma unroll
            for (int it = 0; it < 8; it++) {
                int idx = tid + it * 256;
                int mat = idx >> 10, r = (idx >> 3) & 127, c = idx & 7;
                cpasync16(sb2 + mat * MTILE + swz(r, c),
                          kvmats[mat] + kvb + (size_t)r * HDD + c * 8);
            }
            CP_COMMIT();
        }

        const uint32_t stb = sbase + QB + (t & 1) * KVST;
        #pragma unroll
        for (int s = 0; s < 2; s++) {
            const uint32_t kb2 = stb + s * 64 * 128;
            const uint32_t vb2 = stb + MTILE + s * 64 * 128;

            float c[8][4];
            #pragma unroll
            for (int n = 0; n < 8; n++)
                #pragma unroll
                for (int j = 0; j < 4; j++) c[n][j] = 0.f;
            #pragma unroll
            for (int kc = 0; kc < 4; kc++) {
                uint32_t b[8][2];
                #pragma unroll
                for (int ng = 0; ng < 4; ng++) {
                    uint32_t r[4];
                    ldsm4(r, kb2 + krow[ng] * 128
                              + ((((kc*2 + kcol) ^ krow[ng]) & 7) << 4));
                    b[2*ng][0] = r[0]; b[2*ng][1] = r[1];
                    b[2*ng+1][0] = r[2]; b[2*ng+1][1] = r[3];
                }
                #pragma unroll
                for (int n = 0; n < 8; n++) mma16816(c[n], qh[kc], b[n]);
            }

            float mx0 = -1e30f, mx1 = -1e30f;
            #pragma unroll
            for (int n = 0; n < 8; n++) {
                mx0 = fmaxf(mx0, fmaxf(c[n][0], c[n][1]));
                mx1 = fmaxf(mx1, fmaxf(c[n][2], c[n][3]));
            }
            mx0 = fmaxf(mx0, __shfl_xor_sync(0xffffffffu, mx0, 1));
            mx0 = fmaxf(mx0, __shfl_xor_sync(0xffffffffu, mx0, 2));
            mx1 = fmaxf(mx1, __shfl_xor_sync(0xffffffffu, mx1, 1));
            mx1 = fmaxf(mx1, __shfl_xor_sync(0xffffffffu, mx1, 2));
            float mn0 = fmaxf(m0, mx0), mn1 = fmaxf(m1, mx1);
            float cr0 = exp2fast(m0 - mn0), cr1 = exp2fast(m1 - mn1);
            m0 = mn0; m1 = mn1;
            l0 *= cr0; l1 *= cr1;
            #pragma unroll
            for (int n = 0; n < 8; n++) {
                o[n][0] *= cr0; o[n][1] *= cr0;
                o[n][2] *= cr1; o[n][3] *= cr1;
            }
            uint32_t pa[4][4];
            #pragma unroll
            for (int n = 0; n < 8; n++) {
                float p00 = exp2fast(c[n][0] - mn0);
                float p01 = exp2fast(c[n][1] - mn0);
                float p10 = exp2fast(c[n][2] - mn1);
                float p11 = exp2fast(c[n][3] - mn1);
                l0 += p00 + p01; l1 += p10 + p11;
                int kc2 = n >> 1, ss = (n & 1) * 2;
                pa[kc2][ss]     = pack_h2(p00, p01);
                pa[kc2][ss + 1] = pack_h2(p10, p11);
            }

            #pragma unroll
            for (int kc = 0; kc < 4; kc++) {
                uint32_t b[8][2];
                int vrow = vrowl + kc * 16;
                #pragma unroll
                for (int ng = 0; ng < 4; ng++) {
                    uint32_t r[4];
                    ldsm4t(r, vb2 + vrow * 128
                               + ((((ng*2 + vcol0) ^ vrow) & 7) << 4));
                    b[2*ng][0] = r[0]; b[2*ng][1] = r[1];
                    b[2*ng+1][0] = r[2]; b[2*ng+1][1] = r[3];
                }
                #pragma unroll
                for (int n = 0; n < 8; n++) mma16816(o[n], pa[kc], b[n]);
            }
        }
        __syncthreads();
    }

    l0 += __shfl_xor_sync(0xffffffffu, l0, 1);
    l0 += __shfl_xor_sync(0xffffffffu, l0, 2);
    l1 += __shfl_xor_sync(0xffffffffu, l1, 1);
    l1 += __shfl_xor_sync(0xffffffffu, l1, 2);
    float i0 = 1.0f / l0, i1 = 1.0f / l1;

    const int b2 = bh / NHD, h2 = bh % NHD;
    const int r0 = qb * 128 + wid * 16 + (lane >> 2);
    const int cb = h2 * 64 + (lane & 3) * 2;
    #pragma unroll
    for (int n = 0; n < 8; n++) {
        int col = cb + n * 8;
        size_t o0 = (size_t)(b2 * TT + r0) * HH + col;
        *(uint32_t*)(g_o + o0) = pack_h2(o[n][0] * i0, o[n][1] * i0);
        size_t o1 = (size_t)(b2 * TT + r0 + 8) * HH + col;
        *(uint32_t*)(g_o + o1) = pack_h2(o[n][2] * i1, o[n][3] * i1);
    }
}

// ------------------------------- launcher ----------------------------------
extern "C" void kernel_launch(void* const* d_in, const int* in_sizes, int n_in,
                              void* d_out, int out_size) {
    const float* x      = (const float*)d_in[0];
    const float* t      = (const float*)d_in[1];
    const float* w_qkv  = (const float*)d_in[2];
    const float* b_qkv  = (const float*)d_in[3];
    const float* w_m1   = (const float*)d_in[4];
    const float* b_m1   = (const float*)d_in[5];
    const float* w_m2   = (const float*)d_in[6];
    const float* b_m2   = (const float*)d_in[7];
    const float* w_ss1  = (const float*)d_in[8];
    const float* b_ss1  = (const float*)d_in[9];
    const float* w_ss2  = (const float*)d_in[10];
    const float* b_ss2  = (const float*)d_in[11];
    const float* ln1_g  = (const float*)d_in[12];
    const float* ln1_b  = (const float*)d_in[13];
    const float* ln2_g  = (const float*)d_in[14];
    const float* ln2_b  = (const float*)d_in[15];
    const float* w_f1   = (const float*)d_in[16];
    const float* b_f1   = (const float*)d_in[17];
    const float* w_f2   = (const float*)d_in[18];
    const float* b_f2   = (const float*)d_in[19];
    float* out = (float*)d_out;

    float *p_x1;
    __half *p_h, *p_o, *p_u;
    __half *p_wq, *p_wm1, *p_wm2, *p_wf1, *p_wf2;
    cudaGetSymbolAddress((void**)&p_x1,  g_x1);
    cudaGetSymbolAddress((void**)&p_h,   g_h);
    cudaGetSymbolAddress((void**)&p_o,   g_o);
    cudaGetSymbolAddress((void**)&p_u,   g_u);
    cudaGetSymbolAddress((void**)&p_wq,  g_wqkv);
    cudaGetSymbolAddress((void**)&p_wm1, g_wm1);
    cudaGetSymbolAddress((void**)&p_wm2, g_wm2);
    cudaGetSymbolAddress((void**)&p_wf1, g_wf1);
    cudaGetSymbolAddress((void**)&p_wf2, g_wf2);

    cudaFuncSetAttribute(attn_tc, cudaFuncAttributeMaxDynamicSharedMemorySize, ATTN_SMEM);
    cudaFuncSetAttribute(hgemm_k<1>, cudaFuncAttributeMaxDynamicSharedMemorySize, GEMM_SMEM);
    cudaFuncSetAttribute(hgemm_k<2>, cudaFuncAttributeMaxDynamicSharedMemorySize, GEMM_SMEM);
    cudaFuncSetAttribute(hgemm_k<3>, cudaFuncAttributeMaxDynamicSharedMemorySize, GEMM_SMEM);

    wtconv_all<<<10944, dim3(32, 8)>>>(w_qkv, w_m1, w_m2, w_f1, w_f2);

    temb1_k<<<36, 1024>>>(t, w_ss1, b_ss1);
    temb2_k<<<36, 1024>>>(w_ss2, b_ss2);

    ln_mod_k<<<512, 256>>>(x, ln1_g, ln1_b, 0, p_h);

    hgemm_k<3><<<dim3(2304/128, MROWS/128), 256, GEMM_SMEM>>>(
        p_h, p_wq, b_qkv, nullptr, nullptr, 2304, 768, nullptr, 0);

    attn_tc<<<dim3(BB * NHD, TT / 128), 256, ATTN_SMEM>>>();

    hgemm_k<1><<<dim3(3072/128, MROWS/128), 256, GEMM_SMEM>>>(
        p_o, p_wm1, b_m1, nullptr, p_u, 3072, 768, nullptr, 0);

    hgemm_k<2><<<dim3(768/128, MROWS/128), 256, GEMM_SMEM>>>(
        p_u, p_wm2, b_m2, p_x1, nullptr, 768, 3072, x, 1536);

    ln_mod_k<<<512, 256>>>(p_x1, ln2_g, ln2_b, 2304, p_h);

    hgemm_k<1><<<dim3(3072/128, MROWS/128), 256, GEMM_SMEM>>>(
        p_h, p_wf1, b_f1, nullptr, p_u, 3072, 768, nullptr, 0);

    hgemm_k<2><<<dim3(768/128, MROWS/128), 256, GEMM_SMEM>>>(
        p_u, p_wf2, b_f2, out, nullptr, 768, 3072, p_x1, 3840);
}

// round 11
// speedup vs baseline: 11.5467x; 1.0390x over previous
#include <cuda_runtime.h>
#include <cuda_fp16.h>
#include <math.h>
#include <stdint.h>

// ---------------------------------------------------------------------------
// DiT block. fp16 mma.sync GEMMs (SW128 swizzle, 3-stage cp.async ring),
// fp16 tensor-core flash attention (128-key stages), FFMA exp2 softmax.
// M64 tile variant for the 192-CTA down-projection GEMMs (occupancy fix).
// B=2, T=2048, H=768, NH=12, HD=64.
// ---------------------------------------------------------------------------

#define HH   768
#define NHD  12
#define HDD  64
#define TT   2048
#define BB   2
#define MROWS (BB*TT)          // 4096

#define QSCALE 0.05205877172640942f   // log2(e)/sqrt(768)

// ------------------------- scratch (static device) -------------------------
__device__ float g_hid [BB*6*HH];
__device__ float g_temb[BB*6*HH];
__device__ float g_x1  [MROWS*HH];

__device__ __half g_h[MROWS*HH];
__device__ __half g_o[MROWS*HH];
__device__ __half g_u[MROWS*4*HH];

// attention operands, head-major [b][h][T][64]
__device__ __half g_q[MROWS*HH];
__device__ __half g_k[MROWS*HH];
__device__ __half g_v[MROWS*HH];

// transposed fp16 weights  W[K,N] -> Wt[N,K]
__device__ __half g_wqkv[3*HH*HH];
__device__ __half g_wm1 [4*HH*HH];
__device__ __half g_wm2 [HH*4*HH];
__device__ __half g_wf1 [4*HH*HH];
__device__ __half g_wf2 [HH*4*HH];

// ----------------------------- PTX helpers --------------------------------
__device__ __forceinline__ uint32_t smem_u32(const void* p) {
    uint32_t a;
    asm("{ .reg .u64 t; cvta.to.shared.u64 t, %1; cvt.u32.u64 %0, t; }" : "=r"(a) : "l"(p));
    return a;
}
__device__ __forceinline__ void ldsm4(uint32_t* r, uint32_t a) {
    asm volatile("ldmatrix.sync.aligned.m8n8.x4.shared.b16 {%0,%1,%2,%3}, [%4];"
        : "=r"(r[0]), "=r"(r[1]), "=r"(r[2]), "=r"(r[3]) : "r"(a));
}
__device__ __forceinline__ void ldsm4t(uint32_t* r, uint32_t a) {
    asm volatile("ldmatrix.sync.aligned.m8n8.x4.trans.shared.b16 {%0,%1,%2,%3}, [%4];"
        : "=r"(r[0]), "=r"(r[1]), "=r"(r[2]), "=r"(r[3]) : "r"(a));
}
__device__ __forceinline__ void mma16816(float* d, const uint32_t* a, const uint32_t* b) {
    asm volatile("mma.sync.aligned.m16n8k16.row.col.f32.f16.f16.f32 "
        "{%0,%1,%2,%3},{%4,%5,%6,%7},{%8,%9},{%0,%1,%2,%3};"
        : "+f"(d[0]), "+f"(d[1]), "+f"(d[2]), "+f"(d[3])
        : "r"(a[0]), "r"(a[1]), "r"(a[2]), "r"(a[3]), "r"(b[0]), "r"(b[1]));
}
__device__ __forceinline__ void cpasync16(uint32_t dst, const void* src) {
    asm volatile("cp.async.cg.shared.global [%0], [%1], 16;" :: "r"(dst), "l"(src) : "memory");
}
#define CP_COMMIT() asm volatile("cp.async.commit_group;" ::: "memory")
#define CP_WAIT(n)  asm volatile("cp.async.wait_group %0;" :: "n"(n) : "memory")

// SW128 swizzle: 128B rows; colu = 16B unit index 0..7
__device__ __forceinline__ uint32_t swz(uint32_t row, uint32_t colu) {
    return row * 128 + (((colu ^ row) & 7) << 4) + ((colu & ~7u) << 4);
}
__device__ __forceinline__ uint32_t pack_h2(float x, float y) {
    __half2 h = __floats2half2_rn(x, y);
    return *(uint32_t*)&h;
}
// FFMA-pipe exp2 for t <= 0; err ~1e-5
__device__ __forceinline__ float exp2fast(float t) {
    t = fmaxf(t, -126.0f);
    float fi = floorf(t);
    float f = t - fi;
    float p = 1.5435291e-4f;
    p = p * f + 1.3333558e-3f;
    p = p * f + 9.6181291e-3f;
    p = p * f + 5.5504109e-2f;
    p = p * f + 2.4022651e-1f;
    p = p * f + 6.9314718e-1f;
    p = p * f + 1.0f;
    return __int_as_float(((int)fi + 127) << 23) * p;
}

// ------------------------------- temb path --------------------------------
__global__ void __launch_bounds__(1024) temb1_k(
        const float* __restrict__ t, const float* __restrict__ W,
        const float* __restrict__ bias) {
    __shared__ float red[8][2][128];
    const int n0 = blockIdx.x * 128;
    const int n = threadIdx.x & 127, ks = threadIdx.x >> 7;
    float a0 = 0.f, a1 = 0.f;
    const int kbeg = ks * 96;
    #pragma unroll 4
    for (int k = kbeg; k < kbeg + 96; k++) {
        float w = W[(size_t)k * 4608 + n0 + n];
        a0 += t[k] * w;
        a1 += t[HH + k] * w;
    }
    red[ks][0][n] = a0; red[ks][1][n] = a1;
    __syncthreads();
    if (ks < 2) {
        float s = bias[n0 + n];
        #pragma unroll
        for (int i = 0; i < 8; i++) s += red[i][ks][n];
        g_hid[ks * 4608 + n0 + n] = s / (1.0f + expf(-s));
    }
}
__global__ void __launch_bounds__(1024) temb2_k(
        const float* __restrict__ W, const float* __restrict__ bias) {
    __shared__ float red[8][2][128];
    const int n0 = blockIdx.x * 128;
    const int n = threadIdx.x & 127, ks = threadIdx.x >> 7;
    float a0 = 0.f, a1 = 0.f;
    const int kbeg = ks * 576;
    #pragma unroll 4
    for (int k = kbeg; k < kbeg + 576; k++) {
        float w = W[(size_t)k * 4608 + n0 + n];
        a0 += g_hid[k] * w;
        a1 += g_hid[4608 + k] * w;
    }
    red[ks][0][n] = a0; red[ks][1][n] = a1;
    __syncthreads();
    if (ks < 2) {
        float s = bias[n0 + n];
        #pragma unroll
        for (int i = 0; i < 8; i++) s += red[i][ks][n];
        g_temb[ks * 4608 + n0 + n] = s;
    }
}

// ------------- merged weight transpose + fp16 convert (one launch) ---------
__global__ void wtconv_all(const float* __restrict__ wq, const float* __restrict__ wm1,
                           const float* __restrict__ wm2, const float* __restrict__ wf1,
                           const float* __restrict__ wf2) {
    __shared__ float s[32][33];
    int gid = blockIdx.x;
    const float* W; __half* O; int K, N;
    if (gid < 1728)      { W = wq;  O = g_wqkv; K = 768;  N = 2304; }
    else if (gid < 4032) { W = wm1; O = g_wm1;  K = 768;  N = 3072; gid -= 1728; }
    else if (gid < 6336) { W = wm2; O = g_wm2;  K = 3072; N = 768;  gid -= 4032; }
    else if (gid < 8640) { W = wf1; O = g_wf1;  K = 768;  N = 3072; gid -= 6336; }
    else                 { W = wf2; O = g_wf2;  K = 3072; N = 768;  gid -= 8640; }
    int nx = N >> 5;
    int n0 = (gid % nx) * 32, k0 = (gid / nx) * 32;
    int tx = threadIdx.x, ty = threadIdx.y;
    #pragma unroll
    for (int j = 0; j < 32; j += 8)
        s[ty + j][tx] = W[(size_t)(k0 + ty + j) * N + n0 + tx];
    __syncthreads();
    const int t = ty * 32 + tx;
    #pragma unroll
    for (int it = 0; it < 2; it++) {
        int idx = t + it * 256;
        int r = idx >> 4, kp = idx & 15;
        __half2 hv = __floats2half2_rn(s[2*kp][r], s[2*kp + 1][r]);
        *(__half2*)(O + (size_t)(n0 + r) * K + k0 + 2*kp) = hv;
    }
}

// --------------------------- LayerNorm + modulate --------------------------
__global__ void __launch_bounds__(256) ln_mod_k(
        const float* __restrict__ x,
        const float* __restrict__ lng, const float* __restrict__ lnb,
        int goff, __half* __restrict__ y) {
    const int row = blockIdx.x * 8 + (threadIdx.x >> 5);
    const int lane = threadIdx.x & 31;
    const float4* xr = (const float4*)(x + (size_t)row * HH);
    float4 v[6];
    float s = 0.f, s2 = 0.f;
    #pragma unroll
    for (int j = 0; j < 6; j++) {
        v[j] = xr[lane + j * 32];
        s  += v[j].x + v[j].y + v[j].z + v[j].w;
        s2 += v[j].x*v[j].x + v[j].y*v[j].y + v[j].z*v[j].z + v[j].w*v[j].w;
    }
    #pragma unroll
    for (int o = 16; o; o >>= 1) {
        s  += __shfl_xor_sync(0xffffffffu, s, o);
        s2 += __shfl_xor_sync(0xffffffffu, s2, o);
    }
    const float inv = 1.0f / 768.0f;
    float mu = s * inv;
    float var = s2 * inv - mu * mu;
    float rs = rsqrtf(var + 1e-5f);
    const float4* g4 = (const float4*)lng;
    const float4* b4 = (const float4*)lnb;
    const float* tbb = g_temb + (row >> 11) * 4608 + goff;
    const float4* t4 = (const float4*)tbb;
    const float4* a4 = (const float4*)(tbb + 768);
    #pragma unroll
    for (int j = 0; j < 6; j++) {
        int i = lane + j * 32;
        float4 gg = g4[i], bb = b4[i], tt = t4[i], aa = a4[i];
        float r0 = ((v[j].x - mu) * rs * gg.x + bb.x) * tt.x + aa.x;
        float r1 = ((v[j].y - mu) * rs * gg.y + bb.y) * tt.y + aa.y;
        float r2 = ((v[j].z - mu) * rs * gg.z + bb.z) * tt.z + aa.z;
        float r3 = ((v[j].w - mu) * rs * gg.w + bb.w) * tt.w + aa.w;
        uint2 o2;
        o2.x = pack_h2(r0, r1);
        o2.y = pack_h2(r2, r3);
        *(uint2*)(y + (size_t)row * HH + i * 4) = o2;
    }
}

// ------------------------------ HMMA GEMM (M128) ---------------------------
// EPI: 1=gelu->fp16, 3=qkv->scaled fp16 q/k/v
#define MTILE 16384             // 128 rows * 128B
#define STAGE (2*MTILE)         // 32768
#define GEMM_SMEM (3*STAGE)     // 98304
template <int EPI>
__global__ void __launch_bounds__(256, 2) hgemm_k(
    const __half* __restrict__ A, const __half* __restrict__ Bt,
    const float* __restrict__ bias,
    float* __restrict__ Cf, __half* __restrict__ Ch,
    int N, int K,
    const float* __restrict__ res, int gate_off) {

    extern __shared__ char sm[];
    const uint32_t sbase = smem_u32(sm);
    const int tid = threadIdx.x, lane = tid & 31, wid = tid >> 5;
    const int bm = blockIdx.y, bn = blockIdx.x;
    const int am0 = bm * 128, bn0 = bn * 128;
    const int wm0 = (wid >> 1) * 32, wn0 = (wid & 1) * 64;

    float acc[2][8][4];
    #pragma unroll
    for (int i = 0; i < 2; i++)
        #pragma unroll
        for (int j = 0; j < 8; j++)
            #pragma unroll
            for (int q = 0; q < 4; q++) acc[i][j][q] = 0.f;

    const __half* mats[2] = {A, Bt};
    const __half* srcb[8];
    uint32_t dstb[8];
    #pragma unroll
    for (int it = 0; it < 8; it++) {
        int idx = tid + it * 256;
        int mat = idx >> 10, r = (idx >> 3) & 127, c = idx & 7;
        int grow = (mat == 0 ? am0 : bn0) + r;
        srcb[it] = mats[mat] + (size_t)grow * K + c * 8;
        dstb[it] = sbase + mat * MTILE + swz(r, c);
    }

    uint32_t arowb[2]; int arl[2];
    #pragma unroll
    for (int mi = 0; mi < 2; mi++) {
        int row = wm0 + mi * 16 + (lane & 15);
        arowb[mi] = row * 128; arl[mi] = row & 7;
    }
    const int acol = lane >> 4;
    uint32_t browb[4]; int brl[4];
    #pragma unroll
    for (int ng = 0; ng < 4; ng++) {
        int row = wn0 + ng * 16 + (lane & 7) + ((lane & 16) >> 1);
        browb[ng] = MTILE + row * 128; brl[ng] = row & 7;
    }
    const int bcol = (lane >> 3) & 1;

    const int KB = K >> 6;
    #pragma unroll
    for (int pf = 0; pf < 2; pf++) {
        #pragma unroll
        for (int it = 0; it < 8; it++)
            cpasync16(dstb[it] + pf * STAGE, srcb[it] + pf * 64);
        CP_COMMIT();
    }

    int slot = 0;
    for (int kb = 0; kb < KB; kb++) {
        if (kb + 1 < KB) { CP_WAIT(1); } else { CP_WAIT(0); }
        __syncthreads();
        if (kb + 2 < KB) {
            int wslot = slot + 2; if (wslot >= 3) wslot -= 3;
            const uint32_t so2 = wslot * STAGE;
            const int ko = (kb + 2) << 6;
            #pragma unroll
            for (int it = 0; it < 8; it++) cpasync16(dstb[it] + so2, srcb[it] + ko);
            CP_COMMIT();
        }
        const uint32_t so = sbase + slot * STAGE;
        #pragma unroll
        for (int kc = 0; kc < 4; kc++) {
            uint32_t a[2][4];
            #pragma unroll
            for (int mi = 0; mi < 2; mi++)
                ldsm4(a[mi], so + arowb[mi] + ((((kc*2 + acol) ^ arl[mi]) & 7) << 4));
            uint32_t b[8][2];
            #pragma unroll
            for (int ng = 0; ng < 4; ng++) {
                uint32_t r[4];
                ldsm4(r, so + browb[ng] + ((((kc*2 + bcol) ^ brl[ng]) & 7) << 4));
                b[2*ng][0] = r[0]; b[2*ng][1] = r[1];
                b[2*ng+1][0] = r[2]; b[2*ng+1][1] = r[3];
            }
            #pragma unroll
            for (int mi = 0; mi < 2; mi++)
                #pragma unroll
                for (int ni = 0; ni < 8; ni++)
                    mma16816(acc[mi][ni], a[mi], b[ni]);
        }
        if (++slot == 3) slot = 0;
    }

    const int rbase = am0 + wm0 + (lane >> 2);
    const int cbase = bn0 + wn0 + (lane & 3) * 2;
    #pragma unroll
    for (int mi = 0; mi < 2; mi++) {
        #pragma unroll
        for (int ni = 0; ni < 8; ni++) {
            int col = cbase + ni * 8;
            float2 bb = *(const float2*)&bias[col];
            #pragma unroll
            for (int half2i = 0; half2i < 2; half2i++) {
                int row = rbase + mi * 16 + half2i * 8;
                float v0 = acc[mi][ni][2*half2i]   + bb.x;
                float v1 = acc[mi][ni][2*half2i+1] + bb.y;
                if (EPI == 1) {
                    v0 = 0.5f * v0 * (1.0f + erff(v0 * 0.70710678118654752f));
                    v1 = 0.5f * v1 * (1.0f + erff(v1 * 0.70710678118654752f));
                    *(uint32_t*)(Ch + (size_t)row * N + col) = pack_h2(v0, v1);
                } else if (EPI == 3) {
                    int i3 = col / 768;
                    int rem = col - i3 * 768;
                    int hh = rem >> 6, d = rem & 63;
                    int b2 = row >> 11, t2 = row & 2047;
                    size_t idx = ((size_t)((b2 * NHD + hh) * TT + t2)) * HDD + d;
                    if (i3 == 0) { v0 *= QSCALE; v1 *= QSCALE; }
                    __half* dh = (i3 == 0) ? g_q : (i3 == 1) ? g_k : g_v;
                    *(uint32_t*)(dh + idx) = pack_h2(v0, v1);
                } else {
                    float2 o2; o2.x = v0; o2.y = v1;
                    *(float2*)&Cf[(size_t)row * N + col] = o2;
                }
            }
        }
    }
}

// --------------------- HMMA GEMM (M64, residual+gate) ----------------------
// CTA 64x128, 8 warps of 32x32. grid (N/128, M/64). 3 CTAs/SM.
#define AT64   8192              // 64 rows * 128B
#define STAGE64 (AT64 + MTILE)   // 24576
#define GEMM64_SMEM (3*STAGE64)  // 73728
__global__ void __launch_bounds__(256, 3) hgemm64_k(
    const __half* __restrict__ A, const __half* __restrict__ Bt,
    const float* __restrict__ bias,
    float* __restrict__ Cf,
    int N, int K,
    const float* __restrict__ res, int gate_off) {

    extern __shared__ char sm[];
    const uint32_t sbase = smem_u32(sm);
    const int tid = threadIdx.x, lane = tid & 31, wid = tid >> 5;
    const int bm = blockIdx.y, bn = blockIdx.x;
    const int am0 = bm * 64, bn0 = bn * 128;
    const int wm0 = (wid >> 2) * 32, wn0 = (wid & 3) * 32;

    float acc[2][4][4];
    #pragma unroll
    for (int i = 0; i < 2; i++)
        #pragma unroll
        for (int j = 0; j < 4; j++)
            #pragma unroll
            for (int q = 0; q < 4; q++) acc[i][j][q] = 0.f;

    // cp.async: A 64x8 = 512 chunks, B 128x8 = 1024; total 1536; 6/thread
    const __half* srcb[6];
    uint32_t dstb[6];
    #pragma unroll
    for (int it = 0; it < 6; it++) {
        int idx = tid + it * 256;
        if (idx < 512) {
            int r = idx >> 3, c = idx & 7;
            srcb[it] = A + (size_t)(am0 + r) * K + c * 8;
            dstb[it] = sbase + swz(r, c);
        } else {
            int j = idx - 512;
            int r = j >> 3, c = j & 7;
            srcb[it] = Bt + (size_t)(bn0 + r) * K + c * 8;
            dstb[it] = sbase + AT64 + swz(r, c);
        }
    }

    uint32_t arowb[2]; int arl[2];
    #pragma unroll
    for (int mi = 0; mi < 2; mi++) {
        int row = wm0 + mi * 16 + (lane & 15);
        arowb[mi] = row * 128; arl[mi] = row & 7;
    }
    const int acol = lane >> 4;
    uint32_t browb[2]; int brl[2];
    #pragma unroll
    for (int ng = 0; ng < 2; ng++) {
        int row = wn0 + ng * 16 + (lane & 7) + ((lane & 16) >> 1);
        browb[ng] = AT64 + row * 128; brl[ng] = row & 7;
    }
    const int bcol = (lane >> 3) & 1;

    const int KB = K >> 6;
    #pragma unroll
    for (int pf = 0; pf < 2; pf++) {
        #pragma unroll
        for (int it = 0; it < 6; it++)
            cpasync16(dstb[it] + pf * STAGE64, srcb[it] + pf * 64);
        CP_COMMIT();
    }

    int slot = 0;
    for (int kb = 0; kb < KB; kb++) {
        if (kb + 1 < KB) { CP_WAIT(1); } else { CP_WAIT(0); }
        __syncthreads();
        if (kb + 2 < KB) {
            int wslot = slot + 2; if (wslot >= 3) wslot -= 3;
            const uint32_t so2 = wslot * STAGE64;
            const int ko = (kb + 2) << 6;
            #pragma unroll
            for (int it = 0; it < 6; it++) cpasync16(dstb[it] + so2, srcb[it] + ko);
            CP_COMMIT();
        }
        const uint32_t so = sbase + slot * STAGE64;
        #pragma unroll
        for (int kc = 0; kc < 4; kc++) {
            uint32_t a[2][4];
            #pragma unroll
            for (int mi = 0; mi < 2; mi++)
                ldsm4(a[mi], so + arowb[mi] + ((((kc*2 + acol) ^ arl[mi]) & 7) << 4));
            uint32_t b[4][2];
            #pragma unroll
            for (int ng = 0; ng < 2; ng++) {
                uint32_t r[4];
                ldsm4(r, so + browb[ng] + ((((kc*2 + bcol) ^ brl[ng]) & 7) << 4));
                b[2*ng][0] = r[0]; b[2*ng][1] = r[1];
                b[2*ng+1][0] = r[2]; b[2*ng+1][1] = r[3];
            }
            #pragma unroll
            for (int mi = 0; mi < 2; mi++)
                #pragma unroll
                for (int ni = 0; ni < 4; ni++)
                    mma16816(acc[mi][ni], a[mi], b[ni]);
        }
        if (++slot == 3) slot = 0;
    }

    // epilogue: residual + gate -> fp32
    const int rbase = am0 + wm0 + (lane >> 2);
    const int cbase = bn0 + wn0 + (lane & 3) * 2;
    #pragma unroll
    for (int mi = 0; mi < 2; mi++) {
        #pragma unroll
        for (int ni = 0; ni < 4; ni++) {
            int col = cbase + ni * 8;
            float2 bb = *(const float2*)&bias[col];
            #pragma unroll
            for (int half2i = 0; half2i < 2; half2i++) {
                int row = rbase + mi * 16 + half2i * 8;
                float v0 = acc[mi][ni][2*half2i]   + bb.x;
                float v1 = acc[mi][ni][2*half2i+1] + bb.y;
                const float* tb = g_temb + (row >> 11) * 4608 + gate_off;
                float2 rr = *(const float2*)&res[(size_t)row * N + col];
                float2 gg = *(const float2*)&tb[col];
                v0 = rr.x + gg.x * v0;
                v1 = rr.y + gg.y * v1;
                float2 o2; o2.x = v0; o2.y = v1;
                *(float2*)&Cf[(size_t)row * N + col] = o2;
            }
        }
    }
}

// -------------------- tensor-core flash attention --------------------------
#define QB    16384              // 128 rows * 128B
#define KVST  32768              // K + V
#define ATTN_SMEM (QB + 2*KVST)  // 81920
__global__ void __launch_bounds__(256, 2) attn_tc(void) {
    extern __shared__ char sm[];
    const uint32_t sbase = smem_u32(sm);
    const int tid = threadIdx.x, lane = tid & 31, wid = tid >> 5;
    const int bh = blockIdx.x;
    const int qb = blockIdx.y;
    const size_t headbase = (size_t)bh * TT * HDD;

    const __half* kvmats[2] = {g_k, g_v};

    #pragma unroll
    for (int it = 0; it < 4; it++) {
        int idx = tid + it * 256;
        int r = idx >> 3, c = idx & 7;
        cpasync16(sbase + swz(r, c),
                  g_q + headbase + (size_t)(qb * 128 + r) * HDD + c * 8);
    }
    #pragma unroll
    for (int it = 0; it < 8; it++) {
        int idx = tid + it * 256;
        int mat = idx >> 10, r = (idx >> 3) & 127, c = idx & 7;
        cpasync16(sbase + QB + mat * MTILE + swz(r, c),
                  kvmats[mat] + headbase + (size_t)r * HDD + c * 8);
    }
    CP_COMMIT();

    const int qrow = wid * 16 + (lane & 15);
    const uint32_t qrowb = qrow * 128; const int qrl = qrow & 7;
    const int qcol = lane >> 4;
    int krow[4];
    #pragma unroll
    for (int ng = 0; ng < 4; ng++)
        krow[ng] = ng * 16 + (lane & 7) + ((lane & 16) >> 1);
    const int kcol = (lane >> 3) & 1;
    const int vrowl = (lane & 7) + (lane & 8);
    const int vcol0 = (lane >> 4) & 1;

    uint32_t qh[4][4];
    float o[8][4];
    #pragma unroll
    for (int n = 0; n < 8; n++)
        #pragma unroll
        for (int j = 0; j < 4; j++) o[n][j] = 0.f;
    float m0 = -1e30f, m1 = -1e30f, l0 = 0.f, l1 = 0.f;

    const int NT = TT / 128;   // 16
    for (int t = 0; t < NT; t++) {
        CP_WAIT(0);
        __syncthreads();
        if (t == 0) {
            #pragma unroll
            for (int kc = 0; kc < 4; kc++)
                ldsm4(qh[kc], sbase + qrowb + ((((kc*2 + qcol) ^ qrl) & 7) << 4));
        }
        if (t + 1 < NT) {
            const uint32_t sb2 = sbase + QB + ((t + 1) & 1) * KVST;
            const size_t kvb = headbase + (size_t)(t + 1) * 128 * HDD;
            #pragma unroll
            for (int it = 0; it < 8; it++) {
                int idx = tid + it * 256;
                int mat = idx >> 10, r = (idx >> 3) & 127, c = idx & 7;
                cpasync16(sb2 + mat * MTILE + swz(r, c),
                          kvmats[mat] + kvb + (size_t)r * HDD + c * 8);
            }
            CP_COMMIT();
        }

        const uint32_t stb = sbase + QB + (t & 1) * KVST;
        #pragma unroll
        for (int s = 0; s < 2; s++) {
            const uint32_t kb2 = stb + s * 64 * 128;
            const uint32_t vb2 = stb + MTILE + s * 64 * 128;

            float c[8][4];
            #pragma unroll
            for (int n = 0; n < 8; n++)
                #pragma unroll
                for (int j = 0; j < 4; j++) c[n][j] = 0.f;
            #pragma unroll
            for (int kc = 0; kc < 4; kc++) {
                uint32_t b[8][2];
                #pragma unroll
                for (int ng = 0; ng < 4; ng++) {
                    uint32_t r[4];
                    ldsm4(r, kb2 + krow[ng] * 128
                              + ((((kc*2 + kcol) ^ krow[ng]) & 7) << 4));
                    b[2*ng][0] = r[0]; b[2*ng][1] = r[1];
                    b[2*ng+1][0] = r[2]; b[2*ng+1][1] = r[3];
                }
                #pragma unroll
                for (int n = 0; n < 8; n++) mma16816(c[n], qh[kc], b[n]);
            }

            float mx0 = -1e30f, mx1 = -1e30f;
            #pragma unroll
            for (int n = 0; n < 8; n++) {
                mx0 = fmaxf(mx0, fmaxf(c[n][0], c[n][1]));
                mx1 = fmaxf(mx1, fmaxf(c[n][2], c[n][3]));
            }
            mx0 = fmaxf(mx0, __shfl_xor_sync(0xffffffffu, mx0, 1));
            mx0 = fmaxf(mx0, __shfl_xor_sync(0xffffffffu, mx0, 2));
            mx1 = fmaxf(mx1, __shfl_xor_sync(0xffffffffu, mx1, 1));
            mx1 = fmaxf(mx1, __shfl_xor_sync(0xffffffffu, mx1, 2));
            float mn0 = fmaxf(m0, mx0), mn1 = fmaxf(m1, mx1);
            float cr0 = exp2fast(m0 - mn0), cr1 = exp2fast(m1 - mn1);
            m0 = mn0; m1 = mn1;
            l0 *= cr0; l1 *= cr1;
            #pragma unroll
            for (int n = 0; n < 8; n++) {
                o[n][0] *= cr0; o[n][1] *= cr0;
                o[n][2] *= cr1; o[n][3] *= cr1;
            }
            uint32_t pa[4][4];
            #pragma unroll
            for (int n = 0; n < 8; n++) {
                float p00 = exp2fast(c[n][0] - mn0);
                float p01 = exp2fast(c[n][1] - mn0);
                float p10 = exp2fast(c[n][2] - mn1);
                float p11 = exp2fast(c[n][3] - mn1);
                l0 += p00 + p01; l1 += p10 + p11;
                int kc2 = n >> 1, ss = (n & 1) * 2;
                pa[kc2][ss]     = pack_h2(p00, p01);
                pa[kc2][ss + 1] = pack_h2(p10, p11);
            }

            #pragma unroll
            for (int kc = 0; kc < 4; kc++) {
                uint32_t b[8][2];
                int vrow = vrowl + kc * 16;
                #pragma unroll
                for (int ng = 0; ng < 4; ng++) {
                    uint32_t r[4];
                    ldsm4t(r, vb2 + vrow * 128
                               + ((((ng*2 + vcol0) ^ vrow) & 7) << 4));
                    b[2*ng][0] = r[0]; b[2*ng][1] = r[1];
                    b[2*ng+1][0] = r[2]; b[2*ng+1][1] = r[3];
                }
                #pragma unroll
                for (int n = 0; n < 8; n++) mma16816(o[n], pa[kc], b[n]);
            }
        }
        __syncthreads();
    }

    l0 += __shfl_xor_sync(0xffffffffu, l0, 1);
    l0 += __shfl_xor_sync(0xffffffffu, l0, 2);
    l1 += __shfl_xor_sync(0xffffffffu, l1, 1);
    l1 += __shfl_xor_sync(0xffffffffu, l1, 2);
    float i0 = 1.0f / l0, i1 = 1.0f / l1;

    const int b2 = bh / NHD, h2 = bh % NHD;
    const int r0 = qb * 128 + wid * 16 + (lane >> 2);
    const int cb = h2 * 64 + (lane & 3) * 2;
    #pragma unroll
    for (int n = 0; n < 8; n++) {
        int col = cb + n * 8;
        size_t o0 = (size_t)(b2 * TT + r0) * HH + col;
        *(uint32_t*)(g_o + o0) = pack_h2(o[n][0] * i0, o[n][1] * i0);
        size_t o1 = (size_t)(b2 * TT + r0 + 8) * HH + col;
        *(uint32_t*)(g_o + o1) = pack_h2(o[n][2] * i1, o[n][3] * i1);
    }
}

// ------------------------------- launcher ----------------------------------
extern "C" void kernel_launch(void* const* d_in, const int* in_sizes, int n_in,
                              void* d_out, int out_size) {
    const float* x      = (const float*)d_in[0];
    const float* t      = (const float*)d_in[1];
    const float* w_qkv  = (const float*)d_in[2];
    const float* b_qkv  = (const float*)d_in[3];
    const float* w_m1   = (const float*)d_in[4];
    const float* b_m1   = (const float*)d_in[5];
    const float* w_m2   = (const float*)d_in[6];
    const float* b_m2   = (const float*)d_in[7];
    const float* w_ss1  = (const float*)d_in[8];
    const float* b_ss1  = (const float*)d_in[9];
    const float* w_ss2  = (const float*)d_in[10];
    const float* b_ss2  = (const float*)d_in[11];
    const float* ln1_g  = (const float*)d_in[12];
    const float* ln1_b  = (const float*)d_in[13];
    const float* ln2_g  = (const float*)d_in[14];
    const float* ln2_b  = (const float*)d_in[15];
    const float* w_f1   = (const float*)d_in[16];
    const float* b_f1   = (const float*)d_in[17];
    const float* w_f2   = (const float*)d_in[18];
    const float* b_f2   = (const float*)d_in[19];
    float* out = (float*)d_out;

    float *p_x1;
    __half *p_h, *p_o, *p_u;
    __half *p_wq, *p_wm1, *p_wm2, *p_wf1, *p_wf2;
    cudaGetSymbolAddress((void**)&p_x1,  g_x1);
    cudaGetSymbolAddress((void**)&p_h,   g_h);
    cudaGetSymbolAddress((void**)&p_o,   g_o);
    cudaGetSymbolAddress((void**)&p_u,   g_u);
    cudaGetSymbolAddress((void**)&p_wq,  g_wqkv);
    cudaGetSymbolAddress((void**)&p_wm1, g_wm1);
    cudaGetSymbolAddress((void**)&p_wm2, g_wm2);
    cudaGetSymbolAddress((void**)&p_wf1, g_wf1);
    cudaGetSymbolAddress((void**)&p_wf2, g_wf2);

    cudaFuncSetAttribute(attn_tc, cudaFuncAttributeMaxDynamicSharedMemorySize, ATTN_SMEM);
    cudaFuncSetAttribute(hgemm_k<1>, cudaFuncAttributeMaxDynamicSharedMemorySize, GEMM_SMEM);
    cudaFuncSetAttribute(hgemm_k<3>, cudaFuncAttributeMaxDynamicSharedMemorySize, GEMM_SMEM);
    cudaFuncSetAttribute(hgemm64_k,  cudaFuncAttributeMaxDynamicSharedMemorySize, GEMM64_SMEM);

    wtconv_all<<<10944, dim3(32, 8)>>>(w_qkv, w_m1, w_m2, w_f1, w_f2);

    temb1_k<<<36, 1024>>>(t, w_ss1, b_ss1);
    temb2_k<<<36, 1024>>>(w_ss2, b_ss2);

    ln_mod_k<<<512, 256>>>(x, ln1_g, ln1_b, 0, p_h);

    hgemm_k<3><<<dim3(2304/128, MROWS/128), 256, GEMM_SMEM>>>(
        p_h, p_wq, b_qkv, nullptr, nullptr, 2304, 768, nullptr, 0);

    attn_tc<<<dim3(BB * NHD, TT / 128), 256, ATTN_SMEM>>>();

    hgemm_k<1><<<dim3(3072/128, MROWS/128), 256, GEMM_SMEM>>>(
        p_o, p_wm1, b_m1, nullptr, p_u, 3072, 768, nullptr, 0);

    hgemm64_k<<<dim3(768/128, MROWS/64), 256, GEMM64_SMEM>>>(
        p_u, p_wm2, b_m2, p_x1, 768, 3072, x, 1536);

    ln_mod_k<<<512, 256>>>(p_x1, ln2_g, ln2_b, 2304, p_h);

    hgemm_k<1><<<dim3(3072/128, MROWS/128), 256, GEMM_SMEM>>>(
        p_h, p_wf1, b_f1, nullptr, p_u, 3072, 768, nullptr, 0);

    hgemm64_k<<<dim3(768/128, MROWS/64), 256, GEMM64_SMEM>>>(
        p_u, p_wf2, b_f2, out, 768, 3072, p_x1, 3840);
}

// round 12
// speedup vs baseline: 13.1463x; 1.1385x over previous
#include <cuda_runtime.h>
#include <cuda_fp16.h>
#include <math.h>
#include <stdint.h>

// ---------------------------------------------------------------------------
// DiT block. fp16 mma.sync GEMMs (SW128 swizzle, 3-stage cp.async ring),
// fp16 tensor-core flash attention (128-key stages), FFMA exp2 softmax.
// Split-K temb (full-chip bandwidth), 2-row-per-warp LN.
// B=2, T=2048, H=768, NH=12, HD=64.
// ---------------------------------------------------------------------------

#define HH   768
#define NHD  12
#define HDD  64
#define TT   2048
#define BB   2
#define MROWS (BB*TT)          // 4096

#define QSCALE 0.05205877172640942f   // log2(e)/sqrt(768)

// ------------------------- scratch (static device) -------------------------
__device__ float g_hid [BB*6*HH];
__device__ float g_temb[BB*6*HH];
__device__ float g_x1  [MROWS*HH];
__device__ float g_p1  [4][2*6*HH];    // temb1 partials
__device__ float g_p2  [12][2*6*HH];   // temb2 partials

__device__ __half g_h[MROWS*HH];
__device__ __half g_o[MROWS*HH];
__device__ __half g_u[MROWS*4*HH];

// attention operands, head-major [b][h][T][64]
__device__ __half g_q[MROWS*HH];
__device__ __half g_k[MROWS*HH];
__device__ __half g_v[MROWS*HH];

// transposed fp16 weights  W[K,N] -> Wt[N,K]
__device__ __half g_wqkv[3*HH*HH];
__device__ __half g_wm1 [4*HH*HH];
__device__ __half g_wm2 [HH*4*HH];
__device__ __half g_wf1 [4*HH*HH];
__device__ __half g_wf2 [HH*4*HH];

// ----------------------------- PTX helpers --------------------------------
__device__ __forceinline__ uint32_t smem_u32(const void* p) {
    uint32_t a;
    asm("{ .reg .u64 t; cvta.to.shared.u64 t, %1; cvt.u32.u64 %0, t; }" : "=r"(a) : "l"(p));
    return a;
}
__device__ __forceinline__ void ldsm4(uint32_t* r, uint32_t a) {
    asm volatile("ldmatrix.sync.aligned.m8n8.x4.shared.b16 {%0,%1,%2,%3}, [%4];"
        : "=r"(r[0]), "=r"(r[1]), "=r"(r[2]), "=r"(r[3]) : "r"(a));
}
__device__ __forceinline__ void ldsm4t(uint32_t* r, uint32_t a) {
    asm volatile("ldmatrix.sync.aligned.m8n8.x4.trans.shared.b16 {%0,%1,%2,%3}, [%4];"
        : "=r"(r[0]), "=r"(r[1]), "=r"(r[2]), "=r"(r[3]) : "r"(a));
}
__device__ __forceinline__ void mma16816(float* d, const uint32_t* a, const uint32_t* b) {
    asm volatile("mma.sync.aligned.m16n8k16.row.col.f32.f16.f16.f32 "
        "{%0,%1,%2,%3},{%4,%5,%6,%7},{%8,%9},{%0,%1,%2,%3};"
        : "+f"(d[0]), "+f"(d[1]), "+f"(d[2]), "+f"(d[3])
        : "r"(a[0]), "r"(a[1]), "r"(a[2]), "r"(a[3]), "r"(b[0]), "r"(b[1]));
}
__device__ __forceinline__ void cpasync16(uint32_t dst, const void* src) {
    asm volatile("cp.async.cg.shared.global [%0], [%1], 16;" :: "r"(dst), "l"(src) : "memory");
}
#define CP_COMMIT() asm volatile("cp.async.commit_group;" ::: "memory")
#define CP_WAIT(n)  asm volatile("cp.async.wait_group %0;" :: "n"(n) : "memory")

// SW128 swizzle: 128B rows; colu = 16B unit index 0..7
__device__ __forceinline__ uint32_t swz(uint32_t row, uint32_t colu) {
    return row * 128 + (((colu ^ row) & 7) << 4) + ((colu & ~7u) << 4);
}
__device__ __forceinline__ uint32_t pack_h2(float x, float y) {
    __half2 h = __floats2half2_rn(x, y);
    return *(uint32_t*)&h;
}
// FFMA-pipe exp2 for t <= 0; err ~1e-5
__device__ __forceinline__ float exp2fast(float t) {
    t = fmaxf(t, -126.0f);
    float fi = floorf(t);
    float f = t - fi;
    float p = 1.5435291e-4f;
    p = p * f + 1.3333558e-3f;
    p = p * f + 9.6181291e-3f;
    p = p * f + 5.5504109e-2f;
    p = p * f + 2.4022651e-1f;
    p = p * f + 6.9314718e-1f;
    p = p * f + 1.0f;
    return __int_as_float(((int)fi + 127) << 23) * p;
}

// ------------------------------- temb path --------------------------------
// split-K partial kernels + tiny reduces. block 1024 = 128n x 8ks.
__global__ void __launch_bounds__(1024) temb1p_k(
        const float* __restrict__ t, const float* __restrict__ W) {
    __shared__ float red[8][2][128];
    const int n0 = blockIdx.x * 128, ksl = blockIdx.y;
    const int n = threadIdx.x & 127, ks = threadIdx.x >> 7;
    float a0 = 0.f, a1 = 0.f;
    const int kbeg = ksl * 192 + ks * 24;
    #pragma unroll 4
    for (int k = kbeg; k < kbeg + 24; k++) {
        float w = W[(size_t)k * 4608 + n0 + n];
        a0 += t[k] * w;
        a1 += t[HH + k] * w;
    }
    red[ks][0][n] = a0; red[ks][1][n] = a1;
    __syncthreads();
    if (ks < 2) {
        float s = 0.f;
        #pragma unroll
        for (int i = 0; i < 8; i++) s += red[i][ks][n];
        g_p1[ksl][ks * 4608 + n0 + n] = s;
    }
}
__global__ void temb1r_k(const float* __restrict__ bias) {
    int idx = blockIdx.x * 256 + threadIdx.x;     // 0..9215
    int n = idx % 4608;
    float s = bias[n];
    #pragma unroll
    for (int i = 0; i < 4; i++) s += g_p1[i][idx];
    g_hid[idx] = s / (1.0f + expf(-s));
}
__global__ void __launch_bounds__(1024) temb2p_k(const float* __restrict__ W) {
    __shared__ float red[8][2][128];
    const int n0 = blockIdx.x * 128, ksl = blockIdx.y;
    const int n = threadIdx.x & 127, ks = threadIdx.x >> 7;
    float a0 = 0.f, a1 = 0.f;
    const int kbeg = ksl * 384 + ks * 48;
    #pragma unroll 4
    for (int k = kbeg; k < kbeg + 48; k++) {
        float w = W[(size_t)k * 4608 + n0 + n];
        a0 += g_hid[k] * w;
        a1 += g_hid[4608 + k] * w;
    }
    red[ks][0][n] = a0; red[ks][1][n] = a1;
    __syncthreads();
    if (ks < 2) {
        float s = 0.f;
        #pragma unroll
        for (int i = 0; i < 8; i++) s += red[i][ks][n];
        g_p2[ksl][ks * 4608 + n0 + n] = s;
    }
}
__global__ void temb2r_k(const float* __restrict__ bias) {
    int idx = blockIdx.x * 256 + threadIdx.x;
    int n = idx % 4608;
    float s = bias[n];
    #pragma unroll
    for (int i = 0; i < 12; i++) s += g_p2[i][idx];
    g_temb[idx] = s;
}

// ------------- merged weight transpose + fp16 convert (one launch) ---------
__global__ void wtconv_all(const float* __restrict__ wq, const float* __restrict__ wm1,
                           const float* __restrict__ wm2, const float* __restrict__ wf1,
                           const float* __restrict__ wf2) {
    __shared__ float s[32][33];
    int gid = blockIdx.x;
    const float* W; __half* O; int K, N;
    if (gid < 1728)      { W = wq;  O = g_wqkv; K = 768;  N = 2304; }
    else if (gid < 4032) { W = wm1; O = g_wm1;  K = 768;  N = 3072; gid -= 1728; }
    else if (gid < 6336) { W = wm2; O = g_wm2;  K = 3072; N = 768;  gid -= 4032; }
    else if (gid < 8640) { W = wf1; O = g_wf1;  K = 768;  N = 3072; gid -= 6336; }
    else                 { W = wf2; O = g_wf2;  K = 3072; N = 768;  gid -= 8640; }
    int nx = N >> 5;
    int n0 = (gid % nx) * 32, k0 = (gid / nx) * 32;
    int tx = threadIdx.x, ty = threadIdx.y;
    #pragma unroll
    for (int j = 0; j < 32; j += 8)
        s[ty + j][tx] = W[(size_t)(k0 + ty + j) * N + n0 + tx];
    __syncthreads();
    const int t = ty * 32 + tx;
    #pragma unroll
    for (int it = 0; it < 2; it++) {
        int idx = t + it * 256;
        int r = idx >> 4, kp = idx & 15;
        __half2 hv = __floats2half2_rn(s[2*kp][r], s[2*kp + 1][r]);
        *(__half2*)(O + (size_t)(n0 + r) * K + k0 + 2*kp) = hv;
    }
}

// --------------------------- LayerNorm + modulate --------------------------
// 2 rows per warp; block 256 = 16 rows; grid 256.
__global__ void __launch_bounds__(256) ln_mod_k(
        const float* __restrict__ x,
        const float* __restrict__ lng, const float* __restrict__ lnb,
        int goff, __half* __restrict__ y) {
    const int row0 = blockIdx.x * 16 + (threadIdx.x >> 5) * 2;
    const int lane = threadIdx.x & 31;
    float4 v[2][6];
    float s[2] = {0.f, 0.f}, s2[2] = {0.f, 0.f};
    #pragma unroll
    for (int r = 0; r < 2; r++) {
        const float4* xr = (const float4*)(x + (size_t)(row0 + r) * HH);
        #pragma unroll
        for (int j = 0; j < 6; j++) {
            v[r][j] = xr[lane + j * 32];
            s[r]  += v[r][j].x + v[r][j].y + v[r][j].z + v[r][j].w;
            s2[r] += v[r][j].x*v[r][j].x + v[r][j].y*v[r][j].y
                   + v[r][j].z*v[r][j].z + v[r][j].w*v[r][j].w;
        }
    }
    #pragma unroll
    for (int o = 16; o; o >>= 1) {
        s[0]  += __shfl_xor_sync(0xffffffffu, s[0], o);
        s2[0] += __shfl_xor_sync(0xffffffffu, s2[0], o);
        s[1]  += __shfl_xor_sync(0xffffffffu, s[1], o);
        s2[1] += __shfl_xor_sync(0xffffffffu, s2[1], o);
    }
    const float inv = 1.0f / 768.0f;
    const float4* g4 = (const float4*)lng;
    const float4* b4 = (const float4*)lnb;
    const float* tbb = g_temb + (row0 >> 11) * 4608 + goff;
    const float4* t4 = (const float4*)tbb;
    const float4* a4 = (const float4*)(tbb + 768);
    #pragma unroll
    for (int r = 0; r < 2; r++) {
        float mu = s[r] * inv;
        float var = s2[r] * inv - mu * mu;
        float rs = rsqrtf(var + 1e-5f);
        #pragma unroll
        for (int j = 0; j < 6; j++) {
            int i = lane + j * 32;
            float4 gg = g4[i], bb = b4[i], tt = t4[i], aa = a4[i];
            float r0 = ((v[r][j].x - mu) * rs * gg.x + bb.x) * tt.x + aa.x;
            float r1 = ((v[r][j].y - mu) * rs * gg.y + bb.y) * tt.y + aa.y;
            float r2 = ((v[r][j].z - mu) * rs * gg.z + bb.z) * tt.z + aa.z;
            float r3 = ((v[r][j].w - mu) * rs * gg.w + bb.w) * tt.w + aa.w;
            uint2 o2;
            o2.x = pack_h2(r0, r1);
            o2.y = pack_h2(r2, r3);
            *(uint2*)(y + (size_t)(row0 + r) * HH + i * 4) = o2;
        }
    }
}

// ------------------------------ HMMA GEMM (M128) ---------------------------
// EPI: 1=gelu->fp16, 3=qkv->scaled fp16 q/k/v
#define MTILE 16384             // 128 rows * 128B
#define STAGE (2*MTILE)         // 32768
#define GEMM_SMEM (3*STAGE)     // 98304
template <int EPI>
__global__ void __launch_bounds__(256, 2) hgemm_k(
    const __half* __restrict__ A, const __half* __restrict__ Bt,
    const float* __restrict__ bias,
    float* __restrict__ Cf, __half* __restrict__ Ch,
    int N, int K,
    const float* __restrict__ res, int gate_off) {

    extern __shared__ char sm[];
    const uint32_t sbase = smem_u32(sm);
    const int tid = threadIdx.x, lane = tid & 31, wid = tid >> 5;
    const int bm = blockIdx.y, bn = blockIdx.x;
    const int am0 = bm * 128, bn0 = bn * 128;
    const int wm0 = (wid >> 1) * 32, wn0 = (wid & 1) * 64;

    float acc[2][8][4];
    #pragma unroll
    for (int i = 0; i < 2; i++)
        #pragma unroll
        for (int j = 0; j < 8; j++)
            #pragma unroll
            for (int q = 0; q < 4; q++) acc[i][j][q] = 0.f;

    const __half* mats[2] = {A, Bt};
    const __half* srcb[8];
    uint32_t dstb[8];
    #pragma unroll
    for (int it = 0; it < 8; it++) {
        int idx = tid + it * 256;
        int mat = idx >> 10, r = (idx >> 3) & 127, c = idx & 7;
        int grow = (mat == 0 ? am0 : bn0) + r;
        srcb[it] = mats[mat] + (size_t)grow * K + c * 8;
        dstb[it] = sbase + mat * MTILE + swz(r, c);
    }

    uint32_t arowb[2]; int arl[2];
    #pragma unroll
    for (int mi = 0; mi < 2; mi++) {
        int row = wm0 + mi * 16 + (lane & 15);
        arowb[mi] = row * 128; arl[mi] = row & 7;
    }
    const int acol = lane >> 4;
    uint32_t browb[4]; int brl[4];
    #pragma unroll
    for (int ng = 0; ng < 4; ng++) {
        int row = wn0 + ng * 16 + (lane & 7) + ((lane & 16) >> 1);
        browb[ng] = MTILE + row * 128; brl[ng] = row & 7;
    }
    const int bcol = (lane >> 3) & 1;

    const int KB = K >> 6;
    #pragma unroll
    for (int pf = 0; pf < 2; pf++) {
        #pragma unroll
        for (int it = 0; it < 8; it++)
            cpasync16(dstb[it] + pf * STAGE, srcb[it] + pf * 64);
        CP_COMMIT();
    }

    int slot = 0;
    for (int kb = 0; kb < KB; kb++) {
        if (kb + 1 < KB) { CP_WAIT(1); } else { CP_WAIT(0); }
        __syncthreads();
        if (kb + 2 < KB) {
            int wslot = slot + 2; if (wslot >= 3) wslot -= 3;
            const uint32_t so2 = wslot * STAGE;
            const int ko = (kb + 2) << 6;
            #pragma unroll
            for (int it = 0; it < 8; it++) cpasync16(dstb[it] + so2, srcb[it] + ko);
            CP_COMMIT();
        }
        const uint32_t so = sbase + slot * STAGE;
        #pragma unroll
        for (int kc = 0; kc < 4; kc++) {
            uint32_t a[2][4];
            #pragma unroll
            for (int mi = 0; mi < 2; mi++)
                ldsm4(a[mi], so + arowb[mi] + ((((kc*2 + acol) ^ arl[mi]) & 7) << 4));
            uint32_t b[8][2];
            #pragma unroll
            for (int ng = 0; ng < 4; ng++) {
                uint32_t r[4];
                ldsm4(r, so + browb[ng] + ((((kc*2 + bcol) ^ brl[ng]) & 7) << 4));
                b[2*ng][0] = r[0]; b[2*ng][1] = r[1];
                b[2*ng+1][0] = r[2]; b[2*ng+1][1] = r[3];
            }
            #pragma unroll
            for (int mi = 0; mi < 2; mi++)
                #pragma unroll
                for (int ni = 0; ni < 8; ni++)
                    mma16816(acc[mi][ni], a[mi], b[ni]);
        }
        if (++slot == 3) slot = 0;
    }

    const int rbase = am0 + wm0 + (lane >> 2);
    const int cbase = bn0 + wn0 + (lane & 3) * 2;
    #pragma unroll
    for (int mi = 0; mi < 2; mi++) {
        #pragma unroll
        for (int ni = 0; ni < 8; ni++) {
            int col = cbase + ni * 8;
            float2 bb = *(const float2*)&bias[col];
            #pragma unroll
            for (int half2i = 0; half2i < 2; half2i++) {
                int row = rbase + mi * 16 + half2i * 8;
                float v0 = acc[mi][ni][2*half2i]   + bb.x;
                float v1 = acc[mi][ni][2*half2i+1] + bb.y;
                if (EPI == 1) {
                    v0 = 0.5f * v0 * (1.0f + erff(v0 * 0.70710678118654752f));
                    v1 = 0.5f * v1 * (1.0f + erff(v1 * 0.70710678118654752f));
                    *(uint32_t*)(Ch + (size_t)row * N + col) = pack_h2(v0, v1);
                } else if (EPI == 3) {
                    int i3 = col / 768;
                    int rem = col - i3 * 768;
                    int hh = rem >> 6, d = rem & 63;
                    int b2 = row >> 11, t2 = row & 2047;
                    size_t idx = ((size_t)((b2 * NHD + hh) * TT + t2)) * HDD + d;
                    if (i3 == 0) { v0 *= QSCALE; v1 *= QSCALE; }
                    __half* dh = (i3 == 0) ? g_q : (i3 == 1) ? g_k : g_v;
                    *(uint32_t*)(dh + idx) = pack_h2(v0, v1);
                } else {
                    float2 o2; o2.x = v0; o2.y = v1;
                    *(float2*)&Cf[(size_t)row * N + col] = o2;
                }
            }
        }
    }
}

// --------------------- HMMA GEMM (M64, residual+gate) ----------------------
#define AT64   8192              // 64 rows * 128B
#define STAGE64 (AT64 + MTILE)   // 24576
#define GEMM64_SMEM (3*STAGE64)  // 73728
__global__ void __launch_bounds__(256, 3) hgemm64_k(
    const __half* __restrict__ A, const __half* __restrict__ Bt,
    const float* __restrict__ bias,
    float* __restrict__ Cf,
    int N, int K,
    const float* __restrict__ res, int gate_off) {

    extern __shared__ char sm[];
    const uint32_t sbase = smem_u32(sm);
    const int tid = threadIdx.x, lane = tid & 31, wid = tid >> 5;
    const int bm = blockIdx.y, bn = blockIdx.x;
    const int am0 = bm * 64, bn0 = bn * 128;
    const int wm0 = (wid >> 2) * 32, wn0 = (wid & 3) * 32;

    float acc[2][4][4];
    #pragma unroll
    for (int i = 0; i < 2; i++)
        #pragma unroll
        for (int j = 0; j < 4; j++)
            #pragma unroll
            for (int q = 0; q < 4; q++) acc[i][j][q] = 0.f;

    const __half* srcb[6];
    uint32_t dstb[6];
    #pragma unroll
    for (int it = 0; it < 6; it++) {
        int idx = tid + it * 256;
        if (idx < 512) {
            int r = idx >> 3, c = idx & 7;
            srcb[it] = A + (size_t)(am0 + r) * K + c * 8;
            dstb[it] = sbase + swz(r, c);
        } else {
            int j = idx - 512;
            int r = j >> 3, c = j & 7;
            srcb[it] = Bt + (size_t)(bn0 + r) * K + c * 8;
            dstb[it] = sbase + AT64 + swz(r, c);
        }
    }

    uint32_t arowb[2]; int arl[2];
    #pragma unroll
    for (int mi = 0; mi < 2; mi++) {
        int row = wm0 + mi * 16 + (lane & 15);
        arowb[mi] = row * 128; arl[mi] = row & 7;
    }
    const int acol = lane >> 4;
    uint32_t browb[2]; int brl[2];
    #pragma unroll
    for (int ng = 0; ng < 2; ng++) {
        int row = wn0 + ng * 16 + (lane & 7) + ((lane & 16) >> 1);
        browb[ng] = AT64 + row * 128; brl[ng] = row & 7;
    }
    const int bcol = (lane >> 3) & 1;

    const int KB = K >> 6;
    #pragma unroll
    for (int pf = 0; pf < 2; pf++) {
        #pragma unroll
        for (int it = 0; it < 6; it++)
            cpasync16(dstb[it] + pf * STAGE64, srcb[it] + pf * 64);
        CP_COMMIT();
    }

    int slot = 0;
    for (int kb = 0; kb < KB; kb++) {
        if (kb + 1 < KB) { CP_WAIT(1); } else { CP_WAIT(0); }
        __syncthreads();
        if (kb + 2 < KB) {
            int wslot = slot + 2; if (wslot >= 3) wslot -= 3;
            const uint32_t so2 = wslot * STAGE64;
            const int ko = (kb + 2) << 6;
            #pragma unroll
            for (int it = 0; it < 6; it++) cpasync16(dstb[it] + so2, srcb[it] + ko);
            CP_COMMIT();
        }
        const uint32_t so = sbase + slot * STAGE64;
        #pragma unroll
        for (int kc = 0; kc < 4; kc++) {
            uint32_t a[2][4];
            #pragma unroll
            for (int mi = 0; mi < 2; mi++)
                ldsm4(a[mi], so + arowb[mi] + ((((kc*2 + acol) ^ arl[mi]) & 7) << 4));
            uint32_t b[4][2];
            #pragma unroll
            for (int ng = 0; ng < 2; ng++) {
                uint32_t r[4];
                ldsm4(r, so + browb[ng] + ((((kc*2 + bcol) ^ brl[ng]) & 7) << 4));
                b[2*ng][0] = r[0]; b[2*ng][1] = r[1];
                b[2*ng+1][0] = r[2]; b[2*ng+1][1] = r[3];
            }
            #pragma unroll
            for (int mi = 0; mi < 2; mi++)
                #pragma unroll
                for (int ni = 0; ni < 4; ni++)
                    mma16816(acc[mi][ni], a[mi], b[ni]);
        }
        if (++slot == 3) slot = 0;
    }

    const int rbase = am0 + wm0 + (lane >> 2);
    const int cbase = bn0 + wn0 + (lane & 3) * 2;
    #pragma unroll
    for (int mi = 0; mi < 2; mi++) {
        #pragma unroll
        for (int ni = 0; ni < 4; ni++) {
            int col = cbase + ni * 8;
            float2 bb = *(const float2*)&bias[col];
            #pragma unroll
            for (int half2i = 0; half2i < 2; half2i++) {
                int row = rbase + mi * 16 + half2i * 8;
                float v0 = acc[mi][ni][2*half2i]   + bb.x;
                float v1 = acc[mi][ni][2*half2i+1] + bb.y;
                const float* tb = g_temb + (row >> 11) * 4608 + gate_off;
                float2 rr = *(const float2*)&res[(size_t)row * N + col];
                float2 gg = *(const float2*)&tb[col];
                v0 = rr.x + gg.x * v0;
                v1 = rr.y + gg.y * v1;
                float2 o2; o2.x = v0; o2.y = v1;
                *(float2*)&Cf[(size_t)row * N + col] = o2;
            }
        }
    }
}

// -------------------- tensor-core flash attention --------------------------
#define QB    16384              // 128 rows * 128B
#define KVST  32768              // K + V
#define ATTN_SMEM (QB + 2*KVST)  // 81920
__global__ void __launch_bounds__(256, 2) attn_tc(void) {
    extern __shared__ char sm[];
    const uint32_t sbase = smem_u32(sm);
    const int tid = threadIdx.x, lane = tid & 31, wid = tid >> 5;
    const int bh = blockIdx.x;
    const int qb = blockIdx.y;
    const size_t headbase = (size_t)bh * TT * HDD;

    const __half* kvmats[2] = {g_k, g_v};

    #pragma unroll
    for (int it = 0; it < 4; it++) {
        int idx = tid + it * 256;
        int r = idx >> 3, c = idx & 7;
        cpasync16(sbase + swz(r, c),
                  g_q + headbase + (size_t)(qb * 128 + r) * HDD + c * 8);
    }
    #pragma unroll
    for (int it = 0; it < 8; it++) {
        int idx = tid + it * 256;
        int mat = idx >> 10, r = (idx >> 3) & 127, c = idx & 7;
        cpasync16(sbase + QB + mat * MTILE + swz(r, c),
                  kvmats[mat] + headbase + (size_t)r * HDD + c * 8);
    }
    CP_COMMIT();

    const int qrow = wid * 16 + (lane & 15);
    const uint32_t qrowb = qrow * 128; const int qrl = qrow & 7;
    const int qcol = lane >> 4;
    int krow[4];
    #pragma unroll
    for (int ng = 0; ng < 4; ng++)
        krow[ng] = ng * 16 + (lane & 7) + ((lane & 16) >> 1);
    const int kcol = (lane >> 3) & 1;
    const int vrowl = (lane & 7) + (lane & 8);
    const int vcol0 = (lane >> 4) & 1;

    uint32_t qh[4][4];
    float o[8][4];
    #pragma unroll
    for (int n = 0; n < 8; n++)
        #pragma unroll
        for (int j = 0; j < 4; j++) o[n][j] = 0.f;
    float m0 = -1e30f, m1 = -1e30f, l0 = 0.f, l1 = 0.f;

    const int NT = TT / 128;   // 16
    for (int t = 0; t < NT; t++) {
        CP_WAIT(0);
        __syncthreads();
        if (t == 0) {
            #pragma unroll
            for (int kc = 0; kc < 4; kc++)
                ldsm4(qh[kc], sbase + qrowb + ((((kc*2 + qcol) ^ qrl) & 7) << 4));
        }
        if (t + 1 < NT) {
            const uint32_t sb2 = sbase + QB + ((t + 1) & 1) * KVST;
            const size_t kvb = headbase + (size_t)(t + 1) * 128 * HDD;
            #pragma unroll
            for (int it = 0; it < 8; it++) {
                int idx = tid + it * 256;
                int mat = idx >> 10, r = (idx >> 3) & 127, c = idx & 7;
                cpasync16(sb2 + mat * MTILE + swz(r, c),
                          kvmats[mat] + kvb + (size_t)r * HDD + c * 8);
            }
            CP_COMMIT();
        }

        const uint32_t stb = sbase + QB + (t & 1) * KVST;
        #pragma unroll
        for (int s = 0; s < 2; s++) {
            const uint32_t kb2 = stb + s * 64 * 128;
            const uint32_t vb2 = stb + MTILE + s * 64 * 128;

            float c[8][4];
            #pragma unroll
            for (int n = 0; n < 8; n++)
                #pragma unroll
                for (int j = 0; j < 4; j++) c[n][j] = 0.f;
            #pragma unroll
            for (int kc = 0; kc < 4; kc++) {
                uint32_t b[8][2];
                #pragma unroll
                for (int ng = 0; ng < 4; ng++) {
                    uint32_t r[4];
                    ldsm4(r, kb2 + krow[ng] * 128
                              + ((((kc*2 + kcol) ^ krow[ng]) & 7) << 4));
                    b[2*ng][0] = r[0]; b[2*ng][1] = r[1];
                    b[2*ng+1][0] = r[2]; b[2*ng+1][1] = r[3];
                }
                #pragma unroll
                for (int n = 0; n < 8; n++) mma16816(c[n], qh[kc], b[n]);
            }

            float mx0 = -1e30f, mx1 = -1e30f;
            #pragma unroll
            for (int n = 0; n < 8; n++) {
                mx0 = fmaxf(mx0, fmaxf(c[n][0], c[n][1]));
                mx1 = fmaxf(mx1, fmaxf(c[n][2], c[n][3]));
            }
            mx0 = fmaxf(mx0, __shfl_xor_sync(0xffffffffu, mx0, 1));
            mx0 = fmaxf(mx0, __shfl_xor_sync(0xffffffffu, mx0, 2));
            mx1 = fmaxf(mx1, __shfl_xor_sync(0xffffffffu, mx1, 1));
            mx1 = fmaxf(mx1, __shfl_xor_sync(0xffffffffu, mx1, 2));
            float mn0 = fmaxf(m0, mx0), mn1 = fmaxf(m1, mx1);
            float cr0 = exp2fast(m0 - mn0), cr1 = exp2fast(m1 - mn1);
            m0 = mn0; m1 = mn1;
            l0 *= cr0; l1 *= cr1;
            #pragma unroll
            for (int n = 0; n < 8; n++) {
                o[n][0] *= cr0; o[n][1] *= cr0;
                o[n][2] *= cr1; o[n][3] *= cr1;
            }
            uint32_t pa[4][4];
            #pragma unroll
            for (int n = 0; n < 8; n++) {
                float p00 = exp2fast(c[n][0] - mn0);
                float p01 = exp2fast(c[n][1] - mn0);
                float p10 = exp2fast(c[n][2] - mn1);
                float p11 = exp2fast(c[n][3] - mn1);
                l0 += p00 + p01; l1 += p10 + p11;
                int kc2 = n >> 1, ss = (n & 1) * 2;
                pa[kc2][ss]     = pack_h2(p00, p01);
                pa[kc2][ss + 1] = pack_h2(p10, p11);
            }

            #pragma unroll
            for (int kc = 0; kc < 4; kc++) {
                uint32_t b[8][2];
                int vrow = vrowl + kc * 16;
                #pragma unroll
                for (int ng = 0; ng < 4; ng++) {
                    uint32_t r[4];
                    ldsm4t(r, vb2 + vrow * 128
                               + ((((ng*2 + vcol0) ^ vrow) & 7) << 4));
                    b[2*ng][0] = r[0]; b[2*ng][1] = r[1];
                    b[2*ng+1][0] = r[2]; b[2*ng+1][1] = r[3];
                }
                #pragma unroll
                for (int n = 0; n < 8; n++) mma16816(o[n], pa[kc], b[n]);
            }
        }
        __syncthreads();
    }

    l0 += __shfl_xor_sync(0xffffffffu, l0, 1);
    l0 += __shfl_xor_sync(0xffffffffu, l0, 2);
    l1 += __shfl_xor_sync(0xffffffffu, l1, 1);
    l1 += __shfl_xor_sync(0xffffffffu, l1, 2);
    float i0 = 1.0f / l0, i1 = 1.0f / l1;

    const int b2 = bh / NHD, h2 = bh % NHD;
    const int r0 = qb * 128 + wid * 16 + (lane >> 2);
    const int cb = h2 * 64 + (lane & 3) * 2;
    #pragma unroll
    for (int n = 0; n < 8; n++) {
        int col = cb + n * 8;
        size_t o0 = (size_t)(b2 * TT + r0) * HH + col;
        *(uint32_t*)(g_o + o0) = pack_h2(o[n][0] * i0, o[n][1] * i0);
        size_t o1 = (size_t)(b2 * TT + r0 + 8) * HH + col;
        *(uint32_t*)(g_o + o1) = pack_h2(o[n][2] * i1, o[n][3] * i1);
    }
}

// ------------------------------- launcher ----------------------------------
extern "C" void kernel_launch(void* const* d_in, const int* in_sizes, int n_in,
                              void* d_out, int out_size) {
    const float* x      = (const float*)d_in[0];
    const float* t      = (const float*)d_in[1];
    const float* w_qkv  = (const float*)d_in[2];
    const float* b_qkv  = (const float*)d_in[3];
    const float* w_m1   = (const float*)d_in[4];
    const float* b_m1   = (const float*)d_in[5];
    const float* w_m2   = (const float*)d_in[6];
    const float* b_m2   = (const float*)d_in[7];
    const float* w_ss1  = (const float*)d_in[8];
    const float* b_ss1  = (const float*)d_in[9];
    const float* w_ss2  = (const float*)d_in[10];
    const float* b_ss2  = (const float*)d_in[11];
    const float* ln1_g  = (const float*)d_in[12];
    const float* ln1_b  = (const float*)d_in[13];
    const float* ln2_g  = (const float*)d_in[14];
    const float* ln2_b  = (const float*)d_in[15];
    const float* w_f1   = (const float*)d_in[16];
    const float* b_f1   = (const float*)d_in[17];
    const float* w_f2   = (const float*)d_in[18];
    const float* b_f2   = (const float*)d_in[19];
    float* out = (float*)d_out;

    float *p_x1;
    __half *p_h, *p_o, *p_u;
    __half *p_wq, *p_wm1, *p_wm2, *p_wf1, *p_wf2;
    cudaGetSymbolAddress((void**)&p_x1,  g_x1);
    cudaGetSymbolAddress((void**)&p_h,   g_h);
    cudaGetSymbolAddress((void**)&p_o,   g_o);
    cudaGetSymbolAddress((void**)&p_u,   g_u);
    cudaGetSymbolAddress((void**)&p_wq,  g_wqkv);
    cudaGetSymbolAddress((void**)&p_wm1, g_wm1);
    cudaGetSymbolAddress((void**)&p_wm2, g_wm2);
    cudaGetSymbolAddress((void**)&p_wf1, g_wf1);
    cudaGetSymbolAddress((void**)&p_wf2, g_wf2);

    cudaFuncSetAttribute(attn_tc, cudaFuncAttributeMaxDynamicSharedMemorySize, ATTN_SMEM);
    cudaFuncSetAttribute(hgemm_k<1>, cudaFuncAttributeMaxDynamicSharedMemorySize, GEMM_SMEM);
    cudaFuncSetAttribute(hgemm_k<3>, cudaFuncAttributeMaxDynamicSharedMemorySize, GEMM_SMEM);
    cudaFuncSetAttribute(hgemm64_k,  cudaFuncAttributeMaxDynamicSharedMemorySize, GEMM64_SMEM);

    wtconv_all<<<10944, dim3(32, 8)>>>(w_qkv, w_m1, w_m2, w_f1, w_f2);

    temb1p_k<<<dim3(36, 4), 1024>>>(t, w_ss1);
    temb1r_k<<<36, 256>>>(b_ss1);
    temb2p_k<<<dim3(36, 12), 1024>>>(w_ss2);
    temb2r_k<<<36, 256>>>(b_ss2);

    ln_mod_k<<<256, 256>>>(x, ln1_g, ln1_b, 0, p_h);

    hgemm_k<3><<<dim3(2304/128, MROWS/128), 256, GEMM_SMEM>>>(
        p_h, p_wq, b_qkv, nullptr, nullptr, 2304, 768, nullptr, 0);

    attn_tc<<<dim3(BB * NHD, TT / 128), 256, ATTN_SMEM>>>();

    hgemm_k<1><<<dim3(3072/128, MROWS/128), 256, GEMM_SMEM>>>(
        p_o, p_wm1, b_m1, nullptr, p_u, 3072, 768, nullptr, 0);

    hgemm64_k<<<dim3(768/128, MROWS/64), 256, GEMM64_SMEM>>>(
        p_u, p_wm2, b_m2, p_x1, 768, 3072, x, 1536);

    ln_mod_k<<<256, 256>>>(p_x1, ln2_g, ln2_b, 2304, p_h);

    hgemm_k<1><<<dim3(3072/128, MROWS/128), 256, GEMM_SMEM>>>(
        p_h, p_wf1, b_f1, nullptr, p_u, 3072, 768, nullptr, 0);

    hgemm64_k<<<dim3(768/128, MROWS/64), 256, GEMM64_SMEM>>>(
        p_u, p_wf2, b_f2, out, 768, 3072, p_x1, 3840);
}

// round 13
// speedup vs baseline: 13.1596x; 1.0010x over previous
#include <cuda_runtime.h>
#include <cuda_fp16.h>
#include <math.h>
#include <stdint.h>

// ---------------------------------------------------------------------------
// DiT block. fp16 mma.sync GEMMs (SW128 swizzle, 3-stage cp.async ring),
// fp16 tensor-core flash attention (128-key stages), FFMA exp2 softmax.
// Split-K temb; weight conversion overlapped on a side stream.
// B=2, T=2048, H=768, NH=12, HD=64.
// ---------------------------------------------------------------------------

#define HH   768
#define NHD  12
#define HDD  64
#define TT   2048
#define BB   2
#define MROWS (BB*TT)          // 4096

#define QSCALE 0.05205877172640942f   // log2(e)/sqrt(768)

// ------------------------- scratch (static device) -------------------------
__device__ float g_hid [BB*6*HH];
__device__ float g_temb[BB*6*HH];
__device__ float g_x1  [MROWS*HH];
__device__ float g_p1  [4][2*6*HH];    // temb1 partials
__device__ float g_p2  [12][2*6*HH];   // temb2 partials

__device__ __half g_h[MROWS*HH];
__device__ __half g_o[MROWS*HH];
__device__ __half g_u[MROWS*4*HH];

// attention operands, head-major [b][h][T][64]
__device__ __half g_q[MROWS*HH];
__device__ __half g_k[MROWS*HH];
__device__ __half g_v[MROWS*HH];

// transposed fp16 weights  W[K,N] -> Wt[N,K]
__device__ __half g_wqkv[3*HH*HH];
__device__ __half g_wm1 [4*HH*HH];
__device__ __half g_wm2 [HH*4*HH];
__device__ __half g_wf1 [4*HH*HH];
__device__ __half g_wf2 [HH*4*HH];

// ----------------------------- PTX helpers --------------------------------
__device__ __forceinline__ uint32_t smem_u32(const void* p) {
    uint32_t a;
    asm("{ .reg .u64 t; cvta.to.shared.u64 t, %1; cvt.u32.u64 %0, t; }" : "=r"(a) : "l"(p));
    return a;
}
__device__ __forceinline__ void ldsm4(uint32_t* r, uint32_t a) {
    asm volatile("ldmatrix.sync.aligned.m8n8.x4.shared.b16 {%0,%1,%2,%3}, [%4];"
        : "=r"(r[0]), "=r"(r[1]), "=r"(r[2]), "=r"(r[3]) : "r"(a));
}
__device__ __forceinline__ void ldsm4t(uint32_t* r, uint32_t a) {
    asm volatile("ldmatrix.sync.aligned.m8n8.x4.trans.shared.b16 {%0,%1,%2,%3}, [%4];"
        : "=r"(r[0]), "=r"(r[1]), "=r"(r[2]), "=r"(r[3]) : "r"(a));
}
__device__ __forceinline__ void mma16816(float* d, const uint32_t* a, const uint32_t* b) {
    asm volatile("mma.sync.aligned.m16n8k16.row.col.f32.f16.f16.f32 "
        "{%0,%1,%2,%3},{%4,%5,%6,%7},{%8,%9},{%0,%1,%2,%3};"
        : "+f"(d[0]), "+f"(d[1]), "+f"(d[2]), "+f"(d[3])
        : "r"(a[0]), "r"(a[1]), "r"(a[2]), "r"(a[3]), "r"(b[0]), "r"(b[1]));
}
__device__ __forceinline__ void cpasync16(uint32_t dst, const void* src) {
    asm volatile("cp.async.cg.shared.global [%0], [%1], 16;" :: "r"(dst), "l"(src) : "memory");
}
#define CP_COMMIT() asm volatile("cp.async.commit_group;" ::: "memory")
#define CP_WAIT(n)  asm volatile("cp.async.wait_group %0;" :: "n"(n) : "memory")

// SW128 swizzle: 128B rows; colu = 16B unit index 0..7
__device__ __forceinline__ uint32_t swz(uint32_t row, uint32_t colu) {
    return row * 128 + (((colu ^ row) & 7) << 4) + ((colu & ~7u) << 4);
}
__device__ __forceinline__ uint32_t pack_h2(float x, float y) {
    __half2 h = __floats2half2_rn(x, y);
    return *(uint32_t*)&h;
}
// FFMA-pipe exp2 for t <= 0; err ~1e-5
__device__ __forceinline__ float exp2fast(float t) {
    t = fmaxf(t, -126.0f);
    float fi = floorf(t);
    float f = t - fi;
    float p = 1.5435291e-4f;
    p = p * f + 1.3333558e-3f;
    p = p * f + 9.6181291e-3f;
    p = p * f + 5.5504109e-2f;
    p = p * f + 2.4022651e-1f;
    p = p * f + 6.9314718e-1f;
    p = p * f + 1.0f;
    return __int_as_float(((int)fi + 127) << 23) * p;
}

// ------------------------------- temb path --------------------------------
__global__ void __launch_bounds__(1024) temb1p_k(
        const float* __restrict__ t, const float* __restrict__ W) {
    __shared__ float red[8][2][128];
    const int n0 = blockIdx.x * 128, ksl = blockIdx.y;
    const int n = threadIdx.x & 127, ks = threadIdx.x >> 7;
    float a0 = 0.f, a1 = 0.f;
    const int kbeg = ksl * 192 + ks * 24;
    #pragma unroll 4
    for (int k = kbeg; k < kbeg + 24; k++) {
        float w = W[(size_t)k * 4608 + n0 + n];
        a0 += t[k] * w;
        a1 += t[HH + k] * w;
    }
    red[ks][0][n] = a0; red[ks][1][n] = a1;
    __syncthreads();
    if (ks < 2) {
        float s = 0.f;
        #pragma unroll
        for (int i = 0; i < 8; i++) s += red[i][ks][n];
        g_p1[ksl][ks * 4608 + n0 + n] = s;
    }
}
__global__ void temb1r_k(const float* __restrict__ bias) {
    int idx = blockIdx.x * 256 + threadIdx.x;
    int n = idx % 4608;
    float s = bias[n];
    #pragma unroll
    for (int i = 0; i < 4; i++) s += g_p1[i][idx];
    g_hid[idx] = s / (1.0f + expf(-s));
}
__global__ void __launch_bounds__(1024) temb2p_k(const float* __restrict__ W) {
    __shared__ float red[8][2][128];
    const int n0 = blockIdx.x * 128, ksl = blockIdx.y;
    const int n = threadIdx.x & 127, ks = threadIdx.x >> 7;
    float a0 = 0.f, a1 = 0.f;
    const int kbeg = ksl * 384 + ks * 48;
    #pragma unroll 4
    for (int k = kbeg; k < kbeg + 48; k++) {
        float w = W[(size_t)k * 4608 + n0 + n];
        a0 += g_hid[k] * w;
        a1 += g_hid[4608 + k] * w;
    }
    red[ks][0][n] = a0; red[ks][1][n] = a1;
    __syncthreads();
    if (ks < 2) {
        float s = 0.f;
        #pragma unroll
        for (int i = 0; i < 8; i++) s += red[i][ks][n];
        g_p2[ksl][ks * 4608 + n0 + n] = s;
    }
}
__global__ void temb2r_k(const float* __restrict__ bias) {
    int idx = blockIdx.x * 256 + threadIdx.x;
    int n = idx % 4608;
    float s = bias[n];
    #pragma unroll
    for (int i = 0; i < 12; i++) s += g_p2[i][idx];
    g_temb[idx] = s;
}

// ----------------- weight transpose + fp16 convert (split) -----------------
__device__ __forceinline__ void wtconv_tile(const float* W, __half* O,
                                            int K, int N, int gid) {
    __shared__ float s[32][33];
    int nx = N >> 5;
    int n0 = (gid % nx) * 32, k0 = (gid / nx) * 32;
    int tx = threadIdx.x, ty = threadIdx.y;
    #pragma unroll
    for (int j = 0; j < 32; j += 8)
        s[ty + j][tx] = W[(size_t)(k0 + ty + j) * N + n0 + tx];
    __syncthreads();
    const int t = ty * 32 + tx;
    #pragma unroll
    for (int it = 0; it < 2; it++) {
        int idx = t + it * 256;
        int r = idx >> 4, kp = idx & 15;
        __half2 hv = __floats2half2_rn(s[2*kp][r], s[2*kp + 1][r]);
        *(__half2*)(O + (size_t)(n0 + r) * K + k0 + 2*kp) = hv;
    }
}
// qkv only: 1728 tiles
__global__ void wtconv_qkv(const float* __restrict__ wq) {
    wtconv_tile(wq, g_wqkv, 768, 2304, blockIdx.x);
}
// remaining 4 weights: 9216 tiles
__global__ void wtconv_rest(const float* __restrict__ wm1, const float* __restrict__ wm2,
                            const float* __restrict__ wf1, const float* __restrict__ wf2) {
    int gid = blockIdx.x;
    if (gid < 2304)      wtconv_tile(wm1, g_wm1, 768,  3072, gid);
    else if (gid < 4608) wtconv_tile(wm2, g_wm2, 3072, 768,  gid - 2304);
    else if (gid < 6912) wtconv_tile(wf1, g_wf1, 768,  3072, gid - 4608);
    else                 wtconv_tile(wf2, g_wf2, 3072, 768,  gid - 6912);
}

// --------------------------- LayerNorm + modulate --------------------------
// 2 rows per warp; block 256 = 16 rows; grid 256.
__global__ void __launch_bounds__(256) ln_mod_k(
        const float* __restrict__ x,
        const float* __restrict__ lng, const float* __restrict__ lnb,
        int goff, __half* __restrict__ y) {
    const int row0 = blockIdx.x * 16 + (threadIdx.x >> 5) * 2;
    const int lane = threadIdx.x & 31;
    float4 v[2][6];
    float s[2] = {0.f, 0.f}, s2[2] = {0.f, 0.f};
    #pragma unroll
    for (int r = 0; r < 2; r++) {
        const float4* xr = (const float4*)(x + (size_t)(row0 + r) * HH);
        #pragma unroll
        for (int j = 0; j < 6; j++) {
            v[r][j] = xr[lane + j * 32];
            s[r]  += v[r][j].x + v[r][j].y + v[r][j].z + v[r][j].w;
            s2[r] += v[r][j].x*v[r][j].x + v[r][j].y*v[r][j].y
                   + v[r][j].z*v[r][j].z + v[r][j].w*v[r][j].w;
        }
    }
    #pragma unroll
    for (int o = 16; o; o >>= 1) {
        s[0]  += __shfl_xor_sync(0xffffffffu, s[0], o);
        s2[0] += __shfl_xor_sync(0xffffffffu, s2[0], o);
        s[1]  += __shfl_xor_sync(0xffffffffu, s[1], o);
        s2[1] += __shfl_xor_sync(0xffffffffu, s2[1], o);
    }
    const float inv = 1.0f / 768.0f;
    const float4* g4 = (const float4*)lng;
    const float4* b4 = (const float4*)lnb;
    const float* tbb = g_temb + (row0 >> 11) * 4608 + goff;
    const float4* t4 = (const float4*)tbb;
    const float4* a4 = (const float4*)(tbb + 768);
    #pragma unroll
    for (int r = 0; r < 2; r++) {
        float mu = s[r] * inv;
        float var = s2[r] * inv - mu * mu;
        float rs = rsqrtf(var + 1e-5f);
        #pragma unroll
        for (int j = 0; j < 6; j++) {
            int i = lane + j * 32;
            float4 gg = g4[i], bb = b4[i], tt = t4[i], aa = a4[i];
            float r0 = ((v[r][j].x - mu) * rs * gg.x + bb.x) * tt.x + aa.x;
            float r1 = ((v[r][j].y - mu) * rs * gg.y + bb.y) * tt.y + aa.y;
            float r2 = ((v[r][j].z - mu) * rs * gg.z + bb.z) * tt.z + aa.z;
            float r3 = ((v[r][j].w - mu) * rs * gg.w + bb.w) * tt.w + aa.w;
            uint2 o2;
            o2.x = pack_h2(r0, r1);
            o2.y = pack_h2(r2, r3);
            *(uint2*)(y + (size_t)(row0 + r) * HH + i * 4) = o2;
        }
    }
}

// ------------------------------ HMMA GEMM (M128) ---------------------------
#define MTILE 16384             // 128 rows * 128B
#define STAGE (2*MTILE)         // 32768
#define GEMM_SMEM (3*STAGE)     // 98304
template <int EPI>
__global__ void __launch_bounds__(256, 2) hgemm_k(
    const __half* __restrict__ A, const __half* __restrict__ Bt,
    const float* __restrict__ bias,
    float* __restrict__ Cf, __half* __restrict__ Ch,
    int N, int K,
    const float* __restrict__ res, int gate_off) {

    extern __shared__ char sm[];
    const uint32_t sbase = smem_u32(sm);
    const int tid = threadIdx.x, lane = tid & 31, wid = tid >> 5;
    const int bm = blockIdx.y, bn = blockIdx.x;
    const int am0 = bm * 128, bn0 = bn * 128;
    const int wm0 = (wid >> 1) * 32, wn0 = (wid & 1) * 64;

    float acc[2][8][4];
    #pragma unroll
    for (int i = 0; i < 2; i++)
        #pragma unroll
        for (int j = 0; j < 8; j++)
            #pragma unroll
            for (int q = 0; q < 4; q++) acc[i][j][q] = 0.f;

    const __half* mats[2] = {A, Bt};
    const __half* srcb[8];
    uint32_t dstb[8];
    #pragma unroll
    for (int it = 0; it < 8; it++) {
        int idx = tid + it * 256;
        int mat = idx >> 10, r = (idx >> 3) & 127, c = idx & 7;
        int grow = (mat == 0 ? am0 : bn0) + r;
        srcb[it] = mats[mat] + (size_t)grow * K + c * 8;
        dstb[it] = sbase + mat * MTILE + swz(r, c);
    }

    uint32_t arowb[2]; int arl[2];
    #pragma unroll
    for (int mi = 0; mi < 2; mi++) {
        int row = wm0 + mi * 16 + (lane & 15);
        arowb[mi] = row * 128; arl[mi] = row & 7;
    }
    const int acol = lane >> 4;
    uint32_t browb[4]; int brl[4];
    #pragma unroll
    for (int ng = 0; ng < 4; ng++) {
        int row = wn0 + ng * 16 + (lane & 7) + ((lane & 16) >> 1);
        browb[ng] = MTILE + row * 128; brl[ng] = row & 7;
    }
    const int bcol = (lane >> 3) & 1;

    const int KB = K >> 6;
    #pragma unroll
    for (int pf = 0; pf < 2; pf++) {
        #pragma unroll
        for (int it = 0; it < 8; it++)
            cpasync16(dstb[it] + pf * STAGE, srcb[it] + pf * 64);
        CP_COMMIT();
    }

    int slot = 0;
    for (int kb = 0; kb < KB; kb++) {
        if (kb + 1 < KB) { CP_WAIT(1); } else { CP_WAIT(0); }
        __syncthreads();
        if (kb + 2 < KB) {
            int wslot = slot + 2; if (wslot >= 3) wslot -= 3;
            const uint32_t so2 = wslot * STAGE;
            const int ko = (kb + 2) << 6;
            #pragma unroll
            for (int it = 0; it < 8; it++) cpasync16(dstb[it] + so2, srcb[it] + ko);
            CP_COMMIT();
        }
        const uint32_t so = sbase + slot * STAGE;
        #pragma unroll
        for (int kc = 0; kc < 4; kc++) {
            uint32_t a[2][4];
            #pragma unroll
            for (int mi = 0; mi < 2; mi++)
                ldsm4(a[mi], so + arowb[mi] + ((((kc*2 + acol) ^ arl[mi]) & 7) << 4));
            uint32_t b[8][2];
            #pragma unroll
            for (int ng = 0; ng < 4; ng++) {
                uint32_t r[4];
                ldsm4(r, so + browb[ng] + ((((kc*2 + bcol) ^ brl[ng]) & 7) << 4));
                b[2*ng][0] = r[0]; b[2*ng][1] = r[1];
                b[2*ng+1][0] = r[2]; b[2*ng+1][1] = r[3];
            }
            #pragma unroll
            for (int mi = 0; mi < 2; mi++)
                #pragma unroll
                for (int ni = 0; ni < 8; ni++)
                    mma16816(acc[mi][ni], a[mi], b[ni]);
        }
        if (++slot == 3) slot = 0;
    }

    const int rbase = am0 + wm0 + (lane >> 2);
    const int cbase = bn0 + wn0 + (lane & 3) * 2;
    #pragma unroll
    for (int mi = 0; mi < 2; mi++) {
        #pragma unroll
        for (int ni = 0; ni < 8; ni++) {
            int col = cbase + ni * 8;
            float2 bb = *(const float2*)&bias[col];
            #pragma unroll
            for (int half2i = 0; half2i < 2; half2i++) {
                int row = rbase + mi * 16 + half2i * 8;
                float v0 = acc[mi][ni][2*half2i]   + bb.x;
                float v1 = acc[mi][ni][2*half2i+1] + bb.y;
                if (EPI == 1) {
                    v0 = 0.5f * v0 * (1.0f + erff(v0 * 0.70710678118654752f));
                    v1 = 0.5f * v1 * (1.0f + erff(v1 * 0.70710678118654752f));
                    *(uint32_t*)(Ch + (size_t)row * N + col) = pack_h2(v0, v1);
                } else if (EPI == 3) {
                    int i3 = col / 768;
                    int rem = col - i3 * 768;
                    int hh = rem >> 6, d = rem & 63;
                    int b2 = row >> 11, t2 = row & 2047;
                    size_t idx = ((size_t)((b2 * NHD + hh) * TT + t2)) * HDD + d;
                    if (i3 == 0) { v0 *= QSCALE; v1 *= QSCALE; }
                    __half* dh = (i3 == 0) ? g_q : (i3 == 1) ? g_k : g_v;
                    *(uint32_t*)(dh + idx) = pack_h2(v0, v1);
                } else {
                    float2 o2; o2.x = v0; o2.y = v1;
                    *(float2*)&Cf[(size_t)row * N + col] = o2;
                }
            }
        }
    }
}

// --------------------- HMMA GEMM (M64, residual+gate) ----------------------
#define AT64   8192              // 64 rows * 128B
#define STAGE64 (AT64 + MTILE)   // 24576
#define GEMM64_SMEM (3*STAGE64)  // 73728
__global__ void __launch_bounds__(256, 3) hgemm64_k(
    const __half* __restrict__ A, const __half* __restrict__ Bt,
    const float* __restrict__ bias,
    float* __restrict__ Cf,
    int N, int K,
    const float* __restrict__ res, int gate_off) {

    extern __shared__ char sm[];
    const uint32_t sbase = smem_u32(sm);
    const int tid = threadIdx.x, lane = tid & 31, wid = tid >> 5;
    const int bm = blockIdx.y, bn = blockIdx.x;
    const int am0 = bm * 64, bn0 = bn * 128;
    const int wm0 = (wid >> 2) * 32, wn0 = (wid & 3) * 32;

    float acc[2][4][4];
    #pragma unroll
    for (int i = 0; i < 2; i++)
        #pragma unroll
        for (int j = 0; j < 4; j++)
            #pragma unroll
            for (int q = 0; q < 4; q++) acc[i][j][q] = 0.f;

    const __half* srcb[6];
    uint32_t dstb[6];
    #pragma unroll
    for (int it = 0; it < 6; it++) {
        int idx = tid + it * 256;
        if (idx < 512) {
            int r = idx >> 3, c = idx & 7;
            srcb[it] = A + (size_t)(am0 + r) * K + c * 8;
            dstb[it] = sbase + swz(r, c);
        } else {
            int j = idx - 512;
            int r = j >> 3, c = j & 7;
            srcb[it] = Bt + (size_t)(bn0 + r) * K + c * 8;
            dstb[it] = sbase + AT64 + swz(r, c);
        }
    }

    uint32_t arowb[2]; int arl[2];
    #pragma unroll
    for (int mi = 0; mi < 2; mi++) {
        int row = wm0 + mi * 16 + (lane & 15);
        arowb[mi] = row * 128; arl[mi] = row & 7;
    }
    const int acol = lane >> 4;
    uint32_t browb[2]; int brl[2];
    #pragma unroll
    for (int ng = 0; ng < 2; ng++) {
        int row = wn0 + ng * 16 + (lane & 7) + ((lane & 16) >> 1);
        browb[ng] = AT64 + row * 128; brl[ng] = row & 7;
    }
    const int bcol = (lane >> 3) & 1;

    const int KB = K >> 6;
    #pragma unroll
    for (int pf = 0; pf < 2; pf++) {
        #pragma unroll
        for (int it = 0; it < 6; it++)
            cpasync16(dstb[it] + pf * STAGE64, srcb[it] + pf * 64);
        CP_COMMIT();
    }

    int slot = 0;
    for (int kb = 0; kb < KB; kb++) {
        if (kb + 1 < KB) { CP_WAIT(1); } else { CP_WAIT(0); }
        __syncthreads();
        if (kb + 2 < KB) {
            int wslot = slot + 2; if (wslot >= 3) wslot -= 3;
            const uint32_t so2 = wslot * STAGE64;
            const int ko = (kb + 2) << 6;
            #pragma unroll
            for (int it = 0; it < 6; it++) cpasync16(dstb[it] + so2, srcb[it] + ko);
            CP_COMMIT();
        }
        const uint32_t so = sbase + slot * STAGE64;
        #pragma unroll
        for (int kc = 0; kc < 4; kc++) {
            uint32_t a[2][4];
            #pragma unroll
            for (int mi = 0; mi < 2; mi++)
                ldsm4(a[mi], so + arowb[mi] + ((((kc*2 + acol) ^ arl[mi]) & 7) << 4));
            uint32_t b[4][2];
            #pragma unroll
            for (int ng = 0; ng < 2; ng++) {
                uint32_t r[4];
                ldsm4(r, so + browb[ng] + ((((kc*2 + bcol) ^ brl[ng]) & 7) << 4));
                b[2*ng][0] = r[0]; b[2*ng][1] = r[1];
                b[2*ng+1][0] = r[2]; b[2*ng+1][1] = r[3];
            }
            #pragma unroll
            for (int mi = 0; mi < 2; mi++)
                #pragma unroll
                for (int ni = 0; ni < 4; ni++)
                    mma16816(acc[mi][ni], a[mi], b[ni]);
        }
        if (++slot == 3) slot = 0;
    }

    const int rbase = am0 + wm0 + (lane >> 2);
    const int cbase = bn0 + wn0 + (lane & 3) * 2;
    #pragma unroll
    for (int mi = 0; mi < 2; mi++) {
        #pragma unroll
        for (int ni = 0; ni < 4; ni++) {
            int col = cbase + ni * 8;
            float2 bb = *(const float2*)&bias[col];
            #pragma unroll
            for (int half2i = 0; half2i < 2; half2i++) {
                int row = rbase + mi * 16 + half2i * 8;
                float v0 = acc[mi][ni][2*half2i]   + bb.x;
                float v1 = acc[mi][ni][2*half2i+1] + bb.y;
                const float* tb = g_temb + (row >> 11) * 4608 + gate_off;
                float2 rr = *(const float2*)&res[(size_t)row * N + col];
                float2 gg = *(const float2*)&tb[col];
                v0 = rr.x + gg.x * v0;
                v1 = rr.y + gg.y * v1;
                float2 o2; o2.x = v0; o2.y = v1;
                *(float2*)&Cf[(size_t)row * N + col] = o2;
            }
        }
    }
}

// -------------------- tensor-core flash attention --------------------------
#define QB    16384              // 128 rows * 128B
#define KVST  32768              // K + V
#define ATTN_SMEM (QB + 2*KVST)  // 81920
__global__ void __launch_bounds__(256, 2) attn_tc(void) {
    extern __shared__ char sm[];
    const uint32_t sbase = smem_u32(sm);
    const int tid = threadIdx.x, lane = tid & 31, wid = tid >> 5;
    const int bh = blockIdx.x;
    const int qb = blockIdx.y;
    const size_t headbase = (size_t)bh * TT * HDD;

    const __half* kvmats[2] = {g_k, g_v};

    #pragma unroll
    for (int it = 0; it < 4; it++) {
        int idx = tid + it * 256;
        int r = idx >> 3, c = idx & 7;
        cpasync16(sbase + swz(r, c),
                  g_q + headbase + (size_t)(qb * 128 + r) * HDD + c * 8);
    }
    #pragma unroll
    for (int it = 0; it < 8; it++) {
        int idx = tid + it * 256;
        int mat = idx >> 10, r = (idx >> 3) & 127, c = idx & 7;
        cpasync16(sbase + QB + mat * MTILE + swz(r, c),
                  kvmats[mat] + headbase + (size_t)r * HDD + c * 8);
    }
    CP_COMMIT();

    const int qrow = wid * 16 + (lane & 15);
    const uint32_t qrowb = qrow * 128; const int qrl = qrow & 7;
    const int qcol = lane >> 4;
    int krow[4];
    #pragma unroll
    for (int ng = 0; ng < 4; ng++)
        krow[ng] = ng * 16 + (lane & 7) + ((lane & 16) >> 1);
    const int kcol = (lane >> 3) & 1;
    const int vrowl = (lane & 7) + (lane & 8);
    const int vcol0 = (lane >> 4) & 1;

    uint32_t qh[4][4];
    float o[8][4];
    #pragma unroll
    for (int n = 0; n < 8; n++)
        #pragma unroll
        for (int j = 0; j < 4; j++) o[n][j] = 0.f;
    float m0 = -1e30f, m1 = -1e30f, l0 = 0.f, l1 = 0.f;

    const int NT = TT / 128;   // 16
    for (int t = 0; t < NT; t++) {
        CP_WAIT(0);
        __syncthreads();
        if (t == 0) {
            #pragma unroll
            for (int kc = 0; kc < 4; kc++)
                ldsm4(qh[kc], sbase + qrowb + ((((kc*2 + qcol) ^ qrl) & 7) << 4));
        }
        if (t + 1 < NT) {
            const uint32_t sb2 = sbase + QB + ((t + 1) & 1) * KVST;
            const size_t kvb = headbase + (size_t)(t + 1) * 128 * HDD;
            #pragma unroll
            for (int it = 0; it < 8; it++) {
                int idx = tid + it * 256;
                int mat = idx >> 10, r = (idx >> 3) & 127, c = idx & 7;
                cpasync16(sb2 + mat * MTILE + swz(r, c),
                          kvmats[mat] + kvb + (size_t)r * HDD + c * 8);
            }
            CP_COMMIT();
        }

        const uint32_t stb = sbase + QB + (t & 1) * KVST;
        #pragma unroll
        for (int s = 0; s < 2; s++) {
            const uint32_t kb2 = stb + s * 64 * 128;
            const uint32_t vb2 = stb + MTILE + s * 64 * 128;

            float c[8][4];
            #pragma unroll
            for (int n = 0; n < 8; n++)
                #pragma unroll
                for (int j = 0; j < 4; j++) c[n][j] = 0.f;
            #pragma unroll
            for (int kc = 0; kc < 4; kc++) {
                uint32_t b[8][2];
                #pragma unroll
                for (int ng = 0; ng < 4; ng++) {
                    uint32_t r[4];
                    ldsm4(r, kb2 + krow[ng] * 128
                              + ((((kc*2 + kcol) ^ krow[ng]) & 7) << 4));
                    b[2*ng][0] = r[0]; b[2*ng][1] = r[1];
                    b[2*ng+1][0] = r[2]; b[2*ng+1][1] = r[3];
                }
                #pragma unroll
                for (int n = 0; n < 8; n++) mma16816(c[n], qh[kc], b[n]);
            }

            float mx0 = -1e30f, mx1 = -1e30f;
            #pragma unroll
            for (int n = 0; n < 8; n++) {
                mx0 = fmaxf(mx0, fmaxf(c[n][0], c[n][1]));
                mx1 = fmaxf(mx1, fmaxf(c[n][2], c[n][3]));
            }
            mx0 = fmaxf(mx0, __shfl_xor_sync(0xffffffffu, mx0, 1));
            mx0 = fmaxf(mx0, __shfl_xor_sync(0xffffffffu, mx0, 2));
            mx1 = fmaxf(mx1, __shfl_xor_sync(0xffffffffu, mx1, 1));
            mx1 = fmaxf(mx1, __shfl_xor_sync(0xffffffffu, mx1, 2));
            float mn0 = fmaxf(m0, mx0), mn1 = fmaxf(m1, mx1);
            float cr0 = exp2fast(m0 - mn0), cr1 = exp2fast(m1 - mn1);
            m0 = mn0; m1 = mn1;
            l0 *= cr0; l1 *= cr1;
            #pragma unroll
            for (int n = 0; n < 8; n++) {
                o[n][0] *= cr0; o[n][1] *= cr0;
                o[n][2] *= cr1; o[n][3] *= cr1;
            }
            uint32_t pa[4][4];
            #pragma unroll
            for (int n = 0; n < 8; n++) {
                float p00 = exp2fast(c[n][0] - mn0);
                float p01 = exp2fast(c[n][1] - mn0);
                float p10 = exp2fast(c[n][2] - mn1);
                float p11 = exp2fast(c[n][3] - mn1);
                l0 += p00 + p01; l1 += p10 + p11;
                int kc2 = n >> 1, ss = (n & 1) * 2;
                pa[kc2][ss]     = pack_h2(p00, p01);
                pa[kc2][ss + 1] = pack_h2(p10, p11);
            }

            #pragma unroll
            for (int kc = 0; kc < 4; kc++) {
                uint32_t b[8][2];
                int vrow = vrowl + kc * 16;
                #pragma unroll
                for (int ng = 0; ng < 4; ng++) {
                    uint32_t r[4];
                    ldsm4t(r, vb2 + vrow * 128
                               + ((((ng*2 + vcol0) ^ vrow) & 7) << 4));
                    b[2*ng][0] = r[0]; b[2*ng][1] = r[1];
                    b[2*ng+1][0] = r[2]; b[2*ng+1][1] = r[3];
                }
                #pragma unroll
                for (int n = 0; n < 8; n++) mma16816(o[n], pa[kc], b[n]);
            }
        }
        __syncthreads();
    }

    l0 += __shfl_xor_sync(0xffffffffu, l0, 1);
    l0 += __shfl_xor_sync(0xffffffffu, l0, 2);
    l1 += __shfl_xor_sync(0xffffffffu, l1, 1);
    l1 += __shfl_xor_sync(0xffffffffu, l1, 2);
    float i0 = 1.0f / l0, i1 = 1.0f / l1;

    const int b2 = bh / NHD, h2 = bh % NHD;
    const int r0 = qb * 128 + wid * 16 + (lane >> 2);
    const int cb = h2 * 64 + (lane & 3) * 2;
    #pragma unroll
    for (int n = 0; n < 8; n++) {
        int col = cb + n * 8;
        size_t o0 = (size_t)(b2 * TT + r0) * HH + col;
        *(uint32_t*)(g_o + o0) = pack_h2(o[n][0] * i0, o[n][1] * i0);
        size_t o1 = (size_t)(b2 * TT + r0 + 8) * HH + col;
        *(uint32_t*)(g_o + o1) = pack_h2(o[n][2] * i1, o[n][3] * i1);
    }
}

// ------------------------------- launcher ----------------------------------
extern "C" void kernel_launch(void* const* d_in, const int* in_sizes, int n_in,
                              void* d_out, int out_size) {
    const float* x      = (const float*)d_in[0];
    const float* t      = (const float*)d_in[1];
    const float* w_qkv  = (const float*)d_in[2];
    const float* b_qkv  = (const float*)d_in[3];
    const float* w_m1   = (const float*)d_in[4];
    const float* b_m1   = (const float*)d_in[5];
    const float* w_m2   = (const float*)d_in[6];
    const float* b_m2   = (const float*)d_in[7];
    const float* w_ss1  = (const float*)d_in[8];
    const float* b_ss1  = (const float*)d_in[9];
    const float* w_ss2  = (const float*)d_in[10];
    const float* b_ss2  = (const float*)d_in[11];
    const float* ln1_g  = (const float*)d_in[12];
    const float* ln1_b  = (const float*)d_in[13];
    const float* ln2_g  = (const float*)d_in[14];
    const float* ln2_b  = (const float*)d_in[15];
    const float* w_f1   = (const float*)d_in[16];
    const float* b_f1   = (const float*)d_in[17];
    const float* w_f2   = (const float*)d_in[18];
    const float* b_f2   = (const float*)d_in[19];
    float* out = (float*)d_out;

    float *p_x1;
    __half *p_h, *p_o, *p_u;
    __half *p_wq, *p_wm1, *p_wm2, *p_wf1, *p_wf2;
    cudaGetSymbolAddress((void**)&p_x1,  g_x1);
    cudaGetSymbolAddress((void**)&p_h,   g_h);
    cudaGetSymbolAddress((void**)&p_o,   g_o);
    cudaGetSymbolAddress((void**)&p_u,   g_u);
    cudaGetSymbolAddress((void**)&p_wq,  g_wqkv);
    cudaGetSymbolAddress((void**)&p_wm1, g_wm1);
    cudaGetSymbolAddress((void**)&p_wm2, g_wm2);
    cudaGetSymbolAddress((void**)&p_wf1, g_wf1);
    cudaGetSymbolAddress((void**)&p_wf2, g_wf2);

    cudaFuncSetAttribute(attn_tc, cudaFuncAttributeMaxDynamicSharedMemorySize, ATTN_SMEM);
    cudaFuncSetAttribute(hgemm_k<1>, cudaFuncAttributeMaxDynamicSharedMemorySize, GEMM_SMEM);
    cudaFuncSetAttribute(hgemm_k<3>, cudaFuncAttributeMaxDynamicSharedMemorySize, GEMM_SMEM);
    cudaFuncSetAttribute(hgemm64_k,  cudaFuncAttributeMaxDynamicSharedMemorySize, GEMM64_SMEM);

    // side stream + events (created once; reused every call — resource cache,
    // identical work per call)
    static cudaStream_t s2 = nullptr;
    static cudaEvent_t evFork = nullptr, evQ = nullptr, evR = nullptr;
    if (s2 == nullptr) {
        cudaStreamCreateWithFlags(&s2, cudaStreamNonBlocking);
        cudaEventCreateWithFlags(&evFork, cudaEventDisableTiming);
        cudaEventCreateWithFlags(&evQ,    cudaEventDisableTiming);
        cudaEventCreateWithFlags(&evR,    cudaEventDisableTiming);
    }

    // fork: weight conversion on s2, temb/LN chain on main stream
    cudaEventRecord(evFork, 0);
    cudaStreamWaitEvent(s2, evFork, 0);
    wtconv_qkv<<<1728, dim3(32, 8), 0, s2>>>(w_qkv);
    cudaEventRecord(evQ, s2);
    wtconv_rest<<<9216, dim3(32, 8), 0, s2>>>(w_m1, w_m2, w_f1, w_f2);
    cudaEventRecord(evR, s2);

    temb1p_k<<<dim3(36, 4), 1024>>>(t, w_ss1);
    temb1r_k<<<36, 256>>>(b_ss1);
    temb2p_k<<<dim3(36, 12), 1024>>>(w_ss2);
    temb2r_k<<<36, 256>>>(b_ss2);

    ln_mod_k<<<256, 256>>>(x, ln1_g, ln1_b, 0, p_h);

    // join 1: qkv GEMM needs g_wqkv
    cudaStreamWaitEvent(0, evQ, 0);
    hgemm_k<3><<<dim3(2304/128, MROWS/128), 256, GEMM_SMEM>>>(
        p_h, p_wq, b_qkv, nullptr, nullptr, 2304, 768, nullptr, 0);

    attn_tc<<<dim3(BB * NHD, TT / 128), 256, ATTN_SMEM>>>();

    // join 2: remaining GEMMs need wm1/wm2/wf1/wf2
    cudaStreamWaitEvent(0, evR, 0);
    hgemm_k<1><<<dim3(3072/128, MROWS/128), 256, GEMM_SMEM>>>(
        p_o, p_wm1, b_m1, nullptr, p_u, 3072, 768, nullptr, 0);

    hgemm64_k<<<dim3(768/128, MROWS/64), 256, GEMM64_SMEM>>>(
        p_u, p_wm2, b_m2, p_x1, 768, 3072, x, 1536);

    ln_mod_k<<<256, 256>>>(p_x1, ln2_g, ln2_b, 2304, p_h);

    hgemm_k<1><<<dim3(3072/128, MROWS/128), 256, GEMM_SMEM>>>(
        p_h, p_wf1, b_f1, nullptr, p_u, 3072, 768, nullptr, 0);

    hgemm64_k<<<dim3(768/128, MROWS/64), 256, GEMM64_SMEM>>>(
        p_u, p_wf2, b_f2, out, 768, 3072, p_x1, 3840);
}